// round 2
// baseline (speedup 1.0000x reference)
#include <cuda_runtime.h>
#include <cstdint>
#include <cstddef>

#define B_ 4
#define C_ 256
#define N_ 2048
#define H_ 4
#define D_ 64
#define BH_ 16

// ------------------------- scratch (static device globals) -------------------
__device__ float g_E[(size_t)BH_ * N_ * N_];      // 256 MiB energy scratch
__device__ float g_emb[B_ * C_ * N_];
__device__ float g_h[B_ * C_ * N_];
__device__ float g_q[B_ * C_ * N_];
__device__ float g_v[B_ * C_ * N_];
__device__ float g_xr[B_ * C_ * N_];
__device__ float g_t[B_ * C_ * N_];
__device__ float g_Qh[BH_ * N_ * D_];
__device__ float g_rm[BH_ * N_];
__device__ float g_rsinv[BH_ * N_];
__device__ float g_csinv[BH_ * N_];
__device__ float g_scale[C_];
__device__ float g_shift[C_];

// Fast exp: FMA-only (no MUFU). Accurate to ~1e-7 rel for x <= ~1, valid x >= -87.
__device__ __forceinline__ float fexp(float x) {
    float t = fmaxf(x, -87.0f) * 1.4426950408889634f;
    float fi = rintf(t);
    float f = (t - fi) * 0.6931471805599453f;
    float p = 1.f + f * (1.f + f * (0.5f + f * (0.16666667f + f * (0.041666668f +
              f * (0.008333334f + f * 0.0013888889f)))));
    return __int_as_float(((int)fi + 127) << 23) * p;
}

// ------------------------- positional embedding ------------------------------
__global__ void k_posemb(const float* __restrict__ xyz, const float* __restrict__ pw,
                         const float* __restrict__ pb) {
    int idx = blockIdx.x * 256 + threadIdx.x;            // B*C*N = 2^21
    int n = idx & (N_ - 1);
    int c = (idx >> 11) & (C_ - 1);
    int b = idx >> 19;
    const float* p = xyz + ((size_t)(b * N_ + n)) * 3;
    g_emb[idx] = fmaf(pw[c * 3 + 0], p[0],
                 fmaf(pw[c * 3 + 1], p[1],
                 fmaf(pw[c * 3 + 2], p[2], pb[c])));
}

// ------------------------- 1x1 conv GEMM: Y[b,o,n] = W @ X (+bias) ----------
// MODE 0: X = X1 ; MODE 1: X = X1 + X2 ; MODE 2: X = X1 - X2
template <int MODE>
__global__ __launch_bounds__(256) void k_conv(const float* __restrict__ W,
                                              const float* __restrict__ X1,
                                              const float* __restrict__ X2,
                                              const float* __restrict__ bias,
                                              float* __restrict__ Y) {
    __shared__ __align__(16) float As[64][33];   // [o][k]
    __shared__ __align__(16) float Bs[32][64];   // [k][n]
    int b = blockIdx.z;
    int o0 = blockIdx.y * 64, n0 = blockIdx.x * 64;
    int tid = threadIdx.x, tx = tid & 15, ty = tid >> 4;
    const float* X1b = X1 + (size_t)b * C_ * N_;
    const float* X2b = (MODE != 0) ? (X2 + (size_t)b * C_ * N_) : nullptr;
    float acc[4][4] = {};
    for (int k0 = 0; k0 < C_; k0 += 32) {
        #pragma unroll
        for (int idx = tid; idx < 64 * 32; idx += 256) {
            int o = idx >> 5, k = idx & 31;
            As[o][k] = W[(size_t)(o0 + o) * C_ + k0 + k];
        }
        #pragma unroll
        for (int idx = tid; idx < 32 * 64; idx += 256) {
            int k = idx >> 6, n = idx & 63;
            size_t off = (size_t)(k0 + k) * N_ + n0 + n;
            float xv = X1b[off];
            if (MODE == 1) xv += X2b[off];
            if (MODE == 2) xv -= X2b[off];
            Bs[k][n] = xv;
        }
        __syncthreads();
        #pragma unroll
        for (int kk = 0; kk < 32; kk++) {
            float4 b4 = *(const float4*)&Bs[kk][tx * 4];
            #pragma unroll
            for (int i = 0; i < 4; i++) {
                float av = As[ty * 4 + i][kk];
                acc[i][0] = fmaf(av, b4.x, acc[i][0]);
                acc[i][1] = fmaf(av, b4.y, acc[i][1]);
                acc[i][2] = fmaf(av, b4.z, acc[i][2]);
                acc[i][3] = fmaf(av, b4.w, acc[i][3]);
            }
        }
        __syncthreads();
    }
    #pragma unroll
    for (int i = 0; i < 4; i++) {
        int o = o0 + ty * 4 + i;
        float bv = bias ? bias[o] : 0.f;
        float4 r;
        r.x = acc[i][0] + bv; r.y = acc[i][1] + bv;
        r.z = acc[i][2] + bv; r.w = acc[i][3] + bv;
        *(float4*)&Y[((size_t)b * C_ + o) * N_ + n0 + tx * 4] = r;
    }
}

// ------------------------- BN stats -> per-channel scale/shift ---------------
__global__ void k_bnstats(const float* __restrict__ gamma, const float* __restrict__ beta) {
    int c = blockIdx.x, tid = threadIdx.x;
    float s = 0.f, s2 = 0.f;
    for (int b = 0; b < B_; b++) {
        const float* p = g_t + ((size_t)b * C_ + c) * N_;
        for (int i = tid; i < N_; i += 256) {
            float v = p[i];
            s += v;
            s2 = fmaf(v, v, s2);
        }
    }
    __shared__ float red[256];
    red[tid] = s; __syncthreads();
    for (int st = 128; st > 0; st >>= 1) { if (tid < st) red[tid] += red[tid + st]; __syncthreads(); }
    s = red[0]; __syncthreads();
    red[tid] = s2; __syncthreads();
    for (int st = 128; st > 0; st >>= 1) { if (tid < st) red[tid] += red[tid + st]; __syncthreads(); }
    s2 = red[0];
    if (tid == 0) {
        float mean = s * (1.f / (B_ * N_));
        float var = s2 * (1.f / (B_ * N_)) - mean * mean;
        float inv = rsqrtf(var + 1e-5f);
        g_scale[c] = gamma[c] * inv;
        g_shift[c] = beta[c] - mean * inv * gamma[c];
    }
}

// h = relu(scale * t + shift)
__global__ void k_bnapply() {
    int idx = blockIdx.x * 256 + threadIdx.x;
    int c = (idx >> 11) & (C_ - 1);
    g_h[idx] = fmaxf(fmaf(g_scale[c], g_t[idx], g_shift[c]), 0.f);
}

// ------------------------- quirky x_q permutation ----------------------------
// Qh[bh, nn, d] = q[b, 64*(nn&3)+d, hh*512 + (nn>>2)]
__global__ void k_qperm() {
    int idx = blockIdx.x * 256 + threadIdx.x;            // BH*N*D = 2^21
    int d = idx & 63;
    int nn = (idx >> 6) & (N_ - 1);
    int bh = idx >> 17;
    int b = bh >> 2, hh = bh & 3;
    g_Qh[idx] = g_q[((size_t)(b * C_ + ((nn & 3) << 6) + d)) * N_ + (hh << 9) + (nn >> 2)];
}

// ------------------------- energy GEMM: E = Qh @ K ---------------------------
__global__ __launch_bounds__(256) void k_energy() {
    __shared__ __align__(16) float As[64][65];   // [nn][d]
    __shared__ __align__(16) float Bs[64][64];   // [d][m]
    int bh = blockIdx.z, b = bh >> 2, hh = bh & 3;
    int m0 = blockIdx.x * 64, nn0 = blockIdx.y * 64;
    int tid = threadIdx.x, tx = tid & 15, ty = tid >> 4;
    const float* Qb = g_Qh + ((size_t)bh * N_ + nn0) * D_;
    const float* Kb = g_q + ((size_t)(b * C_ + hh * D_)) * N_ + m0;
    #pragma unroll
    for (int idx = tid; idx < 64 * 64; idx += 256) {
        int r = idx >> 6, c = idx & 63;
        As[r][c] = Qb[(size_t)r * D_ + c];
        Bs[r][c] = Kb[(size_t)r * N_ + c];
    }
    __syncthreads();
    float acc[4][4] = {};
    #pragma unroll
    for (int kk = 0; kk < 64; kk++) {
        float4 b4 = *(const float4*)&Bs[kk][tx * 4];
        #pragma unroll
        for (int i = 0; i < 4; i++) {
            float av = As[ty * 4 + i][kk];
            acc[i][0] = fmaf(av, b4.x, acc[i][0]);
            acc[i][1] = fmaf(av, b4.y, acc[i][1]);
            acc[i][2] = fmaf(av, b4.z, acc[i][2]);
            acc[i][3] = fmaf(av, b4.w, acc[i][3]);
        }
    }
    #pragma unroll
    for (int i = 0; i < 4; i++) {
        float4 r;
        r.x = acc[i][0]; r.y = acc[i][1]; r.z = acc[i][2]; r.w = acc[i][3];
        *(float4*)&g_E[((size_t)bh * N_ + nn0 + ty * 4 + i) * N_ + m0 + tx * 4] = r;
    }
}

// ------------------------- row softmax stats ---------------------------------
__global__ void k_rowstats() {
    int row = blockIdx.y * N_ + blockIdx.x;              // bh * N + nn
    const float* p = g_E + (size_t)row * N_;
    int tid = threadIdx.x;
    float v[8];
    float mx = -3.4e38f;
    #pragma unroll
    for (int t = 0; t < 8; t++) { v[t] = p[tid + t * 256]; mx = fmaxf(mx, v[t]); }
    __shared__ float red[256];
    red[tid] = mx; __syncthreads();
    for (int st = 128; st > 0; st >>= 1) { if (tid < st) red[tid] = fmaxf(red[tid], red[tid + st]); __syncthreads(); }
    mx = red[0]; __syncthreads();
    float s = 0.f;
    #pragma unroll
    for (int t = 0; t < 8; t++) s += fexp(v[t] - mx);
    red[tid] = s; __syncthreads();
    for (int st = 128; st > 0; st >>= 1) { if (tid < st) red[tid] += red[tid + st]; __syncthreads(); }
    if (tid == 0) { g_rm[row] = mx; g_rsinv[row] = 1.f / red[0]; }
}

// ------------------------- column softmax stats ------------------------------
// a[nn,j] in (0,1] -> no max subtraction needed; csinv[j] = 1 / sum_nn exp(a)
__global__ void k_colstats() {
    int bh = blockIdx.x >> 3;
    int j = ((blockIdx.x & 7) << 8) | threadIdx.x;
    const float* base = g_E + ((size_t)bh << 22) + j;
    const float* rmp = g_rm + (bh << 11);
    const float* rsp = g_rsinv + (bh << 11);
    float s = 0.f;
    #pragma unroll 8
    for (int nn = 0; nn < N_; nn++) {
        float a = fexp(base[(size_t)nn << 11] - rmp[nn]) * rsp[nn];
        s += fexp(a);
    }
    g_csinv[(bh << 11) + j] = 1.f / s;
}

// ------------------------- attention output GEMM -----------------------------
// xr[b, hh*64+d, j] = csinv[j] * sum_nn v[b,hh*64+d,nn] * exp( exp(E-rm)*rsinv )
__global__ __launch_bounds__(256) void k_attn() {
    __shared__ __align__(16) float As[64][33];   // [d][k]
    __shared__ __align__(16) float Bs[32][64];   // [k][j]
    int bh = blockIdx.y, b = bh >> 2, hh = bh & 3;
    int j0 = blockIdx.x * 64;
    int tid = threadIdx.x, tx = tid & 15, ty = tid >> 4;
    const float* Vb = g_v + (size_t)(b * C_ + hh * D_) * N_;
    const float* Eb = g_E + (size_t)bh * N_ * N_;
    const float* rmp = g_rm + bh * N_;
    const float* rsp = g_rsinv + bh * N_;
    float acc[4][4] = {};
    for (int nn0 = 0; nn0 < N_; nn0 += 32) {
        #pragma unroll
        for (int idx = tid; idx < 64 * 32; idx += 256) {
            int dd = idx >> 5, k = idx & 31;
            As[dd][k] = Vb[(size_t)dd * N_ + nn0 + k];
        }
        #pragma unroll
        for (int idx = tid; idx < 32 * 64; idx += 256) {
            int k = idx >> 6, j = idx & 63;
            int nn = nn0 + k;
            float e = Eb[(size_t)nn * N_ + j0 + j];
            float a = fexp(e - rmp[nn]) * rsp[nn];
            Bs[k][j] = fexp(a);
        }
        __syncthreads();
        #pragma unroll
        for (int kk = 0; kk < 32; kk++) {
            float4 b4 = *(const float4*)&Bs[kk][tx * 4];
            #pragma unroll
            for (int i = 0; i < 4; i++) {
                float av = As[ty * 4 + i][kk];
                acc[i][0] = fmaf(av, b4.x, acc[i][0]);
                acc[i][1] = fmaf(av, b4.y, acc[i][1]);
                acc[i][2] = fmaf(av, b4.z, acc[i][2]);
                acc[i][3] = fmaf(av, b4.w, acc[i][3]);
            }
        }
        __syncthreads();
    }
    float c0 = g_csinv[bh * N_ + j0 + tx * 4 + 0];
    float c1 = g_csinv[bh * N_ + j0 + tx * 4 + 1];
    float c2 = g_csinv[bh * N_ + j0 + tx * 4 + 2];
    float c3 = g_csinv[bh * N_ + j0 + tx * 4 + 3];
    #pragma unroll
    for (int i = 0; i < 4; i++) {
        int d = ty * 4 + i;
        float4 r;
        r.x = acc[i][0] * c0; r.y = acc[i][1] * c1;
        r.z = acc[i][2] * c2; r.w = acc[i][3] * c3;
        *(float4*)&g_xr[((size_t)(b * C_ + hh * D_ + d)) * N_ + j0 + tx * 4] = r;
    }
}

// ------------------------- residual + BN + relu + output write ---------------
__global__ void k_residual(int layer, float* __restrict__ out) {
    int idx = blockIdx.x * 256 + threadIdx.x;
    int b = idx >> 19;
    int c = (idx >> 11) & (C_ - 1);
    int n = idx & (N_ - 1);
    float r = fmaxf(fmaf(g_scale[c], g_t[idx], g_shift[c]), 0.f);
    float o = g_h[idx] + r;
    g_h[idx] = o;
    out[((size_t)b * (4 * C_) + layer * C_ + c) * N_ + n] = o;
}

// ------------------------- host orchestration --------------------------------
extern "C" void kernel_launch(void* const* d_in, const int* in_sizes, int n_in,
                              void* d_out, int out_size) {
    (void)in_sizes; (void)n_in; (void)out_size;
    const float* x       = (const float*)d_in[0];
    const float* xyz     = (const float*)d_in[1];
    const float* conv1_w = (const float*)d_in[2];
    const float* pos_w   = (const float*)d_in[3];
    const float* pos_b   = (const float*)d_in[4];
    const float* bn1_g   = (const float*)d_in[5];
    const float* bn1_b   = (const float*)d_in[6];
    const float* qk_w    = (const float*)d_in[7];
    const float* v_w     = (const float*)d_in[8];
    const float* v_b     = (const float*)d_in[9];
    const float* t_w     = (const float*)d_in[10];
    const float* t_b     = (const float*)d_in[11];
    const float* bn_g    = (const float*)d_in[12];
    const float* bn_b    = (const float*)d_in[13];
    float* out = (float*)d_out;

    float *ph, *pemb, *pq, *pv, *pxr, *pt;
    cudaGetSymbolAddress((void**)&ph,   g_h);
    cudaGetSymbolAddress((void**)&pemb, g_emb);
    cudaGetSymbolAddress((void**)&pq,   g_q);
    cudaGetSymbolAddress((void**)&pv,   g_v);
    cudaGetSymbolAddress((void**)&pxr,  g_xr);
    cudaGetSymbolAddress((void**)&pt,   g_t);

    const int EW = (B_ * C_ * N_) / 256;   // 8192 blocks for elementwise
    dim3 gConv(N_ / 64, C_ / 64, B_);      // (32, 4, 4)

    k_posemb<<<EW, 256>>>(xyz, pos_w, pos_b);
    k_conv<0><<<gConv, 256>>>(conv1_w, x, nullptr, nullptr, pt);
    k_bnstats<<<C_, 256>>>(bn1_g, bn1_b);
    k_bnapply<<<EW, 256>>>();

    for (int i = 0; i < 4; i++) {
        const float* qw = qk_w + (size_t)i * C_ * C_;
        const float* vw = v_w  + (size_t)i * C_ * C_;
        const float* vb = v_b  + (size_t)i * C_;
        const float* tw = t_w  + (size_t)i * C_ * C_;
        const float* tb = t_b  + (size_t)i * C_;
        const float* bg = bn_g + (size_t)i * C_;
        const float* bb = bn_b + (size_t)i * C_;

        k_conv<1><<<gConv, 256>>>(qw, ph, pemb, nullptr, pq);   // q = qk_w @ (h+emb)
        k_conv<1><<<gConv, 256>>>(vw, ph, pemb, vb, pv);        // v = v_w @ (h+emb) + v_b
        k_qperm<<<EW, 256>>>();
        k_energy<<<dim3(N_ / 64, N_ / 64, BH_), 256>>>();
        k_rowstats<<<dim3(N_, BH_), 256>>>();
        k_colstats<<<BH_ * (N_ / 256), 256>>>();
        k_attn<<<dim3(N_ / 64, BH_), 256>>>();
        k_conv<2><<<gConv, 256>>>(tw, ph, pxr, tb, pt);         // t = t_w @ (h - xr) + t_b
        k_bnstats<<<C_, 256>>>(bg, bb);
        k_residual<<<EW, 256>>>(i, out);
    }
}

// round 4
// speedup vs baseline: 1.3536x; 1.3536x over previous
#include <cuda_runtime.h>
#include <cstdint>
#include <cstddef>

#define B_ 4
#define C_ 256
#define N_ 2048
#define H_ 4
#define D_ 64
#define BH_ 16

typedef unsigned long long u64;

// ------------------------- scratch (static device globals) -------------------
__device__ float g_E[(size_t)BH_ * N_ * N_];      // 256 MiB energy / expA scratch
__device__ float g_emb[B_ * C_ * N_];
__device__ float g_h[B_ * C_ * N_];
__device__ float g_q[B_ * C_ * N_];
__device__ float g_v[B_ * C_ * N_];
__device__ float g_xr[B_ * C_ * N_];
__device__ float g_t[B_ * C_ * N_];
__device__ float g_Qh[BH_ * N_ * D_];
__device__ float g_pm[BH_ * N_ * 32];             // per-block row max partials
__device__ float g_ps[BH_ * N_ * 32];             // per-block row sumexp partials
__device__ float g_cp[BH_ * N_ * 8];              // column-sum partials
__device__ float g_rm[BH_ * N_];
__device__ float g_rsinv[BH_ * N_];
__device__ float g_csinv[BH_ * N_];
__device__ float g_scale[C_];
__device__ float g_shift[C_];

// ------------------------- f32x2 packed helpers ------------------------------
__device__ __forceinline__ u64 pack2(float lo, float hi) {
    u64 r; asm("mov.b64 %0,{%1,%2};" : "=l"(r) : "f"(lo), "f"(hi)); return r;
}
__device__ __forceinline__ void unpack2(u64 v, float& lo, float& hi) {
    asm("mov.b64 {%0,%1},%2;" : "=f"(lo), "=f"(hi) : "l"(v));
}
__device__ __forceinline__ u64 fma2(u64 a, u64 b, u64 c) {
    u64 d; asm("fma.rn.f32x2 %0,%1,%2,%3;" : "=l"(d) : "l"(a), "l"(b), "l"(c)); return d;
}

// Fast exp: FMA-only (no MUFU). Accurate to ~1e-7 rel, valid x >= -87.
__device__ __forceinline__ float fexp(float x) {
    float t = fmaxf(x, -87.0f) * 1.4426950408889634f;
    float fi = rintf(t);
    float f = (t - fi) * 0.6931471805599453f;
    float p = 1.f + f * (1.f + f * (0.5f + f * (0.16666667f + f * (0.041666668f +
              f * (0.008333334f + f * 0.0013888889f)))));
    return __int_as_float(((int)fi + 127) << 23) * p;
}

// ------------------------- positional embedding ------------------------------
__global__ void k_posemb(const float* __restrict__ xyz, const float* __restrict__ pw,
                         const float* __restrict__ pb) {
    int idx = blockIdx.x * 256 + threadIdx.x;
    int n = idx & (N_ - 1);
    int c = (idx >> 11) & (C_ - 1);
    int b = idx >> 19;
    const float* p = xyz + ((size_t)(b * N_ + n)) * 3;
    g_emb[idx] = fmaf(pw[c * 3 + 0], p[0],
                 fmaf(pw[c * 3 + 1], p[1],
                 fmaf(pw[c * 3 + 2], p[2], pb[c])));
}

// ------------------------- 1x1 conv GEMM: Y[b,o,n] = W @ X (+bias) ----------
// MODE 0: X = X1 ; MODE 1: X = X1 + X2 ; MODE 2: X = X1 - X2
template <int MODE>
__global__ __launch_bounds__(256) void k_conv(const float* __restrict__ W,
                                              const float* __restrict__ X1,
                                              const float* __restrict__ X2,
                                              const float* __restrict__ bias,
                                              float* __restrict__ Y) {
    __shared__ __align__(16) float As[32][66];   // [k][o] transposed, pad 66
    __shared__ __align__(16) float Bs[32][64];   // [k][n]
    int b = blockIdx.z;
    int o0 = blockIdx.y * 64, n0 = blockIdx.x * 64;
    int tid = threadIdx.x, tx = tid & 15, ty = tid >> 4;
    const float* X1b = X1 + (size_t)b * C_ * N_;
    const float* X2b = (MODE != 0) ? (X2 + (size_t)b * C_ * N_) : nullptr;
    u64 accp[2][4] = {};
    for (int k0 = 0; k0 < C_; k0 += 32) {
        {   // A: 64o x 32k, float4 over k, scatter-transpose into As[k][o]
            int o = tid >> 3, k4 = (tid & 7) * 4;
            float4 w4 = *(const float4*)&W[(size_t)(o0 + o) * C_ + k0 + k4];
            As[k4 + 0][o] = w4.x; As[k4 + 1][o] = w4.y;
            As[k4 + 2][o] = w4.z; As[k4 + 3][o] = w4.w;
            o += 32;
            w4 = *(const float4*)&W[(size_t)(o0 + o) * C_ + k0 + k4];
            As[k4 + 0][o] = w4.x; As[k4 + 1][o] = w4.y;
            As[k4 + 2][o] = w4.z; As[k4 + 3][o] = w4.w;
        }
        {   // B: 32k x 64n, float4 over n
            int k = tid >> 4, n4 = (tid & 15) * 4;
            size_t off = (size_t)(k0 + k) * N_ + n0 + n4;
            float4 xv = *(const float4*)&X1b[off];
            if (MODE != 0) {
                float4 x2 = *(const float4*)&X2b[off];
                if (MODE == 1) { xv.x += x2.x; xv.y += x2.y; xv.z += x2.z; xv.w += x2.w; }
                else           { xv.x -= x2.x; xv.y -= x2.y; xv.z -= x2.z; xv.w -= x2.w; }
            }
            *(float4*)&Bs[k][n4] = xv;
            off += 16 * N_;
            xv = *(const float4*)&X1b[off];
            if (MODE != 0) {
                float4 x2 = *(const float4*)&X2b[off];
                if (MODE == 1) { xv.x += x2.x; xv.y += x2.y; xv.z += x2.z; xv.w += x2.w; }
                else           { xv.x -= x2.x; xv.y -= x2.y; xv.z -= x2.z; xv.w -= x2.w; }
            }
            *(float4*)&Bs[k + 16][n4] = xv;
        }
        __syncthreads();
        #pragma unroll
        for (int kk = 0; kk < 32; kk++) {
            u64 a01 = *(const u64*)&As[kk][ty * 4];
            u64 a23 = *(const u64*)&As[kk][ty * 4 + 2];
            float4 b4 = *(const float4*)&Bs[kk][tx * 4];
            u64 bb;
            bb = pack2(b4.x, b4.x); accp[0][0] = fma2(a01, bb, accp[0][0]); accp[1][0] = fma2(a23, bb, accp[1][0]);
            bb = pack2(b4.y, b4.y); accp[0][1] = fma2(a01, bb, accp[0][1]); accp[1][1] = fma2(a23, bb, accp[1][1]);
            bb = pack2(b4.z, b4.z); accp[0][2] = fma2(a01, bb, accp[0][2]); accp[1][2] = fma2(a23, bb, accp[1][2]);
            bb = pack2(b4.w, b4.w); accp[0][3] = fma2(a01, bb, accp[0][3]); accp[1][3] = fma2(a23, bb, accp[1][3]);
        }
        __syncthreads();
    }
    float v[4][4];
    #pragma unroll
    for (int p = 0; p < 2; p++)
        #pragma unroll
        for (int j = 0; j < 4; j++) unpack2(accp[p][j], v[2 * p][j], v[2 * p + 1][j]);
    #pragma unroll
    for (int i = 0; i < 4; i++) {
        int o = o0 + ty * 4 + i;
        float bv = bias ? bias[o] : 0.f;
        float4 r;
        r.x = v[i][0] + bv; r.y = v[i][1] + bv; r.z = v[i][2] + bv; r.w = v[i][3] + bv;
        *(float4*)&Y[((size_t)b * C_ + o) * N_ + n0 + tx * 4] = r;
    }
}

// ------------------------- BN stats -> per-channel scale/shift ---------------
__global__ void k_bnstats(const float* __restrict__ gamma, const float* __restrict__ beta) {
    int c = blockIdx.x, tid = threadIdx.x;
    float s = 0.f, s2 = 0.f;
    for (int b = 0; b < B_; b++) {
        const float* p = g_t + ((size_t)b * C_ + c) * N_;
        for (int i = tid; i < N_; i += 256) {
            float v = p[i];
            s += v;
            s2 = fmaf(v, v, s2);
        }
    }
    __shared__ float red[256];
    red[tid] = s; __syncthreads();
    for (int st = 128; st > 0; st >>= 1) { if (tid < st) red[tid] += red[tid + st]; __syncthreads(); }
    s = red[0]; __syncthreads();
    red[tid] = s2; __syncthreads();
    for (int st = 128; st > 0; st >>= 1) { if (tid < st) red[tid] += red[tid + st]; __syncthreads(); }
    s2 = red[0];
    if (tid == 0) {
        float mean = s * (1.f / (B_ * N_));
        float var = s2 * (1.f / (B_ * N_)) - mean * mean;
        float inv = rsqrtf(var + 1e-5f);
        g_scale[c] = gamma[c] * inv;
        g_shift[c] = beta[c] - mean * inv * gamma[c];
    }
}

__global__ void k_bnapply() {
    int idx = blockIdx.x * 256 + threadIdx.x;
    int c = (idx >> 11) & (C_ - 1);
    g_h[idx] = fmaxf(fmaf(g_scale[c], g_t[idx], g_shift[c]), 0.f);
}

// ------------------------- quirky x_q permutation ----------------------------
__global__ void k_qperm() {
    int idx = blockIdx.x * 256 + threadIdx.x;
    int d = idx & 63;
    int nn = (idx >> 6) & (N_ - 1);
    int bh = idx >> 17;
    int b = bh >> 2, hh = bh & 3;
    g_Qh[idx] = g_q[((size_t)(b * C_ + ((nn & 3) << 6) + d)) * N_ + (hh << 9) + (nn >> 2)];
}

// ------------------------- energy GEMM + fused row-softmax partials ----------
__global__ __launch_bounds__(256) void k_energy() {
    __shared__ __align__(16) float As[64][66];   // [d][nn] transposed
    __shared__ __align__(16) float Bs[64][64];   // [d][m]
    int bh = blockIdx.z, b = bh >> 2, hh = bh & 3;
    int m0 = blockIdx.x * 64, nn0 = blockIdx.y * 64;
    int tid = threadIdx.x, tx = tid & 15, ty = tid >> 4;
    const float* Qb = g_Qh + ((size_t)bh * N_ + nn0) * D_;
    const float* Kb = g_q + ((size_t)(b * C_ + hh * D_)) * N_ + m0;
    {   // A: 64nn x 64d, float4 over d, scatter-transpose
        int r = tid >> 2, c4 = (tid & 3) * 4;
        #pragma unroll
        for (int t = 0; t < 4; t++) {
            float4 q4 = *(const float4*)&Qb[(size_t)r * D_ + c4 + t * 16];
            As[c4 + t * 16 + 0][r] = q4.x; As[c4 + t * 16 + 1][r] = q4.y;
            As[c4 + t * 16 + 2][r] = q4.z; As[c4 + t * 16 + 3][r] = q4.w;
        }
        // B: 64d x 64m, float4 direct
        int br = tid >> 4, bc4 = (tid & 15) * 4;
        #pragma unroll
        for (int t = 0; t < 4; t++)
            *(float4*)&Bs[br + t * 16][bc4] = *(const float4*)&Kb[(size_t)(br + t * 16) * N_ + bc4];
    }
    __syncthreads();
    u64 accp[2][4] = {};
    #pragma unroll
    for (int kk = 0; kk < 64; kk++) {
        u64 a01 = *(const u64*)&As[kk][ty * 4];
        u64 a23 = *(const u64*)&As[kk][ty * 4 + 2];
        float4 b4 = *(const float4*)&Bs[kk][tx * 4];
        u64 bb;
        bb = pack2(b4.x, b4.x); accp[0][0] = fma2(a01, bb, accp[0][0]); accp[1][0] = fma2(a23, bb, accp[1][0]);
        bb = pack2(b4.y, b4.y); accp[0][1] = fma2(a01, bb, accp[0][1]); accp[1][1] = fma2(a23, bb, accp[1][1]);
        bb = pack2(b4.z, b4.z); accp[0][2] = fma2(a01, bb, accp[0][2]); accp[1][2] = fma2(a23, bb, accp[1][2]);
        bb = pack2(b4.w, b4.w); accp[0][3] = fma2(a01, bb, accp[0][3]); accp[1][3] = fma2(a23, bb, accp[1][3]);
    }
    float v[4][4];
    #pragma unroll
    for (int p = 0; p < 2; p++)
        #pragma unroll
        for (int j = 0; j < 4; j++) unpack2(accp[p][j], v[2 * p][j], v[2 * p + 1][j]);
    #pragma unroll
    for (int i = 0; i < 4; i++) {
        int row = nn0 + ty * 4 + i;
        float4 r;
        r.x = v[i][0]; r.y = v[i][1]; r.z = v[i][2]; r.w = v[i][3];
        *(float4*)&g_E[((size_t)bh * N_ + row) * N_ + m0 + tx * 4] = r;
        // fused row partial stats over this block's 64 columns
        float m = fmaxf(fmaxf(v[i][0], v[i][1]), fmaxf(v[i][2], v[i][3]));
        #pragma unroll
        for (int o = 8; o > 0; o >>= 1) m = fmaxf(m, __shfl_xor_sync(0xffffffffu, m, o));
        float s = fexp(v[i][0] - m) + fexp(v[i][1] - m) + fexp(v[i][2] - m) + fexp(v[i][3] - m);
        #pragma unroll
        for (int o = 8; o > 0; o >>= 1) s += __shfl_xor_sync(0xffffffffu, s, o);
        if (tx == 0) {
            g_pm[(((size_t)bh * N_ + row) << 5) | blockIdx.x] = m;
            g_ps[(((size_t)bh * N_ + row) << 5) | blockIdx.x] = s;
        }
    }
}

// combine 32 row partials -> rm, rsinv
__global__ void k_rowreduce() {
    int row = blockIdx.x * 8 + (threadIdx.x >> 5);
    int lane = threadIdx.x & 31;
    float pm = g_pm[((size_t)row << 5) | lane];
    float ps = g_ps[((size_t)row << 5) | lane];
    float m = pm;
    #pragma unroll
    for (int o = 16; o > 0; o >>= 1) m = fmaxf(m, __shfl_xor_sync(0xffffffffu, m, o));
    float s = ps * fexp(pm - m);
    #pragma unroll
    for (int o = 16; o > 0; o >>= 1) s += __shfl_xor_sync(0xffffffffu, s, o);
    if (lane == 0) { g_rm[row] = m; g_rsinv[row] = 1.f / s; }
}

// ------------------------- column pass: E <- exp(softmax_row(E)), partials ---
__global__ void k_colpart() {
    int bh = blockIdx.x, seg = blockIdx.y, jb = blockIdx.z;
    int j = jb * 256 + threadIdx.x;
    float* base = g_E + ((size_t)bh << 22) + j;
    const float* rmp = g_rm + (bh << 11);
    const float* rsp = g_rsinv + (bh << 11);
    float s = 0.f;
    int nn0 = seg * 256;
    #pragma unroll 4
    for (int t = 0; t < 256; t++) {
        int nn = nn0 + t;
        float a = fexp(base[(size_t)nn << 11] - rmp[nn]) * rsp[nn];
        float ea = fexp(a);
        base[(size_t)nn << 11] = ea;
        s += ea;
    }
    g_cp[(((size_t)bh << 11) + j) * 8 + seg] = s;
}

__global__ void k_colreduce() {
    int idx = blockIdx.x * 256 + threadIdx.x;     // bh*N + j
    float s = 0.f;
    #pragma unroll
    for (int t = 0; t < 8; t++) s += g_cp[(size_t)idx * 8 + t];
    g_csinv[idx] = 1.f / s;
}

// ------------------------- attention output GEMM (expA already in g_E) -------
__global__ __launch_bounds__(256) void k_attn() {
    __shared__ __align__(16) float As[32][66];   // [k][d] transposed
    __shared__ __align__(16) float Bs[32][64];   // [k][j]
    int bh = blockIdx.y, b = bh >> 2, hh = bh & 3;
    int j0 = blockIdx.x * 64;
    int tid = threadIdx.x, tx = tid & 15, ty = tid >> 4;
    const float* Vb = g_v + (size_t)(b * C_ + hh * D_) * N_;
    const float* Eb = g_E + ((size_t)bh << 22);
    u64 accp[2][4] = {};
    for (int nn0 = 0; nn0 < N_; nn0 += 32) {
        {   // A: 64d x 32k, float4 over k, scatter-transpose
            int dd = tid >> 3, k4 = (tid & 7) * 4;
            float4 v4 = *(const float4*)&Vb[(size_t)dd * N_ + nn0 + k4];
            As[k4 + 0][dd] = v4.x; As[k4 + 1][dd] = v4.y;
            As[k4 + 2][dd] = v4.z; As[k4 + 3][dd] = v4.w;
            dd += 32;
            v4 = *(const float4*)&Vb[(size_t)dd * N_ + nn0 + k4];
            As[k4 + 0][dd] = v4.x; As[k4 + 1][dd] = v4.y;
            As[k4 + 2][dd] = v4.z; As[k4 + 3][dd] = v4.w;
            // B: 32k x 64j float4 direct copy (expA)
            int k = tid >> 4, j4 = (tid & 15) * 4;
            *(float4*)&Bs[k][j4] = *(const float4*)&Eb[(size_t)(nn0 + k) * N_ + j0 + j4];
            *(float4*)&Bs[k + 16][j4] = *(const float4*)&Eb[(size_t)(nn0 + k + 16) * N_ + j0 + j4];
        }
        __syncthreads();
        #pragma unroll
        for (int kk = 0; kk < 32; kk++) {
            u64 a01 = *(const u64*)&As[kk][ty * 4];
            u64 a23 = *(const u64*)&As[kk][ty * 4 + 2];
            float4 b4 = *(const float4*)&Bs[kk][tx * 4];
            u64 bb;
            bb = pack2(b4.x, b4.x); accp[0][0] = fma2(a01, bb, accp[0][0]); accp[1][0] = fma2(a23, bb, accp[1][0]);
            bb = pack2(b4.y, b4.y); accp[0][1] = fma2(a01, bb, accp[0][1]); accp[1][1] = fma2(a23, bb, accp[1][1]);
            bb = pack2(b4.z, b4.z); accp[0][2] = fma2(a01, bb, accp[0][2]); accp[1][2] = fma2(a23, bb, accp[1][2]);
            bb = pack2(b4.w, b4.w); accp[0][3] = fma2(a01, bb, accp[0][3]); accp[1][3] = fma2(a23, bb, accp[1][3]);
        }
        __syncthreads();
    }
    float v[4][4];
    #pragma unroll
    for (int p = 0; p < 2; p++)
        #pragma unroll
        for (int j = 0; j < 4; j++) unpack2(accp[p][j], v[2 * p][j], v[2 * p + 1][j]);
    float c0 = g_csinv[bh * N_ + j0 + tx * 4 + 0];
    float c1 = g_csinv[bh * N_ + j0 + tx * 4 + 1];
    float c2 = g_csinv[bh * N_ + j0 + tx * 4 + 2];
    float c3 = g_csinv[bh * N_ + j0 + tx * 4 + 3];
    #pragma unroll
    for (int i = 0; i < 4; i++) {
        int d = ty * 4 + i;
        float4 r;
        r.x = v[i][0] * c0; r.y = v[i][1] * c1; r.z = v[i][2] * c2; r.w = v[i][3] * c3;
        *(float4*)&g_xr[((size_t)(b * C_ + hh * D_ + d)) * N_ + j0 + tx * 4] = r;
    }
}

// ------------------------- residual + BN + relu + output write ---------------
__global__ void k_residual(int layer, float* __restrict__ out) {
    int idx = blockIdx.x * 256 + threadIdx.x;
    int b = idx >> 19;
    int c = (idx >> 11) & (C_ - 1);
    int n = idx & (N_ - 1);
    float r = fmaxf(fmaf(g_scale[c], g_t[idx], g_shift[c]), 0.f);
    float o = g_h[idx] + r;
    g_h[idx] = o;
    out[((size_t)b * (4 * C_) + layer * C_ + c) * N_ + n] = o;
}

// ------------------------- host orchestration --------------------------------
extern "C" void kernel_launch(void* const* d_in, const int* in_sizes, int n_in,
                              void* d_out, int out_size) {
    (void)in_sizes; (void)n_in; (void)out_size;
    const float* x       = (const float*)d_in[0];
    const float* xyz     = (const float*)d_in[1];
    const float* conv1_w = (const float*)d_in[2];
    const float* pos_w   = (const float*)d_in[3];
    const float* pos_b   = (const float*)d_in[4];
    const float* bn1_g   = (const float*)d_in[5];
    const float* bn1_b   = (const float*)d_in[6];
    const float* qk_w    = (const float*)d_in[7];
    const float* v_w     = (const float*)d_in[8];
    const float* v_b     = (const float*)d_in[9];
    const float* t_w     = (const float*)d_in[10];
    const float* t_b     = (const float*)d_in[11];
    const float* bn_g    = (const float*)d_in[12];
    const float* bn_b    = (const float*)d_in[13];
    float* out = (float*)d_out;

    float *ph, *pemb, *pq, *pv, *pxr, *pt;
    cudaGetSymbolAddress((void**)&ph,   g_h);
    cudaGetSymbolAddress((void**)&pemb, g_emb);
    cudaGetSymbolAddress((void**)&pq,   g_q);
    cudaGetSymbolAddress((void**)&pv,   g_v);
    cudaGetSymbolAddress((void**)&pxr,  g_xr);
    cudaGetSymbolAddress((void**)&pt,   g_t);

    const int EW = (B_ * C_ * N_) / 256;
    dim3 gConv(N_ / 64, C_ / 64, B_);

    k_posemb<<<EW, 256>>>(xyz, pos_w, pos_b);
    k_conv<0><<<gConv, 256>>>(conv1_w, x, nullptr, nullptr, pt);
    k_bnstats<<<C_, 256>>>(bn1_g, bn1_b);
    k_bnapply<<<EW, 256>>>();

    for (int i = 0; i < 4; i++) {
        const float* qw = qk_w + (size_t)i * C_ * C_;
        const float* vw = v_w  + (size_t)i * C_ * C_;
        const float* vb = v_b  + (size_t)i * C_;
        const float* tw = t_w  + (size_t)i * C_ * C_;
        const float* tb = t_b  + (size_t)i * C_;
        const float* bg = bn_g + (size_t)i * C_;
        const float* bb = bn_b + (size_t)i * C_;

        k_conv<1><<<gConv, 256>>>(qw, ph, pemb, nullptr, pq);
        k_conv<1><<<gConv, 256>>>(vw, ph, pemb, vb, pv);
        k_qperm<<<EW, 256>>>();
        k_energy<<<dim3(N_ / 64, N_ / 64, BH_), 256>>>();
        k_rowreduce<<<(BH_ * N_) / 8, 256>>>();
        k_colpart<<<dim3(BH_, 8, 8), 256>>>();
        k_colreduce<<<(BH_ * N_) / 256, 256>>>();
        k_attn<<<dim3(N_ / 64, BH_), 256>>>();
        k_conv<2><<<gConv, 256>>>(tw, ph, pxr, tb, pt);
        k_bnstats<<<C_, 256>>>(bg, bb);
        k_residual<<<EW, 256>>>(i, out);
    }
}

// round 6
// speedup vs baseline: 2.3415x; 1.7298x over previous
#include <cuda_runtime.h>
#include <cuda_bf16.h>
#include <cstdint>
#include <cstddef>

#define B_ 4
#define C_ 256
#define N_ 2048
#define H_ 4
#define D_ 64
#define BH_ 16

typedef unsigned long long u64;
typedef unsigned int u32;

// ------------------------- scratch (static device globals) -------------------
__device__ float g_E[(size_t)BH_ * N_ * N_];             // 256 MiB energy fp32
__device__ __nv_bfloat16 g_expAT[(size_t)BH_ * N_ * N_]; // 128 MiB expA transposed [j][nn]
__device__ float g_emb[B_ * C_ * N_];
__device__ float g_h[B_ * C_ * N_];
__device__ float g_q[B_ * C_ * N_];
__device__ float g_v[B_ * C_ * N_];
__device__ float g_xr[B_ * C_ * N_];
__device__ float g_t[B_ * C_ * N_];
__device__ __nv_bfloat16 g_Qhi[BH_ * N_ * D_];
__device__ __nv_bfloat16 g_Qlo[BH_ * N_ * D_];
__device__ __nv_bfloat16 g_Kthi[BH_ * N_ * D_];
__device__ __nv_bfloat16 g_Ktlo[BH_ * N_ * D_];
__device__ __nv_bfloat16 g_Vb[B_ * C_ * N_];
__device__ float g_pm[(size_t)BH_ * N_ * 32];
__device__ float g_ps[(size_t)BH_ * N_ * 32];
__device__ float g_cp[BH_ * N_ * 8];
__device__ float g_rm[BH_ * N_];
__device__ float g_rsinv[BH_ * N_];
__device__ float g_csinv[BH_ * N_];
__device__ float g_scale[C_];
__device__ float g_shift[C_];

// ------------------------- helpers -------------------------------------------
__device__ __forceinline__ u32 smem_u32(const void* p) {
    u32 a;
    asm("{ .reg .u64 t; cvta.to.shared.u64 t, %1; cvt.u32.u64 %0, t; }" : "=r"(a) : "l"(p));
    return a;
}
#define SW128(o) ((o) ^ (((o) >> 3) & 0x70))

__device__ __forceinline__ void ldm_x4(u32* r, u32 a) {
    asm volatile("ldmatrix.sync.aligned.m8n8.x4.shared.b16 {%0,%1,%2,%3}, [%4];"
        : "=r"(r[0]), "=r"(r[1]), "=r"(r[2]), "=r"(r[3]) : "r"(a));
}
__device__ __forceinline__ void mma16816(float* c, const u32* a, const u32* b) {
    asm volatile("mma.sync.aligned.m16n8k16.row.col.f32.bf16.bf16.f32 "
        "{%0,%1,%2,%3}, {%4,%5,%6,%7}, {%8,%9}, {%0,%1,%2,%3};"
        : "+f"(c[0]), "+f"(c[1]), "+f"(c[2]), "+f"(c[3])
        : "r"(a[0]), "r"(a[1]), "r"(a[2]), "r"(a[3]), "r"(b[0]), "r"(b[1]));
}

// f32x2 packed helpers (conv path)
__device__ __forceinline__ u64 pack2(float lo, float hi) {
    u64 r; asm("mov.b64 %0,{%1,%2};" : "=l"(r) : "f"(lo), "f"(hi)); return r;
}
__device__ __forceinline__ void unpack2(u64 v, float& lo, float& hi) {
    asm("mov.b64 {%0,%1},%2;" : "=f"(lo), "=f"(hi) : "l"(v));
}
__device__ __forceinline__ u64 fma2(u64 a, u64 b, u64 c) {
    u64 d; asm("fma.rn.f32x2 %0,%1,%2,%3;" : "=l"(d) : "l"(a), "l"(b), "l"(c)); return d;
}
__device__ __forceinline__ u32 pkbf(float a, float b) {
    __nv_bfloat162 t = __floats2bfloat162_rn(a, b);
    return *(u32*)&t;
}

// Fast exp (full range, FMA-only)
__device__ __forceinline__ float fexp(float x) {
    float t = fmaxf(x, -87.0f) * 1.4426950408889634f;
    float fi = rintf(t);
    float f = (t - fi) * 0.6931471805599453f;
    float p = 1.f + f * (1.f + f * (0.5f + f * (0.16666667f + f * (0.041666668f +
              f * (0.008333334f + f * 0.0013888889f)))));
    return __int_as_float(((int)fi + 127) << 23) * p;
}
// exp for a in (0,1]
__device__ __forceinline__ float fexp01(float a) {
    return 1.f + a * (1.f + a * (0.5f + a * (0.16666667f + a * (0.041666668f + a * 0.0083333333f))));
}

// ------------------------- positional embedding ------------------------------
__global__ void k_posemb(const float* __restrict__ xyz, const float* __restrict__ pw,
                         const float* __restrict__ pb) {
    int idx = blockIdx.x * 256 + threadIdx.x;
    int n = idx & (N_ - 1);
    int c = (idx >> 11) & (C_ - 1);
    int b = idx >> 19;
    const float* p = xyz + ((size_t)(b * N_ + n)) * 3;
    g_emb[idx] = fmaf(pw[c * 3 + 0], p[0],
                 fmaf(pw[c * 3 + 1], p[1],
                 fmaf(pw[c * 3 + 2], p[2], pb[c])));
}

// ------------------------- 1x1 conv GEMM (f32x2 FFMA path) -------------------
template <int MODE>
__global__ __launch_bounds__(256) void k_conv(const float* __restrict__ W,
                                              const float* __restrict__ X1,
                                              const float* __restrict__ X2,
                                              const float* __restrict__ bias,
                                              float* __restrict__ Y) {
    __shared__ __align__(16) float As[32][66];
    __shared__ __align__(16) float Bs[32][64];
    int b = blockIdx.z;
    int o0 = blockIdx.y * 64, n0 = blockIdx.x * 64;
    int tid = threadIdx.x, tx = tid & 15, ty = tid >> 4;
    const float* X1b = X1 + (size_t)b * C_ * N_;
    const float* X2b = (MODE != 0) ? (X2 + (size_t)b * C_ * N_) : nullptr;
    u64 accp[2][4] = {};
    for (int k0 = 0; k0 < C_; k0 += 32) {
        {
            int o = tid >> 3, k4 = (tid & 7) * 4;
            float4 w4 = *(const float4*)&W[(size_t)(o0 + o) * C_ + k0 + k4];
            As[k4 + 0][o] = w4.x; As[k4 + 1][o] = w4.y;
            As[k4 + 2][o] = w4.z; As[k4 + 3][o] = w4.w;
            o += 32;
            w4 = *(const float4*)&W[(size_t)(o0 + o) * C_ + k0 + k4];
            As[k4 + 0][o] = w4.x; As[k4 + 1][o] = w4.y;
            As[k4 + 2][o] = w4.z; As[k4 + 3][o] = w4.w;
        }
        {
            int k = tid >> 4, n4 = (tid & 15) * 4;
            size_t off = (size_t)(k0 + k) * N_ + n0 + n4;
            float4 xv = *(const float4*)&X1b[off];
            if (MODE != 0) {
                float4 x2 = *(const float4*)&X2b[off];
                if (MODE == 1) { xv.x += x2.x; xv.y += x2.y; xv.z += x2.z; xv.w += x2.w; }
                else           { xv.x -= x2.x; xv.y -= x2.y; xv.z -= x2.z; xv.w -= x2.w; }
            }
            *(float4*)&Bs[k][n4] = xv;
            off += 16 * N_;
            xv = *(const float4*)&X1b[off];
            if (MODE != 0) {
                float4 x2 = *(const float4*)&X2b[off];
                if (MODE == 1) { xv.x += x2.x; xv.y += x2.y; xv.z += x2.z; xv.w += x2.w; }
                else           { xv.x -= x2.x; xv.y -= x2.y; xv.z -= x2.z; xv.w -= x2.w; }
            }
            *(float4*)&Bs[k + 16][n4] = xv;
        }
        __syncthreads();
        #pragma unroll
        for (int kk = 0; kk < 32; kk++) {
            u64 a01 = *(const u64*)&As[kk][ty * 4];
            u64 a23 = *(const u64*)&As[kk][ty * 4 + 2];
            float4 b4 = *(const float4*)&Bs[kk][tx * 4];
            u64 bb;
            bb = pack2(b4.x, b4.x); accp[0][0] = fma2(a01, bb, accp[0][0]); accp[1][0] = fma2(a23, bb, accp[1][0]);
            bb = pack2(b4.y, b4.y); accp[0][1] = fma2(a01, bb, accp[0][1]); accp[1][1] = fma2(a23, bb, accp[1][1]);
            bb = pack2(b4.z, b4.z); accp[0][2] = fma2(a01, bb, accp[0][2]); accp[1][2] = fma2(a23, bb, accp[1][2]);
            bb = pack2(b4.w, b4.w); accp[0][3] = fma2(a01, bb, accp[0][3]); accp[1][3] = fma2(a23, bb, accp[1][3]);
        }
        __syncthreads();
    }
    float v[4][4];
    #pragma unroll
    for (int p = 0; p < 2; p++)
        #pragma unroll
        for (int j = 0; j < 4; j++) unpack2(accp[p][j], v[2 * p][j], v[2 * p + 1][j]);
    #pragma unroll
    for (int i = 0; i < 4; i++) {
        int o = o0 + ty * 4 + i;
        float bv = bias ? bias[o] : 0.f;
        float4 r;
        r.x = v[i][0] + bv; r.y = v[i][1] + bv; r.z = v[i][2] + bv; r.w = v[i][3] + bv;
        *(float4*)&Y[((size_t)b * C_ + o) * N_ + n0 + tx * 4] = r;
    }
}

// ------------------------- BN stats ------------------------------------------
__global__ void k_bnstats(const float* __restrict__ gamma, const float* __restrict__ beta) {
    int c = blockIdx.x, tid = threadIdx.x;
    float s = 0.f, s2 = 0.f;
    for (int b = 0; b < B_; b++) {
        const float* p = g_t + ((size_t)b * C_ + c) * N_;
        for (int i = tid; i < N_; i += 256) {
            float v = p[i];
            s += v;
            s2 = fmaf(v, v, s2);
        }
    }
    __shared__ float red[256];
    red[tid] = s; __syncthreads();
    for (int st = 128; st > 0; st >>= 1) { if (tid < st) red[tid] += red[tid + st]; __syncthreads(); }
    s = red[0]; __syncthreads();
    red[tid] = s2; __syncthreads();
    for (int st = 128; st > 0; st >>= 1) { if (tid < st) red[tid] += red[tid + st]; __syncthreads(); }
    s2 = red[0];
    if (tid == 0) {
        float mean = s * (1.f / (B_ * N_));
        float var = s2 * (1.f / (B_ * N_)) - mean * mean;
        float inv = rsqrtf(var + 1e-5f);
        g_scale[c] = gamma[c] * inv;
        g_shift[c] = beta[c] - mean * inv * gamma[c];
    }
}

__global__ void k_bnapply() {
    int idx = blockIdx.x * 256 + threadIdx.x;
    int c = (idx >> 11) & (C_ - 1);
    g_h[idx] = fmaxf(fmaf(g_scale[c], g_t[idx], g_shift[c]), 0.f);
}

// ------------------------- Q split (quirky perm) + bf16 hi/lo ---------------
__global__ void k_qsplit() {
    int idx = blockIdx.x * 256 + threadIdx.x;     // [bh][nn][d]
    int d = idx & 63;
    int nn = (idx >> 6) & (N_ - 1);
    int bh = idx >> 17;
    int b = bh >> 2, hh = bh & 3;
    float v = g_q[((size_t)(b * C_ + ((nn & 3) << 6) + d)) * N_ + (hh << 9) + (nn >> 2)];
    __nv_bfloat16 hi = __float2bfloat16(v);
    g_Qhi[idx] = hi;
    g_Qlo[idx] = __float2bfloat16(v - __bfloat162float(hi));
}

// ------------------------- K transpose + bf16 hi/lo --------------------------
__global__ __launch_bounds__(256) void k_ktsplit() {
    __shared__ float tile[64][65];
    int m0 = blockIdx.x * 64, bh = blockIdx.y;
    int b = bh >> 2, hh = bh & 3;
    int t = threadIdx.x;
    int dr = t >> 4, m4 = (t & 15) * 4;
    #pragma unroll
    for (int i = 0; i < 4; i++) {
        int d = dr + i * 16;
        float4 v = *(const float4*)&g_q[((size_t)(b * C_ + hh * 64 + d)) * N_ + m0 + m4];
        tile[d][m4 + 0] = v.x; tile[d][m4 + 1] = v.y;
        tile[d][m4 + 2] = v.z; tile[d][m4 + 3] = v.w;
    }
    __syncthreads();
    #pragma unroll
    for (int i = 0; i < 8; i++) {
        int lin = i * 256 + t;
        int m = lin >> 5, dp = lin & 31;
        float v0 = tile[2 * dp][m], v1 = tile[2 * dp + 1][m];
        __nv_bfloat16 h0 = __float2bfloat16(v0), h1 = __float2bfloat16(v1);
        float l0 = v0 - __bfloat162float(h0), l1 = v1 - __bfloat162float(h1);
        size_t o = ((size_t)(bh * 2048 + m0 + m)) * 32 + dp;
        ((u32*)g_Kthi)[o] = pkbf(__bfloat162float(h0), __bfloat162float(h1));
        ((u32*)g_Ktlo)[o] = pkbf(l0, l1);
    }
}

// ------------------------- V -> bf16 -----------------------------------------
__global__ void k_vbf16() {
    int idx = blockIdx.x * 256 + threadIdx.x;
    float4 v = *(const float4*)&g_v[(size_t)idx * 4];
    uint2 o; o.x = pkbf(v.x, v.y); o.y = pkbf(v.z, v.w);
    *(uint2*)&g_Vb[(size_t)idx * 4] = o;
}

// ------------------------- energy MMA (mma.sync, split-bf16) -----------------
// E[nn][m] = Q[nn][d] . Kt[m][d], 3-pass: hi*hi + hi*lo + lo*hi
__global__ __launch_bounds__(256) void k_energy_mma() {
    extern __shared__ char smem[];
    const int AHI = 0, ALO = 16384, BHI = 32768, BLO = 49152;
    const u32 sbase = smem_u32(smem);
    int tid = threadIdx.x, wid = tid >> 5, lane = tid & 31;
    int mt = blockIdx.x, nt = blockIdx.y, bh = blockIdx.z;
    int m0 = mt * 128, nn0 = nt * 128;
    int wy = wid >> 1, wx = wid & 1;   // warp tile: 32 nn x 64 m

    const uint4* Ah = (const uint4*)g_Qhi + ((size_t)(bh * 2048 + nn0)) * 8;
    const uint4* Al = (const uint4*)g_Qlo + ((size_t)(bh * 2048 + nn0)) * 8;
    const uint4* Bh = (const uint4*)g_Kthi + ((size_t)(bh * 2048 + m0)) * 8;
    const uint4* Bl = (const uint4*)g_Ktlo + ((size_t)(bh * 2048 + m0)) * 8;
    #pragma unroll
    for (int i = 0; i < 4; i++) {
        int u = i * 256 + tid;
        int r = u >> 3, q = u & 7;
        int so = SW128(r * 128 + q * 16);
        *(uint4*)(smem + AHI + so) = Ah[(size_t)r * 8 + q];
        *(uint4*)(smem + ALO + so) = Al[(size_t)r * 8 + q];
        *(uint4*)(smem + BHI + so) = Bh[(size_t)r * 8 + q];
        *(uint4*)(smem + BLO + so) = Bl[(size_t)r * 8 + q];
    }
    __syncthreads();

    float acc[2][8][4] = {};
    #pragma unroll
    for (int ks = 0; ks < 4; ks++) {
        u32 ah[2][4], al[2][4], bhf[8][2], blf[8][2];
        int rsub = ((lane >> 3) & 1) * 8 + (lane & 7);
        int q = ks * 2 + (lane >> 4);
        #pragma unroll
        for (int ma = 0; ma < 2; ma++) {
            int row = wy * 32 + ma * 16 + rsub;
            u32 off = SW128(row * 128 + q * 16);
            ldm_x4(ah[ma], sbase + AHI + off);
            ldm_x4(al[ma], sbase + ALO + off);
        }
        #pragma unroll
        for (int p = 0; p < 4; p++) {
            int row = wx * 64 + p * 16 + rsub;
            u32 off = SW128(row * 128 + q * 16);
            u32 t4[4];
            ldm_x4(t4, sbase + BHI + off);
            bhf[p * 2][0] = t4[0]; bhf[p * 2][1] = t4[2];
            bhf[p * 2 + 1][0] = t4[1]; bhf[p * 2 + 1][1] = t4[3];
            ldm_x4(t4, sbase + BLO + off);
            blf[p * 2][0] = t4[0]; blf[p * 2][1] = t4[2];
            blf[p * 2 + 1][0] = t4[1]; blf[p * 2 + 1][1] = t4[3];
        }
        #pragma unroll
        for (int ma = 0; ma < 2; ma++)
            #pragma unroll
            for (int na = 0; na < 8; na++) {
                mma16816(acc[ma][na], ah[ma], bhf[na]);
                mma16816(acc[ma][na], ah[ma], blf[na]);
                mma16816(acc[ma][na], al[ma], bhf[na]);
            }
    }

    // epilogue: E store + fused row-softmax partials
    #pragma unroll
    for (int ma = 0; ma < 2; ma++) {
        #pragma unroll
        for (int half = 0; half < 2; half++) {
            int rloc = wy * 32 + ma * 16 + half * 8 + (lane >> 2);
            int rowg = bh * 2048 + nn0 + rloc;
            float mx = -3.4e38f;
            #pragma unroll
            for (int na = 0; na < 8; na++)
                mx = fmaxf(mx, fmaxf(acc[ma][na][half * 2], acc[ma][na][half * 2 + 1]));
            mx = fmaxf(mx, __shfl_xor_sync(0xffffffffu, mx, 1));
            mx = fmaxf(mx, __shfl_xor_sync(0xffffffffu, mx, 2));
            float s = 0.f;
            #pragma unroll
            for (int na = 0; na < 8; na++)
                s += fexp(acc[ma][na][half * 2] - mx) + fexp(acc[ma][na][half * 2 + 1] - mx);
            s += __shfl_xor_sync(0xffffffffu, s, 1);
            s += __shfl_xor_sync(0xffffffffu, s, 2);
            float* Erow = g_E + ((size_t)bh << 22) + ((size_t)nn0 + rloc) * 2048
                          + m0 + wx * 64 + (lane & 3) * 2;
            #pragma unroll
            for (int na = 0; na < 8; na++) {
                float2 w2; w2.x = acc[ma][na][half * 2]; w2.y = acc[ma][na][half * 2 + 1];
                *(float2*)&Erow[na * 8] = w2;
            }
            if ((lane & 3) == 0) {
                g_pm[(size_t)rowg * 32 + mt * 2 + wx] = mx;
                g_ps[(size_t)rowg * 32 + mt * 2 + wx] = s;
            }
        }
    }
}

// combine 32 row partials -> rm, rsinv
__global__ void k_rowreduce() {
    int row = blockIdx.x * 8 + (threadIdx.x >> 5);
    int lane = threadIdx.x & 31;
    float pm = g_pm[((size_t)row << 5) | lane];
    float ps = g_ps[((size_t)row << 5) | lane];
    float m = pm;
    #pragma unroll
    for (int o = 16; o > 0; o >>= 1) m = fmaxf(m, __shfl_xor_sync(0xffffffffu, m, o));
    float s = ps * fexp(pm - m);
    #pragma unroll
    for (int o = 16; o > 0; o >>= 1) s += __shfl_xor_sync(0xffffffffu, s, o);
    if (lane == 0) { g_rm[row] = m; g_rsinv[row] = 1.f / s; }
}

// ------------------------- col pass: expA^T bf16 + column partial sums -------
__global__ __launch_bounds__(256) void k_colpartT() {
    extern __shared__ char smem[];
    __nv_bfloat16* tile = (__nv_bfloat16*)smem;            // [256 nn][130 j]
    float* scol = (float*)(smem + 256 * 130 * 2);          // [128]
    int bh = blockIdx.x, jt = blockIdx.y, seg = blockIdx.z;
    int j0 = jt * 128, nn0 = seg * 256;
    int t = threadIdx.x;
    if (t < 128) scol[t] = 0.f;
    __syncthreads();
    int r = t >> 3, c0 = (t & 7) * 16;
    float sum16[16];
    #pragma unroll
    for (int i = 0; i < 16; i++) sum16[i] = 0.f;
    const float* rmp = g_rm + (bh << 11);
    const float* rsp = g_rsinv + (bh << 11);
    for (int s = 0; s < 8; s++) {
        int nn = nn0 + s * 32 + r;
        float irm = rmp[nn], irs = rsp[nn];
        const float* Er = g_E + ((size_t)bh << 22) + (size_t)nn * 2048 + j0 + c0;
        #pragma unroll
        for (int q = 0; q < 4; q++) {
            float4 e4 = *(const float4*)&Er[q * 4];
            __nv_bfloat16 b0 = __float2bfloat16(fexp01(fexp(e4.x - irm) * irs));
            __nv_bfloat16 b1 = __float2bfloat16(fexp01(fexp(e4.y - irm) * irs));
            __nv_bfloat16 b2 = __float2bfloat16(fexp01(fexp(e4.z - irm) * irs));
            __nv_bfloat16 b3 = __float2bfloat16(fexp01(fexp(e4.w - irm) * irs));
            sum16[q * 4 + 0] += __bfloat162float(b0);
            sum16[q * 4 + 1] += __bfloat162float(b1);
            sum16[q * 4 + 2] += __bfloat162float(b2);
            sum16[q * 4 + 3] += __bfloat162float(b3);
            int base = (s * 32 + r) * 130 + c0 + q * 4;
            tile[base + 0] = b0; tile[base + 1] = b1;
            tile[base + 2] = b2; tile[base + 3] = b3;
        }
    }
    #pragma unroll
    for (int i = 0; i < 16; i++) atomicAdd(&scol[c0 + i], sum16[i]);
    __syncthreads();
    u32* outp = (u32*)g_expAT;
    for (int it = 0; it < 64; it++) {
        int j = it * 2 + (t >> 7);
        int k = t & 127;
        __nv_bfloat16 v0 = tile[(2 * k) * 130 + j];
        __nv_bfloat16 v1 = tile[(2 * k + 1) * 130 + j];
        u32 pk = ((u32)*(unsigned short*)&v1 << 16) | (u32)*(unsigned short*)&v0;
        outp[((size_t)(bh * 2048 + j0 + j)) * 1024 + (nn0 >> 1) + k] = pk;
    }
    if (t < 128) g_cp[((size_t)(bh << 11) + j0 + t) * 8 + seg] = scol[t];
}

__global__ void k_colreduce() {
    int idx = blockIdx.x * 256 + threadIdx.x;
    float s = 0.f;
    #pragma unroll
    for (int t = 0; t < 8; t++) s += g_cp[(size_t)idx * 8 + t];
    g_csinv[idx] = 1.f / s;
}

// ------------------------- attn MMA: D[j][d] = expAT . V^T -------------------
__global__ __launch_bounds__(256) void k_attn_mma() {
    extern __shared__ char smem[];
    const int AOF = 0, BOF = 16384;
    const u32 sbase = smem_u32(smem);
    int tid = threadIdx.x, wid = tid >> 5, lane = tid & 31;
    int jt = blockIdx.x, bh = blockIdx.y;
    int b = bh >> 2, hh = bh & 3;
    int j0 = jt * 128;
    int wy = wid >> 1, wx = wid & 1;   // warp tile: 32 j x 32 d

    const uint4* Ag = (const uint4*)g_expAT;   // row stride 256 uint4
    const uint4* Bg = (const uint4*)g_Vb;

    float acc[2][4][4] = {};
    for (int c = 0; c < 32; c++) {
        #pragma unroll
        for (int i = 0; i < 4; i++) {
            int u = i * 256 + tid;
            int r = u >> 3, q = u & 7;
            *(uint4*)(smem + AOF + SW128(r * 128 + q * 16)) =
                Ag[((size_t)(bh * 2048 + j0 + r)) * 256 + c * 8 + q];
        }
        #pragma unroll
        for (int i = 0; i < 2; i++) {
            int u = i * 256 + tid;
            int r = u >> 3, q = u & 7;
            *(uint4*)(smem + BOF + SW128(r * 128 + q * 16)) =
                Bg[((size_t)(b * C_ + hh * 64 + r)) * 256 + c * 8 + q];
        }
        __syncthreads();
        #pragma unroll
        for (int ks = 0; ks < 4; ks++) {
            u32 af[2][4], bf[4][2];
            int rsub = ((lane >> 3) & 1) * 8 + (lane & 7);
            int q = ks * 2 + (lane >> 4);
            #pragma unroll
            for (int ma = 0; ma < 2; ma++) {
                int row = wy * 32 + ma * 16 + rsub;
                ldm_x4(af[ma], sbase + AOF + SW128(row * 128 + q * 16));
            }
            #pragma unroll
            for (int p = 0; p < 2; p++) {
                int row = wx * 32 + p * 16 + rsub;
                u32 t4[4];
                ldm_x4(t4, sbase + BOF + SW128(row * 128 + q * 16));
                bf[p * 2][0] = t4[0]; bf[p * 2][1] = t4[2];
                bf[p * 2 + 1][0] = t4[1]; bf[p * 2 + 1][1] = t4[3];
            }
            #pragma unroll
            for (int ma = 0; ma < 2; ma++)
                #pragma unroll
                for (int na = 0; na < 4; na++)
                    mma16816(acc[ma][na], af[ma], bf[na]);
        }
        __syncthreads();
    }

    // epilogue: csinv scale, smem transpose, coalesced xr write
    float* stg = (float*)smem;                  // [128][65]
    #pragma unroll
    for (int ma = 0; ma < 2; ma++) {
        #pragma unroll
        for (int half = 0; half < 2; half++) {
            int jl = wy * 32 + ma * 16 + half * 8 + (lane >> 2);
            float cs = g_csinv[bh * 2048 + j0 + jl];
            #pragma unroll
            for (int na = 0; na < 4; na++) {
                int d = wx * 32 + na * 8 + (lane & 3) * 2;
                stg[jl * 65 + d]     = acc[ma][na][half * 2] * cs;
                stg[jl * 65 + d + 1] = acc[ma][na][half * 2 + 1] * cs;
            }
        }
    }
    __syncthreads();
    for (int it = 0; it < 32; it++) {
        int d = it * 2 + (tid >> 7);
        int j = tid & 127;
        g_xr[((size_t)(b * C_ + hh * 64 + d)) * N_ + j0 + j] = stg[j * 65 + d];
    }
}

// ------------------------- residual + BN + relu + output write ---------------
__global__ void k_residual(int layer, float* __restrict__ out) {
    int idx = blockIdx.x * 256 + threadIdx.x;
    int b = idx >> 19;
    int c = (idx >> 11) & (C_ - 1);
    int n = idx & (N_ - 1);
    float r = fmaxf(fmaf(g_scale[c], g_t[idx], g_shift[c]), 0.f);
    float o = g_h[idx] + r;
    g_h[idx] = o;
    out[((size_t)b * (4 * C_) + layer * C_ + c) * N_ + n] = o;
}

// ------------------------- host orchestration --------------------------------
extern "C" void kernel_launch(void* const* d_in, const int* in_sizes, int n_in,
                              void* d_out, int out_size) {
    (void)in_sizes; (void)n_in; (void)out_size;
    const float* x       = (const float*)d_in[0];
    const float* xyz     = (const float*)d_in[1];
    const float* conv1_w = (const float*)d_in[2];
    const float* pos_w   = (const float*)d_in[3];
    const float* pos_b   = (const float*)d_in[4];
    const float* bn1_g   = (const float*)d_in[5];
    const float* bn1_b   = (const float*)d_in[6];
    const float* qk_w    = (const float*)d_in[7];
    const float* v_w     = (const float*)d_in[8];
    const float* v_b     = (const float*)d_in[9];
    const float* t_w     = (const float*)d_in[10];
    const float* t_b     = (const float*)d_in[11];
    const float* bn_g    = (const float*)d_in[12];
    const float* bn_b    = (const float*)d_in[13];
    float* out = (float*)d_out;

    float *ph, *pemb, *pq, *pv, *pxr, *pt;
    cudaGetSymbolAddress((void**)&ph,   g_h);
    cudaGetSymbolAddress((void**)&pemb, g_emb);
    cudaGetSymbolAddress((void**)&pq,   g_q);
    cudaGetSymbolAddress((void**)&pv,   g_v);
    cudaGetSymbolAddress((void**)&pxr,  g_xr);
    cudaGetSymbolAddress((void**)&pt,   g_t);

    cudaFuncSetAttribute(k_energy_mma, cudaFuncAttributeMaxDynamicSharedMemorySize, 65536);
    cudaFuncSetAttribute(k_colpartT,   cudaFuncAttributeMaxDynamicSharedMemorySize, 67072);
    cudaFuncSetAttribute(k_attn_mma,   cudaFuncAttributeMaxDynamicSharedMemorySize, 33280);

    const int EW = (B_ * C_ * N_) / 256;
    dim3 gConv(N_ / 64, C_ / 64, B_);

    k_posemb<<<EW, 256>>>(xyz, pos_w, pos_b);
    k_conv<0><<<gConv, 256>>>(conv1_w, x, nullptr, nullptr, pt);
    k_bnstats<<<C_, 256>>>(bn1_g, bn1_b);
    k_bnapply<<<EW, 256>>>();

    for (int i = 0; i < 4; i++) {
        const float* qw = qk_w + (size_t)i * C_ * C_;
        const float* vw = v_w  + (size_t)i * C_ * C_;
        const float* vb = v_b  + (size_t)i * C_;
        const float* tw = t_w  + (size_t)i * C_ * C_;
        const float* tb = t_b  + (size_t)i * C_;
        const float* bg = bn_g + (size_t)i * C_;
        const float* bb = bn_b + (size_t)i * C_;

        k_conv<1><<<gConv, 256>>>(qw, ph, pemb, nullptr, pq);
        k_conv<1><<<gConv, 256>>>(vw, ph, pemb, vb, pv);
        k_qsplit<<<(BH_ * N_ * D_) / 256, 256>>>();
        k_ktsplit<<<dim3(N_ / 64, BH_), 256>>>();
        k_vbf16<<<(B_ * C_ * N_) / 1024, 256>>>();
        k_energy_mma<<<dim3(16, 16, BH_), 256, 65536>>>();
        k_rowreduce<<<(BH_ * N_) / 8, 256>>>();
        k_colpartT<<<dim3(BH_, 16, 8), 256, 67072>>>();
        k_colreduce<<<(BH_ * N_) / 256, 256>>>();
        k_attn_mma<<<dim3(16, BH_), 256, 33280>>>();
        k_conv<2><<<gConv, 256>>>(tw, ph, pxr, tb, pt);
        k_bnstats<<<C_, 256>>>(bg, bb);
        k_residual<<<EW, 256>>>(i, out);
    }
}

// round 8
// speedup vs baseline: 3.7098x; 1.5844x over previous
#include <cuda_runtime.h>
#include <cuda_bf16.h>
#include <cstdint>
#include <cstddef>

#define B_ 4
#define C_ 256
#define N_ 2048
#define H_ 4
#define D_ 64
#define BH_ 16

typedef unsigned long long u64;
typedef unsigned int u32;

// ------------------------- scratch (static device globals) -------------------
__device__ __nv_bfloat16 g_E[(size_t)BH_ * N_ * N_];     // 128 MiB energy bf16
__device__ float g_emb[B_ * C_ * N_];
__device__ float g_h[B_ * C_ * N_];
__device__ float g_q[B_ * C_ * N_];
__device__ float g_v[B_ * C_ * N_];
__device__ float g_xr[B_ * C_ * N_];
__device__ float g_t[B_ * C_ * N_];
__device__ __nv_bfloat16 g_Qhi[BH_ * N_ * D_];
__device__ __nv_bfloat16 g_Qlo[BH_ * N_ * D_];
__device__ __nv_bfloat16 g_Kthi[BH_ * N_ * D_];
__device__ __nv_bfloat16 g_Ktlo[BH_ * N_ * D_];
__device__ __nv_bfloat16 g_Vb[B_ * C_ * N_];
__device__ __nv_bfloat16 g_Whi[13 * C_ * C_];
__device__ __nv_bfloat16 g_Wlo[13 * C_ * C_];
__device__ float g_pm[(size_t)BH_ * N_ * 32];
__device__ float g_ps[(size_t)BH_ * N_ * 32];
__device__ float g_rm[BH_ * N_];
__device__ float g_rsinv[BH_ * N_];
__device__ float g_scale[C_];
__device__ float g_shift[C_];

// ------------------------- helpers -------------------------------------------
__device__ __forceinline__ u32 smem_u32(const void* p) {
    u32 a;
    asm("{ .reg .u64 t; cvta.to.shared.u64 t, %1; cvt.u32.u64 %0, t; }" : "=r"(a) : "l"(p));
    return a;
}
#define SW128(o) ((o) ^ (((o) >> 3) & 0x70))
#define SW256(o) ((o) ^ (((o) >> 4) & 0x70))

__device__ __forceinline__ void ldm_x4(u32* r, u32 a) {
    asm volatile("ldmatrix.sync.aligned.m8n8.x4.shared.b16 {%0,%1,%2,%3}, [%4];"
        : "=r"(r[0]), "=r"(r[1]), "=r"(r[2]), "=r"(r[3]) : "r"(a));
}
__device__ __forceinline__ void ldm_x4t(u32* r, u32 a) {
    asm volatile("ldmatrix.sync.aligned.m8n8.x4.trans.shared.b16 {%0,%1,%2,%3}, [%4];"
        : "=r"(r[0]), "=r"(r[1]), "=r"(r[2]), "=r"(r[3]) : "r"(a));
}
__device__ __forceinline__ void mma16816(float* c, const u32* a, const u32* b) {
    asm volatile("mma.sync.aligned.m16n8k16.row.col.f32.bf16.bf16.f32 "
        "{%0,%1,%2,%3}, {%4,%5,%6,%7}, {%8,%9}, {%0,%1,%2,%3};"
        : "+f"(c[0]), "+f"(c[1]), "+f"(c[2]), "+f"(c[3])
        : "r"(a[0]), "r"(a[1]), "r"(a[2]), "r"(a[3]), "r"(b[0]), "r"(b[1]));
}
__device__ __forceinline__ u32 pkbf(float a, float b) {
    __nv_bfloat162 t = __floats2bfloat162_rn(a, b);
    return *(u32*)&t;
}

// ------------------------- positional embedding ------------------------------
__global__ void k_posemb(const float* __restrict__ xyz, const float* __restrict__ pw,
                         const float* __restrict__ pb) {
    int idx = blockIdx.x * 256 + threadIdx.x;
    int n = idx & (N_ - 1);
    int c = (idx >> 11) & (C_ - 1);
    int b = idx >> 19;
    const float* p = xyz + ((size_t)(b * N_ + n)) * 3;
    g_emb[idx] = fmaf(pw[c * 3 + 0], p[0],
                 fmaf(pw[c * 3 + 1], p[1],
                 fmaf(pw[c * 3 + 2], p[2], pb[c])));
}

// ------------------------- weight pre-split ----------------------------------
// slots: 0 conv1, 1..4 qk, 5..8 v, 9..12 t
__global__ void k_wsplit(const float* __restrict__ conv1_w, const float* __restrict__ qk_w,
                         const float* __restrict__ v_w, const float* __restrict__ t_w) {
    int idx = blockIdx.x * 256 + threadIdx.x;     // 13*65536
    int slot = idx >> 16, i = idx & 65535;
    float w;
    if (slot == 0) w = conv1_w[i];
    else if (slot < 5) w = qk_w[(slot - 1) * 65536 + i];
    else if (slot < 9) w = v_w[(slot - 5) * 65536 + i];
    else w = t_w[(slot - 9) * 65536 + i];
    __nv_bfloat16 hi = __float2bfloat16(w);
    g_Whi[idx] = hi;
    g_Wlo[idx] = __float2bfloat16(w - __bfloat162float(hi));
}

// ------------------------- conv via split-bf16 MMA ---------------------------
// Y[b,o,n] = W @ X (+bias); MODE 0: X=X1, 1: X1+X2, 2: X1-X2
// block: 128 o x 128 n; smem: Whi/Wlo [128][40bf16,pitch 80B], Xhi/Xlo [32][128, pitch 256B]
template <int MODE>
__global__ __launch_bounds__(256) void k_convmma(int wslot,
                                                 const float* __restrict__ X1,
                                                 const float* __restrict__ X2,
                                                 const float* __restrict__ bias,
                                                 float* __restrict__ Y) {
    extern __shared__ char smem[];
    const int WHI = 0, WLO = 10240, XHI = 20480, XLO = 28672;
    const u32 sbase = smem_u32(smem);
    int tid = threadIdx.x, wid = tid >> 5, lane = tid & 31;
    int n0 = blockIdx.x * 128, o0 = blockIdx.y * 128, b = blockIdx.z;
    int wy = wid >> 1, wx = wid & 1;   // warp: 32 o x 64 n
    const uint4* WhiG = (const uint4*)(g_Whi + (size_t)wslot * 65536);
    const uint4* WloG = (const uint4*)(g_Wlo + (size_t)wslot * 65536);
    const float* X1b = X1 + (size_t)b * C_ * N_;
    const float* X2b = (MODE != 0) ? (X2 + (size_t)b * C_ * N_) : nullptr;

    float acc[2][8][4] = {};
    for (int k0 = 0; k0 < C_; k0 += 32) {
        // W tiles: 128 rows x 32 k (64B = 4x16B per row)
        #pragma unroll
        for (int i = 0; i < 2; i++) {
            int u = i * 256 + tid;
            int r = u >> 2, q = u & 3;
            int gi = ((o0 + r) << 5) + (k0 >> 3) + q;   // uint4 index: row*32 + (k0+q*8)/8
            int so = r * 80 + q * 16;
            *(uint4*)(smem + WHI + so) = WhiG[gi];
            *(uint4*)(smem + WLO + so) = WloG[gi];
        }
        // X tile: 32 k x 128 n fp32 -> split bf16 hi/lo
        #pragma unroll
        for (int i = 0; i < 4; i++) {
            int u = i * 256 + tid;
            int r = u >> 5, s = u & 31;
            size_t off = (size_t)(k0 + r) * N_ + n0 + s * 4;
            float4 xv = *(const float4*)&X1b[off];
            if (MODE != 0) {
                float4 x2 = *(const float4*)&X2b[off];
                if (MODE == 1) { xv.x += x2.x; xv.y += x2.y; xv.z += x2.z; xv.w += x2.w; }
                else           { xv.x -= x2.x; xv.y -= x2.y; xv.z -= x2.z; xv.w -= x2.w; }
            }
            __nv_bfloat16 h0 = __float2bfloat16(xv.x), h1 = __float2bfloat16(xv.y);
            __nv_bfloat16 h2 = __float2bfloat16(xv.z), h3 = __float2bfloat16(xv.w);
            int so = SW256(r * 256 + s * 8);
            ((u32*)(smem + XHI + so))[0] = pkbf(__bfloat162float(h0), __bfloat162float(h1));
            ((u32*)(smem + XHI + so))[1] = pkbf(__bfloat162float(h2), __bfloat162float(h3));
            ((u32*)(smem + XLO + so))[0] = pkbf(xv.x - __bfloat162float(h0), xv.y - __bfloat162float(h1));
            ((u32*)(smem + XLO + so))[1] = pkbf(xv.z - __bfloat162float(h2), xv.w - __bfloat162float(h3));
        }
        __syncthreads();
        #pragma unroll
        for (int kk = 0; kk < 2; kk++) {
            int rsub = ((lane >> 3) & 1) * 8 + (lane & 7);
            u32 ah[2][4], al[2][4], bhf[8][2], blf[8][2];
            #pragma unroll
            for (int ma = 0; ma < 2; ma++) {
                u32 ad = sbase + (wy * 32 + ma * 16 + rsub) * 80 + (kk * 2 + (lane >> 4)) * 16;
                ldm_x4(ah[ma], ad + WHI);
                ldm_x4(al[ma], ad + WLO);
            }
            #pragma unroll
            for (int ng = 0; ng < 4; ng++) {
                int krow = kk * 16 + ((lane >> 4) & 1) * 8 + (lane & 7);
                int ncol = wx * 64 + ng * 16 + ((lane >> 3) & 1) * 8;
                u32 ad = sbase + SW256(krow * 256 + ncol * 2);
                u32 t4[4];
                ldm_x4t(t4, ad + XHI);
                bhf[ng * 2][0] = t4[0]; bhf[ng * 2][1] = t4[2];
                bhf[ng * 2 + 1][0] = t4[1]; bhf[ng * 2 + 1][1] = t4[3];
                ldm_x4t(t4, ad + XLO);
                blf[ng * 2][0] = t4[0]; blf[ng * 2][1] = t4[2];
                blf[ng * 2 + 1][0] = t4[1]; blf[ng * 2 + 1][1] = t4[3];
            }
            #pragma unroll
            for (int ma = 0; ma < 2; ma++)
                #pragma unroll
                for (int nb = 0; nb < 8; nb++) {
                    mma16816(acc[ma][nb], ah[ma], bhf[nb]);
                    mma16816(acc[ma][nb], ah[ma], blf[nb]);
                    mma16816(acc[ma][nb], al[ma], bhf[nb]);
                }
        }
        __syncthreads();
    }
    #pragma unroll
    for (int ma = 0; ma < 2; ma++)
        #pragma unroll
        for (int half = 0; half < 2; half++) {
            int o = o0 + wy * 32 + ma * 16 + half * 8 + (lane >> 2);
            float bv = bias ? bias[o] : 0.f;
            #pragma unroll
            for (int nb = 0; nb < 8; nb++) {
                int n = n0 + wx * 64 + nb * 8 + (lane & 3) * 2;
                float2 r;
                r.x = acc[ma][nb][half * 2] + bv;
                r.y = acc[ma][nb][half * 2 + 1] + bv;
                *(float2*)&Y[((size_t)(b * C_ + o)) * N_ + n] = r;
            }
        }
}

// ------------------------- BN stats ------------------------------------------
__global__ void k_bnstats(const float* __restrict__ gamma, const float* __restrict__ beta) {
    int c = blockIdx.x, tid = threadIdx.x;
    float s = 0.f, s2 = 0.f;
    for (int b = 0; b < B_; b++) {
        const float* p = g_t + ((size_t)b * C_ + c) * N_;
        for (int i = tid; i < N_; i += 256) {
            float v = p[i];
            s += v;
            s2 = fmaf(v, v, s2);
        }
    }
    __shared__ float red[256];
    red[tid] = s; __syncthreads();
    for (int st = 128; st > 0; st >>= 1) { if (tid < st) red[tid] += red[tid + st]; __syncthreads(); }
    s = red[0]; __syncthreads();
    red[tid] = s2; __syncthreads();
    for (int st = 128; st > 0; st >>= 1) { if (tid < st) red[tid] += red[tid + st]; __syncthreads(); }
    s2 = red[0];
    if (tid == 0) {
        float mean = s * (1.f / (B_ * N_));
        float var = s2 * (1.f / (B_ * N_)) - mean * mean;
        float inv = rsqrtf(var + 1e-5f);
        g_scale[c] = gamma[c] * inv;
        g_shift[c] = beta[c] - mean * inv * gamma[c];
    }
}

__global__ void k_bnapply() {
    int idx = blockIdx.x * 256 + threadIdx.x;
    int c = (idx >> 11) & (C_ - 1);
    g_h[idx] = fmaxf(fmaf(g_scale[c], g_t[idx], g_shift[c]), 0.f);
}

// ------------------------- Q split (quirky perm) + bf16 hi/lo ---------------
__global__ void k_qsplit() {
    int idx = blockIdx.x * 256 + threadIdx.x;     // [bh][nn][d]
    int d = idx & 63;
    int nn = (idx >> 6) & (N_ - 1);
    int bh = idx >> 17;
    int b = bh >> 2, hh = bh & 3;
    float v = g_q[((size_t)(b * C_ + ((nn & 3) << 6) + d)) * N_ + (hh << 9) + (nn >> 2)];
    __nv_bfloat16 hi = __float2bfloat16(v);
    g_Qhi[idx] = hi;
    g_Qlo[idx] = __float2bfloat16(v - __bfloat162float(hi));
}

// ------------------------- K transpose + bf16 hi/lo --------------------------
__global__ __launch_bounds__(256) void k_ktsplit() {
    __shared__ float tile[64][65];
    int m0 = blockIdx.x * 64, bh = blockIdx.y;
    int b = bh >> 2, hh = bh & 3;
    int t = threadIdx.x;
    int dr = t >> 4, m4 = (t & 15) * 4;
    #pragma unroll
    for (int i = 0; i < 4; i++) {
        int d = dr + i * 16;
        float4 v = *(const float4*)&g_q[((size_t)(b * C_ + hh * 64 + d)) * N_ + m0 + m4];
        tile[d][m4 + 0] = v.x; tile[d][m4 + 1] = v.y;
        tile[d][m4 + 2] = v.z; tile[d][m4 + 3] = v.w;
    }
    __syncthreads();
    #pragma unroll
    for (int i = 0; i < 8; i++) {
        int lin = i * 256 + t;
        int m = lin >> 5, dp = lin & 31;
        float v0 = tile[2 * dp][m], v1 = tile[2 * dp + 1][m];
        __nv_bfloat16 h0 = __float2bfloat16(v0), h1 = __float2bfloat16(v1);
        float l0 = v0 - __bfloat162float(h0), l1 = v1 - __bfloat162float(h1);
        size_t o = ((size_t)(bh * 2048 + m0 + m)) * 32 + dp;
        ((u32*)g_Kthi)[o] = pkbf(__bfloat162float(h0), __bfloat162float(h1));
        ((u32*)g_Ktlo)[o] = pkbf(l0, l1);
    }
}

// ------------------------- V -> bf16 -----------------------------------------
__global__ void k_vbf16() {
    int idx = blockIdx.x * 256 + threadIdx.x;
    float4 v = *(const float4*)&g_v[(size_t)idx * 4];
    uint2 o; o.x = pkbf(v.x, v.y); o.y = pkbf(v.z, v.w);
    *(uint2*)&g_Vb[(size_t)idx * 4] = o;
}

// ------------------------- energy MMA (split-bf16) ---------------------------
// E[nn][m] = Q . Kt, bf16 output; row-softmax partials computed on ROUNDED E.
__global__ __launch_bounds__(256) void k_energy_mma() {
    extern __shared__ char smem[];
    const int AHI = 0, ALO = 16384, BHI = 32768, BLO = 49152;
    const u32 sbase = smem_u32(smem);
    int tid = threadIdx.x, wid = tid >> 5, lane = tid & 31;
    int mt = blockIdx.x, nt = blockIdx.y, bh = blockIdx.z;
    int m0 = mt * 128, nn0 = nt * 128;
    int wy = wid >> 1, wx = wid & 1;   // warp: 32 nn x 64 m

    const uint4* Ah = (const uint4*)g_Qhi + ((size_t)(bh * 2048 + nn0)) * 8;
    const uint4* Al = (const uint4*)g_Qlo + ((size_t)(bh * 2048 + nn0)) * 8;
    const uint4* Bh = (const uint4*)g_Kthi + ((size_t)(bh * 2048 + m0)) * 8;
    const uint4* Bl = (const uint4*)g_Ktlo + ((size_t)(bh * 2048 + m0)) * 8;
    #pragma unroll
    for (int i = 0; i < 4; i++) {
        int u = i * 256 + tid;
        int r = u >> 3, q = u & 7;
        int so = SW128(r * 128 + q * 16);
        *(uint4*)(smem + AHI + so) = Ah[(size_t)r * 8 + q];
        *(uint4*)(smem + ALO + so) = Al[(size_t)r * 8 + q];
        *(uint4*)(smem + BHI + so) = Bh[(size_t)r * 8 + q];
        *(uint4*)(smem + BLO + so) = Bl[(size_t)r * 8 + q];
    }
    __syncthreads();

    float acc[2][8][4] = {};
    #pragma unroll
    for (int ks = 0; ks < 4; ks++) {
        u32 ah[2][4], al[2][4], bhf[8][2], blf[8][2];
        int rsub = ((lane >> 3) & 1) * 8 + (lane & 7);
        int q = ks * 2 + (lane >> 4);
        #pragma unroll
        for (int ma = 0; ma < 2; ma++) {
            int row = wy * 32 + ma * 16 + rsub;
            u32 off = SW128(row * 128 + q * 16);
            ldm_x4(ah[ma], sbase + AHI + off);
            ldm_x4(al[ma], sbase + ALO + off);
        }
        #pragma unroll
        for (int p = 0; p < 4; p++) {
            int row = wx * 64 + p * 16 + rsub;
            u32 off = SW128(row * 128 + q * 16);
            u32 t4[4];
            ldm_x4(t4, sbase + BHI + off);
            bhf[p * 2][0] = t4[0]; bhf[p * 2][1] = t4[2];
            bhf[p * 2 + 1][0] = t4[1]; bhf[p * 2 + 1][1] = t4[3];
            ldm_x4(t4, sbase + BLO + off);
            blf[p * 2][0] = t4[0]; blf[p * 2][1] = t4[2];
            blf[p * 2 + 1][0] = t4[1]; blf[p * 2 + 1][1] = t4[3];
        }
        #pragma unroll
        for (int ma = 0; ma < 2; ma++)
            #pragma unroll
            for (int na = 0; na < 8; na++) {
                mma16816(acc[ma][na], ah[ma], bhf[na]);
                mma16816(acc[ma][na], ah[ma], blf[na]);
                mma16816(acc[ma][na], al[ma], bhf[na]);
            }
    }

    // epilogue: round to bf16, store, stats on rounded values
    #pragma unroll
    for (int ma = 0; ma < 2; ma++) {
        #pragma unroll
        for (int half = 0; half < 2; half++) {
            int rloc = wy * 32 + ma * 16 + half * 8 + (lane >> 2);
            int rowg = bh * 2048 + nn0 + rloc;
            u32 pk[8];
            float fr[16];
            #pragma unroll
            for (int na = 0; na < 8; na++) {
                __nv_bfloat162 h2 = __floats2bfloat162_rn(acc[ma][na][half * 2],
                                                          acc[ma][na][half * 2 + 1]);
                pk[na] = *(u32*)&h2;
                float2 f2 = __bfloat1622float2(h2);
                fr[na * 2] = f2.x; fr[na * 2 + 1] = f2.y;
            }
            float mx = -3.4e38f;
            #pragma unroll
            for (int i = 0; i < 16; i++) mx = fmaxf(mx, fr[i]);
            mx = fmaxf(mx, __shfl_xor_sync(0xffffffffu, mx, 1));
            mx = fmaxf(mx, __shfl_xor_sync(0xffffffffu, mx, 2));
            float s = 0.f;
            #pragma unroll
            for (int i = 0; i < 16; i++) s += __expf(fr[i] - mx);
            s += __shfl_xor_sync(0xffffffffu, s, 1);
            s += __shfl_xor_sync(0xffffffffu, s, 2);
            u32* Eo = (u32*)g_E + ((((size_t)bh << 22) + (size_t)(nn0 + rloc) * 2048
                      + m0 + wx * 64) >> 1) + (lane & 3);
            #pragma unroll
            for (int na = 0; na < 8; na++) Eo[na * 4] = pk[na];
            if ((lane & 3) == 0) {
                g_pm[(size_t)rowg * 32 + mt * 2 + wx] = mx;
                g_ps[(size_t)rowg * 32 + mt * 2 + wx] = s;
            }
        }
    }
}

// combine 32 row partials -> rm, rsinv
__global__ void k_rowreduce() {
    int row = blockIdx.x * 8 + (threadIdx.x >> 5);
    int lane = threadIdx.x & 31;
    float pm = g_pm[((size_t)row << 5) | lane];
    float ps = g_ps[((size_t)row << 5) | lane];
    float m = pm;
    #pragma unroll
    for (int o = 16; o > 0; o >>= 1) m = fmaxf(m, __shfl_xor_sync(0xffffffffu, m, o));
    float s = ps * __expf(pm - m);
    #pragma unroll
    for (int o = 16; o > 0; o >>= 1) s += __shfl_xor_sync(0xffffffffu, s, o);
    if (lane == 0) { g_rm[row] = m; g_rsinv[row] = 1.f / s; }
}

// ------------------------- fused attn: ea on-the-fly + local colsum + MMA ----
// D[j][d] = sum_nn ea[nn][j] * V[d][nn] * csinv[j]
__global__ __launch_bounds__(256) void k_attn_mma() {
    extern __shared__ char smem[];
    const int EA = 0, VOF = 16384, SCOL = 24576, RMRS = 25088;
    const u32 sbase = smem_u32(smem);
    int tid = threadIdx.x, wid = tid >> 5, lane = tid & 31;
    int jt = blockIdx.x, bh = blockIdx.y;
    int b = bh >> 2, hh = bh & 3;
    int j0 = jt * 128;
    int wy = wid >> 1, wx = wid & 1;   // warp: 32 j x 32 d

    float* scol = (float*)(smem + SCOL);
    float2* rmrs = (float2*)(smem + RMRS);
    if (tid < 128) scol[tid] = 0.f;
    for (int i = tid; i < 2048; i += 256) {
        float2 rr; rr.x = g_rm[bh * 2048 + i]; rr.y = g_rsinv[bh * 2048 + i];
        rmrs[i] = rr;
    }
    __syncthreads();

    const uint4* Eg = (const uint4*)g_E;     // row pitch 256 uint4
    const uint4* Vg = (const uint4*)g_Vb;    // row pitch 256 uint4
    int jq = tid & 15, r0 = tid >> 4;
    float sums[8];
    #pragma unroll
    for (int i = 0; i < 8; i++) sums[i] = 0.f;

    float acc[2][4][4] = {};
    for (int c = 0; c < 32; c++) {
        int nn0 = c * 64;
        // ea compute: 4 rows x 8 j per thread
        #pragma unroll
        for (int i = 0; i < 4; i++) {
            int nnl = i * 16 + r0;
            int nn = nn0 + nnl;
            uint4 e4 = Eg[((size_t)(bh * 2048 + nn)) * 256 + (j0 >> 3) + jq];
            float2 rr = rmrs[nn];
            u32 pk[4];
            const u32* ew = (const u32*)&e4;
            #pragma unroll
            for (int q = 0; q < 4; q++) {
                float2 f2 = __bfloat1622float2(*(const __nv_bfloat162*)&ew[q]);
                float ea0 = __expf(__expf(f2.x - rr.x) * rr.y);
                float ea1 = __expf(__expf(f2.y - rr.x) * rr.y);
                __nv_bfloat162 h2 = __floats2bfloat162_rn(ea0, ea1);
                pk[q] = *(u32*)&h2;
                float2 fb = __bfloat1622float2(h2);
                sums[q * 2] += fb.x; sums[q * 2 + 1] += fb.y;
            }
            *(uint4*)(smem + EA + SW256(nnl * 256 + jq * 16)) = *(uint4*)pk;
        }
        // V tile: 64 d x 64 nn
        #pragma unroll
        for (int i = 0; i < 2; i++) {
            int u = i * 256 + tid;
            int r = u >> 3, q = u & 7;
            *(uint4*)(smem + VOF + SW128(r * 128 + q * 16)) =
                Vg[((size_t)(b * C_ + hh * 64 + r)) * 256 + (nn0 >> 3) + q];
        }
        __syncthreads();
        #pragma unroll
        for (int ks = 0; ks < 4; ks++) {
            u32 af[2][4], bf[4][2];
            int rsub = ((lane >> 3) & 1) * 8 + (lane & 7);
            #pragma unroll
            for (int ma = 0; ma < 2; ma++) {
                int nnrow = ks * 16 + ((lane >> 4) & 1) * 8 + (lane & 7);
                int jcol = wy * 32 + ma * 16 + ((lane >> 3) & 1) * 8;
                ldm_x4t(af[ma], sbase + EA + SW256(nnrow * 256 + jcol * 2));
            }
            #pragma unroll
            for (int p = 0; p < 2; p++) {
                int row = wx * 32 + p * 16 + rsub;
                int q = ks * 2 + (lane >> 4);
                u32 t4[4];
                ldm_x4(t4, sbase + VOF + SW128(row * 128 + q * 16));
                bf[p * 2][0] = t4[0]; bf[p * 2][1] = t4[2];
                bf[p * 2 + 1][0] = t4[1]; bf[p * 2 + 1][1] = t4[3];
            }
            #pragma unroll
            for (int ma = 0; ma < 2; ma++)
                #pragma unroll
                for (int na = 0; na < 4; na++)
                    mma16816(acc[ma][na], af[ma], bf[na]);
        }
        __syncthreads();
    }
    // column sums -> csinv
    #pragma unroll
    for (int i = 0; i < 8; i++) atomicAdd(&scol[jq * 8 + i], sums[i]);
    __syncthreads();
    if (tid < 128) scol[tid] = 1.f / scol[tid];
    __syncthreads();
    // read csinv to regs (stg overwrites scol region)
    float csv[2][2];
    #pragma unroll
    for (int ma = 0; ma < 2; ma++)
        #pragma unroll
        for (int half = 0; half < 2; half++)
            csv[ma][half] = scol[wy * 32 + ma * 16 + half * 8 + (lane >> 2)];
    __syncthreads();
    // epilogue: scale, transpose via smem, coalesced xr write
    float* stg = (float*)smem;                  // [128][65]
    #pragma unroll
    for (int ma = 0; ma < 2; ma++)
        #pragma unroll
        for (int half = 0; half < 2; half++) {
            int jl = wy * 32 + ma * 16 + half * 8 + (lane >> 2);
            float cs = csv[ma][half];
            #pragma unroll
            for (int na = 0; na < 4; na++) {
                int d = wx * 32 + na * 8 + (lane & 3) * 2;
                stg[jl * 65 + d]     = acc[ma][na][half * 2] * cs;
                stg[jl * 65 + d + 1] = acc[ma][na][half * 2 + 1] * cs;
            }
        }
    __syncthreads();
    for (int it = 0; it < 32; it++) {
        int d = it * 2 + (tid >> 7);
        int j = tid & 127;
        g_xr[((size_t)(b * C_ + hh * 64 + d)) * N_ + j0 + j] = stg[j * 65 + d];
    }
}

// ------------------------- residual + BN + relu + output write ---------------
__global__ void k_residual(int layer, float* __restrict__ out) {
    int idx = blockIdx.x * 256 + threadIdx.x;
    int b = idx >> 19;
    int c = (idx >> 11) & (C_ - 1);
    int n = idx & (N_ - 1);
    float r = fmaxf(fmaf(g_scale[c], g_t[idx], g_shift[c]), 0.f);
    float o = g_h[idx] + r;
    g_h[idx] = o;
    out[((size_t)b * (4 * C_) + layer * C_ + c) * N_ + n] = o;
}

// ------------------------- host orchestration --------------------------------
extern "C" void kernel_launch(void* const* d_in, const int* in_sizes, int n_in,
                              void* d_out, int out_size) {
    (void)in_sizes; (void)n_in; (void)out_size;
    const float* x       = (const float*)d_in[0];
    const float* xyz     = (const float*)d_in[1];
    const float* conv1_w = (const float*)d_in[2];
    const float* pos_w   = (const float*)d_in[3];
    const float* pos_b   = (const float*)d_in[4];
    const float* bn1_g   = (const float*)d_in[5];
    const float* bn1_b   = (const float*)d_in[6];
    const float* qk_w    = (const float*)d_in[7];
    const float* v_w     = (const float*)d_in[8];
    const float* v_b     = (const float*)d_in[9];
    const float* t_w     = (const float*)d_in[10];
    const float* t_b     = (const float*)d_in[11];
    const float* bn_g    = (const float*)d_in[12];
    const float* bn_b    = (const float*)d_in[13];
    float* out = (float*)d_out;

    float *ph, *pemb, *pq, *pv, *pxr, *pt;
    cudaGetSymbolAddress((void**)&ph,   g_h);
    cudaGetSymbolAddress((void**)&pemb, g_emb);
    cudaGetSymbolAddress((void**)&pq,   g_q);
    cudaGetSymbolAddress((void**)&pv,   g_v);
    cudaGetSymbolAddress((void**)&pxr,  g_xr);
    cudaGetSymbolAddress((void**)&pt,   g_t);

    cudaFuncSetAttribute(k_energy_mma,  cudaFuncAttributeMaxDynamicSharedMemorySize, 65536);
    cudaFuncSetAttribute(k_attn_mma,    cudaFuncAttributeMaxDynamicSharedMemorySize, 41472);
    cudaFuncSetAttribute(k_convmma<0>,  cudaFuncAttributeMaxDynamicSharedMemorySize, 36864);
    cudaFuncSetAttribute(k_convmma<1>,  cudaFuncAttributeMaxDynamicSharedMemorySize, 36864);
    cudaFuncSetAttribute(k_convmma<2>,  cudaFuncAttributeMaxDynamicSharedMemorySize, 36864);

    const int EW = (B_ * C_ * N_) / 256;
    dim3 gCv(16, 2, 4);

    k_wsplit<<<13 * 256, 256>>>(conv1_w, qk_w, v_w, t_w);
    k_posemb<<<EW, 256>>>(xyz, pos_w, pos_b);
    k_convmma<0><<<gCv, 256, 36864>>>(0, x, nullptr, nullptr, pt);
    k_bnstats<<<C_, 256>>>(bn1_g, bn1_b);
    k_bnapply<<<EW, 256>>>();

    for (int i = 0; i < 4; i++) {
        const float* vb = v_b  + (size_t)i * C_;
        const float* tb = t_b  + (size_t)i * C_;
        const float* bg = bn_g + (size_t)i * C_;
        const float* bb = bn_b + (size_t)i * C_;

        k_convmma<1><<<gCv, 256, 36864>>>(1 + i, ph, pemb, nullptr, pq);
        k_convmma<1><<<gCv, 256, 36864>>>(5 + i, ph, pemb, vb, pv);
        k_qsplit<<<(BH_ * N_ * D_) / 256, 256>>>();
        k_ktsplit<<<dim3(N_ / 64, BH_), 256>>>();
        k_vbf16<<<(B_ * C_ * N_) / 1024, 256>>>();
        k_energy_mma<<<dim3(16, 16, BH_), 256, 65536>>>();
        k_rowreduce<<<(BH_ * N_) / 8, 256>>>();
        k_attn_mma<<<dim3(16, BH_), 256, 41472>>>();
        k_convmma<2><<<gCv, 256, 36864>>>(9 + i, ph, pxr, tb, pt);
        k_bnstats<<<C_, 256>>>(bg, bb);
        k_residual<<<EW, 256>>>(i, out);
    }
}

// round 9
// speedup vs baseline: 4.0354x; 1.0877x over previous
#include <cuda_runtime.h>
#include <cuda_bf16.h>
#include <cstdint>
#include <cstddef>

#define B_ 4
#define C_ 256
#define N_ 2048
#define H_ 4
#define D_ 64
#define BH_ 16

typedef unsigned long long u64;
typedef unsigned int u32;

// ------------------------- scratch (static device globals) -------------------
__device__ __nv_bfloat16 g_E[(size_t)BH_ * N_ * N_];     // 128 MiB energy bf16
__device__ float g_emb[B_ * C_ * N_];
__device__ float g_h[B_ * C_ * N_];
__device__ float g_xr[B_ * C_ * N_];
__device__ float g_t[B_ * C_ * N_];
__device__ __nv_bfloat16 g_qbhi[B_ * C_ * N_];           // q bf16 hi, [c][n]
__device__ __nv_bfloat16 g_qblo[B_ * C_ * N_];           // q bf16 lo
__device__ __nv_bfloat16 g_Vb[B_ * C_ * N_];             // v bf16
__device__ __nv_bfloat16 g_Whi[13 * C_ * C_];
__device__ __nv_bfloat16 g_Wlo[13 * C_ * C_];
__device__ float g_pm[(size_t)BH_ * N_ * 32];
__device__ float g_ps[(size_t)BH_ * N_ * 32];
__device__ float g_rm[BH_ * N_];
__device__ float g_rsinv[BH_ * N_];
__device__ float g_scale[C_];
__device__ float g_shift[C_];
__device__ float g_bns[C_];
__device__ float g_bns2[C_];

// ------------------------- helpers -------------------------------------------
__device__ __forceinline__ u32 smem_u32(const void* p) {
    u32 a;
    asm("{ .reg .u64 t; cvta.to.shared.u64 t, %1; cvt.u32.u64 %0, t; }" : "=r"(a) : "l"(p));
    return a;
}
#define SW128(o) ((o) ^ (((o) >> 3) & 0x70))
#define SW256(o) ((o) ^ (((o) >> 4) & 0x70))

__device__ __forceinline__ void ldm_x4(u32* r, u32 a) {
    asm volatile("ldmatrix.sync.aligned.m8n8.x4.shared.b16 {%0,%1,%2,%3}, [%4];"
        : "=r"(r[0]), "=r"(r[1]), "=r"(r[2]), "=r"(r[3]) : "r"(a));
}
__device__ __forceinline__ void ldm_x4t(u32* r, u32 a) {
    asm volatile("ldmatrix.sync.aligned.m8n8.x4.trans.shared.b16 {%0,%1,%2,%3}, [%4];"
        : "=r"(r[0]), "=r"(r[1]), "=r"(r[2]), "=r"(r[3]) : "r"(a));
}
__device__ __forceinline__ void mma16816(float* c, const u32* a, const u32* b) {
    asm volatile("mma.sync.aligned.m16n8k16.row.col.f32.bf16.bf16.f32 "
        "{%0,%1,%2,%3}, {%4,%5,%6,%7}, {%8,%9}, {%0,%1,%2,%3};"
        : "+f"(c[0]), "+f"(c[1]), "+f"(c[2]), "+f"(c[3])
        : "r"(a[0]), "r"(a[1]), "r"(a[2]), "r"(a[3]), "r"(b[0]), "r"(b[1]));
}
__device__ __forceinline__ u32 pkbf(float a, float b) {
    __nv_bfloat162 t = __floats2bfloat162_rn(a, b);
    return *(u32*)&t;
}

// ------------------------- positional embedding ------------------------------
__global__ void k_posemb(const float* __restrict__ xyz, const float* __restrict__ pw,
                         const float* __restrict__ pb) {
    int idx = blockIdx.x * 256 + threadIdx.x;
    int n = idx & (N_ - 1);
    int c = (idx >> 11) & (C_ - 1);
    int b = idx >> 19;
    const float* p = xyz + ((size_t)(b * N_ + n)) * 3;
    g_emb[idx] = fmaf(pw[c * 3 + 0], p[0],
                 fmaf(pw[c * 3 + 1], p[1],
                 fmaf(pw[c * 3 + 2], p[2], pb[c])));
}

// ------------------------- weight pre-split + bn accumulator zero ------------
__global__ void k_wsplit(const float* __restrict__ conv1_w, const float* __restrict__ qk_w,
                         const float* __restrict__ v_w, const float* __restrict__ t_w) {
    int idx = blockIdx.x * 256 + threadIdx.x;     // 13*65536
    if (blockIdx.x == 0 && threadIdx.x < C_) { g_bns[threadIdx.x] = 0.f; g_bns2[threadIdx.x] = 0.f; }
    int slot = idx >> 16, i = idx & 65535;
    float w;
    if (slot == 0) w = conv1_w[i];
    else if (slot < 5) w = qk_w[(slot - 1) * 65536 + i];
    else if (slot < 9) w = v_w[(slot - 5) * 65536 + i];
    else w = t_w[(slot - 9) * 65536 + i];
    __nv_bfloat16 hi = __float2bfloat16(w);
    g_Whi[idx] = hi;
    g_Wlo[idx] = __float2bfloat16(w - __bfloat162float(hi));
}

// ------------------------- conv via split-bf16 MMA ---------------------------
// MODE 0: X=X1, 1: X1+X2, 2: X1-X2
// OUT 0: fp32 Y + BN partial sums; OUT 1: bf16 hi/lo -> g_qbhi/g_qblo; OUT 2: bf16 -> g_Vb
template <int MODE, int OUT>
__global__ __launch_bounds__(256) void k_convmma(int wslot,
                                                 const float* __restrict__ X1,
                                                 const float* __restrict__ X2,
                                                 const float* __restrict__ bias,
                                                 float* __restrict__ Y) {
    extern __shared__ char smem[];
    const int WHI = 0, WLO = 10240, XHI = 20480, XLO = 28672;
    const u32 sbase = smem_u32(smem);
    int tid = threadIdx.x, wid = tid >> 5, lane = tid & 31;
    int n0 = blockIdx.x * 128, o0 = blockIdx.y * 128, b = blockIdx.z;
    int wy = wid >> 1, wx = wid & 1;   // warp: 32 o x 64 n
    const uint4* WhiG = (const uint4*)(g_Whi + (size_t)wslot * 65536);
    const uint4* WloG = (const uint4*)(g_Wlo + (size_t)wslot * 65536);
    const float* X1b = X1 + (size_t)b * C_ * N_;
    const float* X2b = (MODE != 0) ? (X2 + (size_t)b * C_ * N_) : nullptr;

    float acc[2][8][4] = {};
    for (int k0 = 0; k0 < C_; k0 += 32) {
        #pragma unroll
        for (int i = 0; i < 2; i++) {
            int u = i * 256 + tid;
            int r = u >> 2, q = u & 3;
            int gi = ((o0 + r) << 5) + (k0 >> 3) + q;
            int so = r * 80 + q * 16;
            *(uint4*)(smem + WHI + so) = WhiG[gi];
            *(uint4*)(smem + WLO + so) = WloG[gi];
        }
        #pragma unroll
        for (int i = 0; i < 4; i++) {
            int u = i * 256 + tid;
            int r = u >> 5, s = u & 31;
            size_t off = (size_t)(k0 + r) * N_ + n0 + s * 4;
            float4 xv = *(const float4*)&X1b[off];
            if (MODE != 0) {
                float4 x2 = *(const float4*)&X2b[off];
                if (MODE == 1) { xv.x += x2.x; xv.y += x2.y; xv.z += x2.z; xv.w += x2.w; }
                else           { xv.x -= x2.x; xv.y -= x2.y; xv.z -= x2.z; xv.w -= x2.w; }
            }
            __nv_bfloat16 h0 = __float2bfloat16(xv.x), h1 = __float2bfloat16(xv.y);
            __nv_bfloat16 h2 = __float2bfloat16(xv.z), h3 = __float2bfloat16(xv.w);
            int so = SW256(r * 256 + s * 8);
            ((u32*)(smem + XHI + so))[0] = pkbf(__bfloat162float(h0), __bfloat162float(h1));
            ((u32*)(smem + XHI + so))[1] = pkbf(__bfloat162float(h2), __bfloat162float(h3));
            ((u32*)(smem + XLO + so))[0] = pkbf(xv.x - __bfloat162float(h0), xv.y - __bfloat162float(h1));
            ((u32*)(smem + XLO + so))[1] = pkbf(xv.z - __bfloat162float(h2), xv.w - __bfloat162float(h3));
        }
        __syncthreads();
        #pragma unroll
        for (int kk = 0; kk < 2; kk++) {
            int rsub = ((lane >> 3) & 1) * 8 + (lane & 7);
            u32 ah[2][4], al[2][4], bhf[8][2], blf[8][2];
            #pragma unroll
            for (int ma = 0; ma < 2; ma++) {
                u32 ad = sbase + (wy * 32 + ma * 16 + rsub) * 80 + (kk * 2 + (lane >> 4)) * 16;
                ldm_x4(ah[ma], ad + WHI);
                ldm_x4(al[ma], ad + WLO);
            }
            #pragma unroll
            for (int ng = 0; ng < 4; ng++) {
                int krow = kk * 16 + ((lane >> 4) & 1) * 8 + (lane & 7);
                int ncol = wx * 64 + ng * 16 + ((lane >> 3) & 1) * 8;
                u32 ad = sbase + SW256(krow * 256 + ncol * 2);
                u32 t4[4];
                ldm_x4t(t4, ad + XHI);
                bhf[ng * 2][0] = t4[0]; bhf[ng * 2][1] = t4[2];
                bhf[ng * 2 + 1][0] = t4[1]; bhf[ng * 2 + 1][1] = t4[3];
                ldm_x4t(t4, ad + XLO);
                blf[ng * 2][0] = t4[0]; blf[ng * 2][1] = t4[2];
                blf[ng * 2 + 1][0] = t4[1]; blf[ng * 2 + 1][1] = t4[3];
            }
            #pragma unroll
            for (int ma = 0; ma < 2; ma++)
                #pragma unroll
                for (int nb = 0; nb < 8; nb++) {
                    mma16816(acc[ma][nb], ah[ma], bhf[nb]);
                    mma16816(acc[ma][nb], ah[ma], blf[nb]);
                    mma16816(acc[ma][nb], al[ma], bhf[nb]);
                }
        }
        __syncthreads();
    }
    #pragma unroll
    for (int ma = 0; ma < 2; ma++)
        #pragma unroll
        for (int half = 0; half < 2; half++) {
            int o = o0 + wy * 32 + ma * 16 + half * 8 + (lane >> 2);
            float bv = bias ? bias[o] : 0.f;
            size_t row = (size_t)(b * C_ + o);
            if (OUT == 0) {
                float s = 0.f, s2 = 0.f;
                #pragma unroll
                for (int nb = 0; nb < 8; nb++) {
                    int n = n0 + wx * 64 + nb * 8 + (lane & 3) * 2;
                    float rx = acc[ma][nb][half * 2] + bv;
                    float ry = acc[ma][nb][half * 2 + 1] + bv;
                    float2 r; r.x = rx; r.y = ry;
                    *(float2*)&Y[row * N_ + n] = r;
                    s += rx + ry;
                    s2 = fmaf(rx, rx, fmaf(ry, ry, s2));
                }
                s += __shfl_xor_sync(0xffffffffu, s, 1);
                s += __shfl_xor_sync(0xffffffffu, s, 2);
                s2 += __shfl_xor_sync(0xffffffffu, s2, 1);
                s2 += __shfl_xor_sync(0xffffffffu, s2, 2);
                if ((lane & 3) == 0) { atomicAdd(&g_bns[o], s); atomicAdd(&g_bns2[o], s2); }
            } else {
                #pragma unroll
                for (int nb = 0; nb < 8; nb++) {
                    int nc = (n0 >> 1) + wx * 32 + nb * 4 + (lane & 3);
                    float rx = acc[ma][nb][half * 2] + bv;
                    float ry = acc[ma][nb][half * 2 + 1] + bv;
                    if (OUT == 1) {
                        __nv_bfloat16 h0 = __float2bfloat16(rx), h1 = __float2bfloat16(ry);
                        ((u32*)g_qbhi)[row * 1024 + nc] = pkbf(__bfloat162float(h0), __bfloat162float(h1));
                        ((u32*)g_qblo)[row * 1024 + nc] = pkbf(rx - __bfloat162float(h0), ry - __bfloat162float(h1));
                    } else {
                        ((u32*)g_Vb)[row * 1024 + nc] = pkbf(rx, ry);
                    }
                }
            }
        }
}

// ------------------------- BN finalize (scale/shift + re-zero accum) ---------
__global__ void k_bnfinal(const float* __restrict__ gamma, const float* __restrict__ beta) {
    int c = threadIdx.x;
    float s = g_bns[c], s2 = g_bns2[c];
    float mean = s * (1.f / (B_ * N_));
    float var = s2 * (1.f / (B_ * N_)) - mean * mean;
    float inv = rsqrtf(var + 1e-5f);
    g_scale[c] = gamma[c] * inv;
    g_shift[c] = beta[c] - mean * inv * gamma[c];
    g_bns[c] = 0.f; g_bns2[c] = 0.f;
}

__global__ void k_bnapply() {
    int idx = blockIdx.x * 256 + threadIdx.x;
    int c = (idx >> 11) & (C_ - 1);
    g_h[idx] = fmaxf(fmaf(g_scale[c], g_t[idx], g_shift[c]), 0.f);
}

// ------------------------- energy MMA (2-pass split, fused perm/transpose) ---
// E[nn][m] = Q[nn][d] . K[d][m];  Q = quirky perm of q, K = native q slice.
// E ~= Qhi.Khi + Qhi.Klo   (Qlo terms dropped; same scale as bf16 E rounding)
// A smem rows relabeled nn' = quad*32 + nloc; epilogue maps back.
__global__ __launch_bounds__(256) void k_energy_mma() {
    extern __shared__ char smem[];
    const int AHI = 0, BHI = 16384, BLO = 32768;
    const u32 sbase = smem_u32(smem);
    int tid = threadIdx.x, wid = tid >> 5, lane = tid & 31;
    int mt = blockIdx.x, nt = blockIdx.y, bh = blockIdx.z;
    int m0 = mt * 128;
    int b = bh >> 2, hh = bh & 3;
    int wy = wid >> 1, wx = wid & 1;   // warp: 32 nn' x 64 m

    // A: perm tile [64 d][128 nn'], hi only
    const uint4* Qg = (const uint4*)g_qbhi;
    #pragma unroll
    for (int i = 0; i < 4; i++) {
        int u = i * 256 + tid;
        int c = u >> 2, q = u & 3;
        int d = c & 63, quad = c >> 6;
        uint4 v = Qg[((size_t)(b * C_ + c)) * 256 + hh * 64 + nt * 4 + q];
        *(uint4*)(smem + AHI + SW256(d * 256 + quad * 64 + q * 16)) = v;
    }
    // B: native [64 d][128 m], hi + lo
    const uint4* Kl = (const uint4*)g_qblo;
    #pragma unroll
    for (int i = 0; i < 4; i++) {
        int u = i * 256 + tid;
        int r = u >> 4, q = u & 15;
        size_t gi = ((size_t)(b * C_ + hh * 64 + r)) * 256 + (m0 >> 3) + q;
        int so = SW256(r * 256 + q * 16);
        *(uint4*)(smem + BHI + so) = Qg[gi];
        *(uint4*)(smem + BLO + so) = Kl[gi];
    }
    __syncthreads();

    float acc[2][8][4] = {};
    #pragma unroll
    for (int ks = 0; ks < 4; ks++) {
        u32 af[2][4], bhf[8][2], blf[8][2];
        int drow = ks * 16 + ((lane >> 4) & 1) * 8 + (lane & 7);
        #pragma unroll
        for (int ma = 0; ma < 2; ma++) {
            int nncol = wy * 32 + ma * 16 + ((lane >> 3) & 1) * 8;
            ldm_x4t(af[ma], sbase + AHI + SW256(drow * 256 + nncol * 2));
        }
        #pragma unroll
        for (int ng = 0; ng < 4; ng++) {
            int mcol = wx * 64 + ng * 16 + ((lane >> 3) & 1) * 8;
            u32 ad = SW256(drow * 256 + mcol * 2);
            u32 t4[4];
            ldm_x4t(t4, sbase + BHI + ad);
            bhf[ng * 2][0] = t4[0]; bhf[ng * 2][1] = t4[2];
            bhf[ng * 2 + 1][0] = t4[1]; bhf[ng * 2 + 1][1] = t4[3];
            ldm_x4t(t4, sbase + BLO + ad);
            blf[ng * 2][0] = t4[0]; blf[ng * 2][1] = t4[2];
            blf[ng * 2 + 1][0] = t4[1]; blf[ng * 2 + 1][1] = t4[3];
        }
        #pragma unroll
        for (int ma = 0; ma < 2; ma++)
            #pragma unroll
            for (int na = 0; na < 8; na++) {
                mma16816(acc[ma][na], af[ma], bhf[na]);
                mma16816(acc[ma][na], af[ma], blf[na]);
            }
    }

    // epilogue: round to bf16, store (perm-mapped rows), stats on rounded values
    #pragma unroll
    for (int ma = 0; ma < 2; ma++) {
        #pragma unroll
        for (int half = 0; half < 2; half++) {
            int rp = wy * 32 + ma * 16 + half * 8 + (lane >> 2);    // nn'
            int nn = nt * 128 + ((rp & 31) << 2) + (rp >> 5);        // actual nn
            int rowg = bh * 2048 + nn;
            u32 pk[8];
            float fr[16];
            #pragma unroll
            for (int na = 0; na < 8; na++) {
                __nv_bfloat162 h2 = __floats2bfloat162_rn(acc[ma][na][half * 2],
                                                          acc[ma][na][half * 2 + 1]);
                pk[na] = *(u32*)&h2;
                float2 f2 = __bfloat1622float2(h2);
                fr[na * 2] = f2.x; fr[na * 2 + 1] = f2.y;
            }
            float mx = -3.4e38f;
            #pragma unroll
            for (int i = 0; i < 16; i++) mx = fmaxf(mx, fr[i]);
            mx = fmaxf(mx, __shfl_xor_sync(0xffffffffu, mx, 1));
            mx = fmaxf(mx, __shfl_xor_sync(0xffffffffu, mx, 2));
            float s = 0.f;
            #pragma unroll
            for (int i = 0; i < 16; i++) s += __expf(fr[i] - mx);
            s += __shfl_xor_sync(0xffffffffu, s, 1);
            s += __shfl_xor_sync(0xffffffffu, s, 2);
            u32* Eo = (u32*)g_E + ((((size_t)bh << 22) + (size_t)nn * 2048
                      + m0 + wx * 64) >> 1) + (lane & 3);
            #pragma unroll
            for (int na = 0; na < 8; na++) Eo[na * 4] = pk[na];
            if ((lane & 3) == 0) {
                g_pm[(size_t)rowg * 32 + mt * 2 + wx] = mx;
                g_ps[(size_t)rowg * 32 + mt * 2 + wx] = s;
            }
        }
    }
}

// combine 32 row partials -> rm, rsinv
__global__ void k_rowreduce() {
    int row = blockIdx.x * 8 + (threadIdx.x >> 5);
    int lane = threadIdx.x & 31;
    float pm = g_pm[((size_t)row << 5) | lane];
    float ps = g_ps[((size_t)row << 5) | lane];
    float m = pm;
    #pragma unroll
    for (int o = 16; o > 0; o >>= 1) m = fmaxf(m, __shfl_xor_sync(0xffffffffu, m, o));
    float s = ps * __expf(pm - m);
    #pragma unroll
    for (int o = 16; o > 0; o >>= 1) s += __shfl_xor_sync(0xffffffffu, s, o);
    if (lane == 0) { g_rm[row] = m; g_rsinv[row] = 1.f / s; }
}

// ------------------------- fused attn: ea on-the-fly + local colsum + MMA ----
__global__ __launch_bounds__(256) void k_attn_mma() {
    extern __shared__ char smem[];
    const int EA = 0, VOF = 16384, SCOL = 24576, RMRS = 25088;
    const u32 sbase = smem_u32(smem);
    int tid = threadIdx.x, wid = tid >> 5, lane = tid & 31;
    int jt = blockIdx.x, bh = blockIdx.y;
    int b = bh >> 2, hh = bh & 3;
    int j0 = jt * 128;
    int wy = wid >> 1, wx = wid & 1;   // warp: 32 j x 32 d

    float* scol = (float*)(smem + SCOL);
    float2* rmrs = (float2*)(smem + RMRS);
    if (tid < 128) scol[tid] = 0.f;
    for (int i = tid; i < 2048; i += 256) {
        float2 rr; rr.x = g_rm[bh * 2048 + i]; rr.y = g_rsinv[bh * 2048 + i];
        rmrs[i] = rr;
    }
    __syncthreads();

    const uint4* Eg = (const uint4*)g_E;
    const uint4* Vg = (const uint4*)g_Vb;
    int jq = tid & 15, r0 = tid >> 4;
    float sums[8];
    #pragma unroll
    for (int i = 0; i < 8; i++) sums[i] = 0.f;

    float acc[2][4][4] = {};
    for (int c = 0; c < 32; c++) {
        int nn0 = c * 64;
        #pragma unroll
        for (int i = 0; i < 4; i++) {
            int nnl = i * 16 + r0;
            int nn = nn0 + nnl;
            uint4 e4 = Eg[((size_t)(bh * 2048 + nn)) * 256 + (j0 >> 3) + jq];
            float2 rr = rmrs[nn];
            u32 pk[4];
            const u32* ew = (const u32*)&e4;
            #pragma unroll
            for (int q = 0; q < 4; q++) {
                float2 f2 = __bfloat1622float2(*(const __nv_bfloat162*)&ew[q]);
                float ea0 = __expf(__expf(f2.x - rr.x) * rr.y);
                float ea1 = __expf(__expf(f2.y - rr.x) * rr.y);
                __nv_bfloat162 h2 = __floats2bfloat162_rn(ea0, ea1);
                pk[q] = *(u32*)&h2;
                float2 fb = __bfloat1622float2(h2);
                sums[q * 2] += fb.x; sums[q * 2 + 1] += fb.y;
            }
            *(uint4*)(smem + EA + SW256(nnl * 256 + jq * 16)) = *(uint4*)pk;
        }
        #pragma unroll
        for (int i = 0; i < 2; i++) {
            int u = i * 256 + tid;
            int r = u >> 3, q = u & 7;
            *(uint4*)(smem + VOF + SW128(r * 128 + q * 16)) =
                Vg[((size_t)(b * C_ + hh * 64 + r)) * 256 + (nn0 >> 3) + q];
        }
        __syncthreads();
        #pragma unroll
        for (int ks = 0; ks < 4; ks++) {
            u32 af[2][4], bf[4][2];
            int rsub = ((lane >> 3) & 1) * 8 + (lane & 7);
            #pragma unroll
            for (int ma = 0; ma < 2; ma++) {
                int nnrow = ks * 16 + ((lane >> 4) & 1) * 8 + (lane & 7);
                int jcol = wy * 32 + ma * 16 + ((lane >> 3) & 1) * 8;
                ldm_x4t(af[ma], sbase + EA + SW256(nnrow * 256 + jcol * 2));
            }
            #pragma unroll
            for (int p = 0; p < 2; p++) {
                int row = wx * 32 + p * 16 + rsub;
                int q = ks * 2 + (lane >> 4);
                u32 t4[4];
                ldm_x4(t4, sbase + VOF + SW128(row * 128 + q * 16));
                bf[p * 2][0] = t4[0]; bf[p * 2][1] = t4[2];
                bf[p * 2 + 1][0] = t4[1]; bf[p * 2 + 1][1] = t4[3];
            }
            #pragma unroll
            for (int ma = 0; ma < 2; ma++)
                #pragma unroll
                for (int na = 0; na < 4; na++)
                    mma16816(acc[ma][na], af[ma], bf[na]);
        }
        __syncthreads();
    }
    #pragma unroll
    for (int i = 0; i < 8; i++) atomicAdd(&scol[jq * 8 + i], sums[i]);
    __syncthreads();
    if (tid < 128) scol[tid] = 1.f / scol[tid];
    __syncthreads();
    float csv[2][2];
    #pragma unroll
    for (int ma = 0; ma < 2; ma++)
        #pragma unroll
        for (int half = 0; half < 2; half++)
            csv[ma][half] = scol[wy * 32 + ma * 16 + half * 8 + (lane >> 2)];
    __syncthreads();
    float* stg = (float*)smem;                  // [128][65]
    #pragma unroll
    for (int ma = 0; ma < 2; ma++)
        #pragma unroll
        for (int half = 0; half < 2; half++) {
            int jl = wy * 32 + ma * 16 + half * 8 + (lane >> 2);
            float cs = csv[ma][half];
            #pragma unroll
            for (int na = 0; na < 4; na++) {
                int d = wx * 32 + na * 8 + (lane & 3) * 2;
                stg[jl * 65 + d]     = acc[ma][na][half * 2] * cs;
                stg[jl * 65 + d + 1] = acc[ma][na][half * 2 + 1] * cs;
            }
        }
    __syncthreads();
    for (int it = 0; it < 32; it++) {
        int d = it * 2 + (tid >> 7);
        int j = tid & 127;
        g_xr[((size_t)(b * C_ + hh * 64 + d)) * N_ + j0 + j] = stg[j * 65 + d];
    }
}

// ------------------------- residual + BN + relu + output write ---------------
__global__ void k_residual(int layer, float* __restrict__ out) {
    int idx = blockIdx.x * 256 + threadIdx.x;
    int b = idx >> 19;
    int c = (idx >> 11) & (C_ - 1);
    int n = idx & (N_ - 1);
    float r = fmaxf(fmaf(g_scale[c], g_t[idx], g_shift[c]), 0.f);
    float o = g_h[idx] + r;
    g_h[idx] = o;
    out[((size_t)b * (4 * C_) + layer * C_ + c) * N_ + n] = o;
}

// ------------------------- host orchestration --------------------------------
extern "C" void kernel_launch(void* const* d_in, const int* in_sizes, int n_in,
                              void* d_out, int out_size) {
    (void)in_sizes; (void)n_in; (void)out_size;
    const float* x       = (const float*)d_in[0];
    const float* xyz     = (const float*)d_in[1];
    const float* conv1_w = (const float*)d_in[2];
    const float* pos_w   = (const float*)d_in[3];
    const float* pos_b   = (const float*)d_in[4];
    const float* bn1_g   = (const float*)d_in[5];
    const float* bn1_b   = (const float*)d_in[6];
    const float* qk_w    = (const float*)d_in[7];
    const float* v_w     = (const float*)d_in[8];
    const float* v_b     = (const float*)d_in[9];
    const float* t_w     = (const float*)d_in[10];
    const float* t_b     = (const float*)d_in[11];
    const float* bn_g    = (const float*)d_in[12];
    const float* bn_b    = (const float*)d_in[13];
    float* out = (float*)d_out;

    float *ph, *pemb, *pxr, *pt;
    cudaGetSymbolAddress((void**)&ph,   g_h);
    cudaGetSymbolAddress((void**)&pemb, g_emb);
    cudaGetSymbolAddress((void**)&pxr,  g_xr);
    cudaGetSymbolAddress((void**)&pt,   g_t);

    cudaFuncSetAttribute(k_energy_mma,     cudaFuncAttributeMaxDynamicSharedMemorySize, 49152);
    cudaFuncSetAttribute(k_attn_mma,       cudaFuncAttributeMaxDynamicSharedMemorySize, 41472);
    cudaFuncSetAttribute(k_convmma<0, 0>,  cudaFuncAttributeMaxDynamicSharedMemorySize, 36864);
    cudaFuncSetAttribute(k_convmma<1, 1>,  cudaFuncAttributeMaxDynamicSharedMemorySize, 36864);
    cudaFuncSetAttribute(k_convmma<1, 2>,  cudaFuncAttributeMaxDynamicSharedMemorySize, 36864);
    cudaFuncSetAttribute(k_convmma<2, 0>,  cudaFuncAttributeMaxDynamicSharedMemorySize, 36864);

    const int EW = (B_ * C_ * N_) / 256;
    dim3 gCv(16, 2, 4);

    k_wsplit<<<13 * 256, 256>>>(conv1_w, qk_w, v_w, t_w);
    k_posemb<<<EW, 256>>>(xyz, pos_w, pos_b);
    k_convmma<0, 0><<<gCv, 256, 36864>>>(0, x, nullptr, nullptr, pt);
    k_bnfinal<<<1, 256>>>(bn1_g, bn1_b);
    k_bnapply<<<EW, 256>>>();

    for (int i = 0; i < 4; i++) {
        const float* vb = v_b  + (size_t)i * C_;
        const float* tb = t_b  + (size_t)i * C_;
        const float* bg = bn_g + (size_t)i * C_;
        const float* bb = bn_b + (size_t)i * C_;

        k_convmma<1, 1><<<gCv, 256, 36864>>>(1 + i, ph, pemb, nullptr, nullptr);
        k_convmma<1, 2><<<gCv, 256, 36864>>>(5 + i, ph, pemb, vb, nullptr);
        k_energy_mma<<<dim3(16, 16, BH_), 256, 49152>>>();
        k_rowreduce<<<(BH_ * N_) / 8, 256>>>();
        k_attn_mma<<<dim3(16, BH_), 256, 41472>>>();
        k_convmma<2, 0><<<gCv, 256, 36864>>>(9 + i, ph, pxr, tb, pt);
        k_bnfinal<<<1, 256>>>(bg, bb);
        k_residual<<<EW, 256>>>(i, out);
    }
}

// round 10
// speedup vs baseline: 4.1494x; 1.0283x over previous
#include <cuda_runtime.h>
#include <cuda_bf16.h>
#include <cstdint>
#include <cstddef>

#define B_ 4
#define C_ 256
#define N_ 2048
#define H_ 4
#define D_ 64
#define BH_ 16

typedef unsigned long long u64;
typedef unsigned int u32;

// ------------------------- scratch (static device globals) -------------------
__device__ __nv_bfloat16 g_E[(size_t)BH_ * N_ * N_];     // 128 MiB energy bf16
__device__ float g_emb[B_ * C_ * N_];
__device__ float g_h[B_ * C_ * N_];
__device__ float g_xr[B_ * C_ * N_];
__device__ float g_t[B_ * C_ * N_];
__device__ __nv_bfloat16 g_qbhi[B_ * C_ * N_];           // q bf16, [c][n]
__device__ __nv_bfloat16 g_Vb[B_ * C_ * N_];             // v bf16
__device__ __nv_bfloat16 g_Whi[13 * C_ * C_];
__device__ __nv_bfloat16 g_Wlo[13 * C_ * C_];
__device__ float g_pm[(size_t)BH_ * N_ * 32];
__device__ float g_ps[(size_t)BH_ * N_ * 32];
__device__ float g_rm[BH_ * N_];
__device__ float g_rsinv[BH_ * N_];
__device__ float g_scale[C_];
__device__ float g_shift[C_];
__device__ float g_bns[C_];
__device__ float g_bns2[C_];

// ------------------------- helpers -------------------------------------------
__device__ __forceinline__ u32 smem_u32(const void* p) {
    u32 a;
    asm("{ .reg .u64 t; cvta.to.shared.u64 t, %1; cvt.u32.u64 %0, t; }" : "=r"(a) : "l"(p));
    return a;
}
#define SW128(o) ((o) ^ (((o) >> 3) & 0x70))
#define SW256(o) ((o) ^ (((o) >> 4) & 0x70))

__device__ __forceinline__ void ldm_x4(u32* r, u32 a) {
    asm volatile("ldmatrix.sync.aligned.m8n8.x4.shared.b16 {%0,%1,%2,%3}, [%4];"
        : "=r"(r[0]), "=r"(r[1]), "=r"(r[2]), "=r"(r[3]) : "r"(a));
}
__device__ __forceinline__ void ldm_x4t(u32* r, u32 a) {
    asm volatile("ldmatrix.sync.aligned.m8n8.x4.trans.shared.b16 {%0,%1,%2,%3}, [%4];"
        : "=r"(r[0]), "=r"(r[1]), "=r"(r[2]), "=r"(r[3]) : "r"(a));
}
__device__ __forceinline__ void mma16816(float* c, const u32* a, const u32* b) {
    asm volatile("mma.sync.aligned.m16n8k16.row.col.f32.bf16.bf16.f32 "
        "{%0,%1,%2,%3}, {%4,%5,%6,%7}, {%8,%9}, {%0,%1,%2,%3};"
        : "+f"(c[0]), "+f"(c[1]), "+f"(c[2]), "+f"(c[3])
        : "r"(a[0]), "r"(a[1]), "r"(a[2]), "r"(a[3]), "r"(b[0]), "r"(b[1]));
}
__device__ __forceinline__ u32 pkbf(float a, float b) {
    __nv_bfloat162 t = __floats2bfloat162_rn(a, b);
    return *(u32*)&t;
}
// exp for a in (0,1]: degree-5 Taylor, rel err <= 6e-4 (below bf16 storage rounding)
__device__ __forceinline__ float fexp01(float a) {
    return 1.f + a * (1.f + a * (0.5f + a * (0.16666667f + a * (0.041666668f + a * 0.0083333333f))));
}

// ------------------------- positional embedding ------------------------------
__global__ void k_posemb(const float* __restrict__ xyz, const float* __restrict__ pw,
                         const float* __restrict__ pb) {
    int idx = blockIdx.x * 256 + threadIdx.x;
    int n = idx & (N_ - 1);
    int c = (idx >> 11) & (C_ - 1);
    int b = idx >> 19;
    const float* p = xyz + ((size_t)(b * N_ + n)) * 3;
    g_emb[idx] = fmaf(pw[c * 3 + 0], p[0],
                 fmaf(pw[c * 3 + 1], p[1],
                 fmaf(pw[c * 3 + 2], p[2], pb[c])));
}

// ------------------------- weight pre-split + bn accumulator zero ------------
__global__ void k_wsplit(const float* __restrict__ conv1_w, const float* __restrict__ qk_w,
                         const float* __restrict__ v_w, const float* __restrict__ t_w) {
    int idx = blockIdx.x * 256 + threadIdx.x;     // 13*65536
    if (blockIdx.x == 0 && threadIdx.x < C_) { g_bns[threadIdx.x] = 0.f; g_bns2[threadIdx.x] = 0.f; }
    int slot = idx >> 16, i = idx & 65535;
    float w;
    if (slot == 0) w = conv1_w[i];
    else if (slot < 5) w = qk_w[(slot - 1) * 65536 + i];
    else if (slot < 9) w = v_w[(slot - 5) * 65536 + i];
    else w = t_w[(slot - 9) * 65536 + i];
    __nv_bfloat16 hi = __float2bfloat16(w);
    g_Whi[idx] = hi;
    g_Wlo[idx] = __float2bfloat16(w - __bfloat162float(hi));
}

// ------------------------- conv via split-bf16 MMA ---------------------------
// MODE 0: X=X1, 1: X1+X2, 2: X1-X2
// OUT 0: fp32 Y + BN partial sums; OUT 1: bf16 -> g_qbhi; OUT 2: bf16 -> g_Vb
template <int MODE, int OUT>
__global__ __launch_bounds__(256) void k_convmma(int wslot,
                                                 const float* __restrict__ X1,
                                                 const float* __restrict__ X2,
                                                 const float* __restrict__ bias,
                                                 float* __restrict__ Y) {
    extern __shared__ char smem[];
    const int WHI = 0, WLO = 10240, XHI = 20480, XLO = 28672;
    const u32 sbase = smem_u32(smem);
    int tid = threadIdx.x, wid = tid >> 5, lane = tid & 31;
    int n0 = blockIdx.x * 128, o0 = blockIdx.y * 128, b = blockIdx.z;
    int wy = wid >> 1, wx = wid & 1;   // warp: 32 o x 64 n
    const uint4* WhiG = (const uint4*)(g_Whi + (size_t)wslot * 65536);
    const uint4* WloG = (const uint4*)(g_Wlo + (size_t)wslot * 65536);
    const float* X1b = X1 + (size_t)b * C_ * N_;
    const float* X2b = (MODE != 0) ? (X2 + (size_t)b * C_ * N_) : nullptr;

    float acc[2][8][4] = {};
    for (int k0 = 0; k0 < C_; k0 += 32) {
        #pragma unroll
        for (int i = 0; i < 2; i++) {
            int u = i * 256 + tid;
            int r = u >> 2, q = u & 3;
            int gi = ((o0 + r) << 5) + (k0 >> 3) + q;
            int so = r * 80 + q * 16;
            *(uint4*)(smem + WHI + so) = WhiG[gi];
            *(uint4*)(smem + WLO + so) = WloG[gi];
        }
        #pragma unroll
        for (int i = 0; i < 4; i++) {
            int u = i * 256 + tid;
            int r = u >> 5, s = u & 31;
            size_t off = (size_t)(k0 + r) * N_ + n0 + s * 4;
            float4 xv = *(const float4*)&X1b[off];
            if (MODE != 0) {
                float4 x2 = *(const float4*)&X2b[off];
                if (MODE == 1) { xv.x += x2.x; xv.y += x2.y; xv.z += x2.z; xv.w += x2.w; }
                else           { xv.x -= x2.x; xv.y -= x2.y; xv.z -= x2.z; xv.w -= x2.w; }
            }
            __nv_bfloat16 h0 = __float2bfloat16(xv.x), h1 = __float2bfloat16(xv.y);
            __nv_bfloat16 h2 = __float2bfloat16(xv.z), h3 = __float2bfloat16(xv.w);
            int so = SW256(r * 256 + s * 8);
            ((u32*)(smem + XHI + so))[0] = pkbf(__bfloat162float(h0), __bfloat162float(h1));
            ((u32*)(smem + XHI + so))[1] = pkbf(__bfloat162float(h2), __bfloat162float(h3));
            ((u32*)(smem + XLO + so))[0] = pkbf(xv.x - __bfloat162float(h0), xv.y - __bfloat162float(h1));
            ((u32*)(smem + XLO + so))[1] = pkbf(xv.z - __bfloat162float(h2), xv.w - __bfloat162float(h3));
        }
        __syncthreads();
        #pragma unroll
        for (int kk = 0; kk < 2; kk++) {
            int rsub = ((lane >> 3) & 1) * 8 + (lane & 7);
            u32 ah[2][4], al[2][4], bhf[8][2], blf[8][2];
            #pragma unroll
            for (int ma = 0; ma < 2; ma++) {
                u32 ad = sbase + (wy * 32 + ma * 16 + rsub) * 80 + (kk * 2 + (lane >> 4)) * 16;
                ldm_x4(ah[ma], ad + WHI);
                ldm_x4(al[ma], ad + WLO);
            }
            #pragma unroll
            for (int ng = 0; ng < 4; ng++) {
                int krow = kk * 16 + ((lane >> 4) & 1) * 8 + (lane & 7);
                int ncol = wx * 64 + ng * 16 + ((lane >> 3) & 1) * 8;
                u32 ad = sbase + SW256(krow * 256 + ncol * 2);
                u32 t4[4];
                ldm_x4t(t4, ad + XHI);
                bhf[ng * 2][0] = t4[0]; bhf[ng * 2][1] = t4[2];
                bhf[ng * 2 + 1][0] = t4[1]; bhf[ng * 2 + 1][1] = t4[3];
                ldm_x4t(t4, ad + XLO);
                blf[ng * 2][0] = t4[0]; blf[ng * 2][1] = t4[2];
                blf[ng * 2 + 1][0] = t4[1]; blf[ng * 2 + 1][1] = t4[3];
            }
            #pragma unroll
            for (int ma = 0; ma < 2; ma++)
                #pragma unroll
                for (int nb = 0; nb < 8; nb++) {
                    mma16816(acc[ma][nb], ah[ma], bhf[nb]);
                    mma16816(acc[ma][nb], ah[ma], blf[nb]);
                    mma16816(acc[ma][nb], al[ma], bhf[nb]);
                }
        }
        __syncthreads();
    }
    #pragma unroll
    for (int ma = 0; ma < 2; ma++)
        #pragma unroll
        for (int half = 0; half < 2; half++) {
            int o = o0 + wy * 32 + ma * 16 + half * 8 + (lane >> 2);
            float bv = bias ? bias[o] : 0.f;
            size_t row = (size_t)(b * C_ + o);
            if (OUT == 0) {
                float s = 0.f, s2 = 0.f;
                #pragma unroll
                for (int nb = 0; nb < 8; nb++) {
                    int n = n0 + wx * 64 + nb * 8 + (lane & 3) * 2;
                    float rx = acc[ma][nb][half * 2] + bv;
                    float ry = acc[ma][nb][half * 2 + 1] + bv;
                    float2 r; r.x = rx; r.y = ry;
                    *(float2*)&Y[row * N_ + n] = r;
                    s += rx + ry;
                    s2 = fmaf(rx, rx, fmaf(ry, ry, s2));
                }
                s += __shfl_xor_sync(0xffffffffu, s, 1);
                s += __shfl_xor_sync(0xffffffffu, s, 2);
                s2 += __shfl_xor_sync(0xffffffffu, s2, 1);
                s2 += __shfl_xor_sync(0xffffffffu, s2, 2);
                if ((lane & 3) == 0) { atomicAdd(&g_bns[o], s); atomicAdd(&g_bns2[o], s2); }
            } else {
                #pragma unroll
                for (int nb = 0; nb < 8; nb++) {
                    int nc = (n0 >> 1) + wx * 32 + nb * 4 + (lane & 3);
                    float rx = acc[ma][nb][half * 2] + bv;
                    float ry = acc[ma][nb][half * 2 + 1] + bv;
                    if (OUT == 1) ((u32*)g_qbhi)[row * 1024 + nc] = pkbf(rx, ry);
                    else          ((u32*)g_Vb)[row * 1024 + nc]   = pkbf(rx, ry);
                }
            }
        }
}

// ------------------------- BN finalize (scale/shift + re-zero accum) ---------
__global__ void k_bnfinal(const float* __restrict__ gamma, const float* __restrict__ beta) {
    int c = threadIdx.x;
    float s = g_bns[c], s2 = g_bns2[c];
    float mean = s * (1.f / (B_ * N_));
    float var = s2 * (1.f / (B_ * N_)) - mean * mean;
    float inv = rsqrtf(var + 1e-5f);
    g_scale[c] = gamma[c] * inv;
    g_shift[c] = beta[c] - mean * inv * gamma[c];
    g_bns[c] = 0.f; g_bns2[c] = 0.f;
}

__global__ void k_bnapply() {
    int idx = blockIdx.x * 256 + threadIdx.x;
    int c = (idx >> 11) & (C_ - 1);
    g_h[idx] = fmaxf(fmaf(g_scale[c], g_t[idx], g_shift[c]), 0.f);
}

// ------------------------- energy MMA (1-pass bf16, fused perm/transpose) ----
// E[nn][m] = Qhi[nn][d] . Khi[d][m]; logit noise ~ bf16-E-rounding scale.
// A smem rows relabeled nn' = quad*32 + nloc; epilogue maps back.
__global__ __launch_bounds__(256) void k_energy_mma() {
    extern __shared__ char smem[];
    const int AHI = 0, BHI = 16384;
    const u32 sbase = smem_u32(smem);
    int tid = threadIdx.x, wid = tid >> 5, lane = tid & 31;
    int mt = blockIdx.x, nt = blockIdx.y, bh = blockIdx.z;
    int m0 = mt * 128;
    int b = bh >> 2, hh = bh & 3;
    int wy = wid >> 1, wx = wid & 1;   // warp: 32 nn' x 64 m

    // A: perm tile [64 d][128 nn']
    const uint4* Qg = (const uint4*)g_qbhi;
    #pragma unroll
    for (int i = 0; i < 4; i++) {
        int u = i * 256 + tid;
        int c = u >> 2, q = u & 3;
        int d = c & 63, quad = c >> 6;
        uint4 v = Qg[((size_t)(b * C_ + c)) * 256 + hh * 64 + nt * 4 + q];
        *(uint4*)(smem + AHI + SW256(d * 256 + quad * 64 + q * 16)) = v;
    }
    // B: native [64 d][128 m]
    #pragma unroll
    for (int i = 0; i < 4; i++) {
        int u = i * 256 + tid;
        int r = u >> 4, q = u & 15;
        size_t gi = ((size_t)(b * C_ + hh * 64 + r)) * 256 + (m0 >> 3) + q;
        *(uint4*)(smem + BHI + SW256(r * 256 + q * 16)) = Qg[gi];
    }
    __syncthreads();

    float acc[2][8][4] = {};
    #pragma unroll
    for (int ks = 0; ks < 4; ks++) {
        u32 af[2][4], bhf[8][2];
        int drow = ks * 16 + ((lane >> 4) & 1) * 8 + (lane & 7);
        #pragma unroll
        for (int ma = 0; ma < 2; ma++) {
            int nncol = wy * 32 + ma * 16 + ((lane >> 3) & 1) * 8;
            ldm_x4t(af[ma], sbase + AHI + SW256(drow * 256 + nncol * 2));
        }
        #pragma unroll
        for (int ng = 0; ng < 4; ng++) {
            int mcol = wx * 64 + ng * 16 + ((lane >> 3) & 1) * 8;
            u32 t4[4];
            ldm_x4t(t4, sbase + BHI + SW256(drow * 256 + mcol * 2));
            bhf[ng * 2][0] = t4[0]; bhf[ng * 2][1] = t4[2];
            bhf[ng * 2 + 1][0] = t4[1]; bhf[ng * 2 + 1][1] = t4[3];
        }
        #pragma unroll
        for (int ma = 0; ma < 2; ma++)
            #pragma unroll
            for (int na = 0; na < 8; na++)
                mma16816(acc[ma][na], af[ma], bhf[na]);
    }

    // epilogue: round to bf16, store (perm-mapped rows), stats on rounded values
    #pragma unroll
    for (int ma = 0; ma < 2; ma++) {
        #pragma unroll
        for (int half = 0; half < 2; half++) {
            int rp = wy * 32 + ma * 16 + half * 8 + (lane >> 2);    // nn'
            int nn = nt * 128 + ((rp & 31) << 2) + (rp >> 5);        // actual nn
            int rowg = bh * 2048 + nn;
            u32 pk[8];
            float fr[16];
            #pragma unroll
            for (int na = 0; na < 8; na++) {
                __nv_bfloat162 h2 = __floats2bfloat162_rn(acc[ma][na][half * 2],
                                                          acc[ma][na][half * 2 + 1]);
                pk[na] = *(u32*)&h2;
                float2 f2 = __bfloat1622float2(h2);
                fr[na * 2] = f2.x; fr[na * 2 + 1] = f2.y;
            }
            float mx = -3.4e38f;
            #pragma unroll
            for (int i = 0; i < 16; i++) mx = fmaxf(mx, fr[i]);
            mx = fmaxf(mx, __shfl_xor_sync(0xffffffffu, mx, 1));
            mx = fmaxf(mx, __shfl_xor_sync(0xffffffffu, mx, 2));
            float s = 0.f;
            #pragma unroll
            for (int i = 0; i < 16; i++) s += __expf(fr[i] - mx);
            s += __shfl_xor_sync(0xffffffffu, s, 1);
            s += __shfl_xor_sync(0xffffffffu, s, 2);
            u32* Eo = (u32*)g_E + ((((size_t)bh << 22) + (size_t)nn * 2048
                      + m0 + wx * 64) >> 1) + (lane & 3);
            #pragma unroll
            for (int na = 0; na < 8; na++) Eo[na * 4] = pk[na];
            if ((lane & 3) == 0) {
                g_pm[(size_t)rowg * 32 + mt * 2 + wx] = mx;
                g_ps[(size_t)rowg * 32 + mt * 2 + wx] = s;
            }
        }
    }
}

// combine 32 row partials -> rm, rsinv
__global__ void k_rowreduce() {
    int row = blockIdx.x * 8 + (threadIdx.x >> 5);
    int lane = threadIdx.x & 31;
    float pm = g_pm[((size_t)row << 5) | lane];
    float ps = g_ps[((size_t)row << 5) | lane];
    float m = pm;
    #pragma unroll
    for (int o = 16; o > 0; o >>= 1) m = fmaxf(m, __shfl_xor_sync(0xffffffffu, m, o));
    float s = ps * __expf(pm - m);
    #pragma unroll
    for (int o = 16; o > 0; o >>= 1) s += __shfl_xor_sync(0xffffffffu, s, o);
    if (lane == 0) { g_rm[row] = m; g_rsinv[row] = 1.f / s; }
}

// ------------------------- fused attn: ea on-the-fly + local colsum + MMA ----
__global__ __launch_bounds__(256) void k_attn_mma() {
    extern __shared__ char smem[];
    const int EA = 0, VOF = 16384, SCOL = 24576, RMRS = 25088;
    const u32 sbase = smem_u32(smem);
    int tid = threadIdx.x, wid = tid >> 5, lane = tid & 31;
    int jt = blockIdx.x, bh = blockIdx.y;
    int b = bh >> 2, hh = bh & 3;
    int j0 = jt * 128;
    int wy = wid >> 1, wx = wid & 1;   // warp: 32 j x 32 d

    float* scol = (float*)(smem + SCOL);
    float2* rmrs = (float2*)(smem + RMRS);
    if (tid < 128) scol[tid] = 0.f;
    for (int i = tid; i < 2048; i += 256) {
        float2 rr; rr.x = g_rm[bh * 2048 + i]; rr.y = g_rsinv[bh * 2048 + i];
        rmrs[i] = rr;
    }
    __syncthreads();

    const uint4* Eg = (const uint4*)g_E;
    const uint4* Vg = (const uint4*)g_Vb;
    int jq = tid & 15, r0 = tid >> 4;
    float sums[8];
    #pragma unroll
    for (int i = 0; i < 8; i++) sums[i] = 0.f;

    float acc[2][4][4] = {};
    for (int c = 0; c < 32; c++) {
        int nn0 = c * 64;
        #pragma unroll
        for (int i = 0; i < 4; i++) {
            int nnl = i * 16 + r0;
            int nn = nn0 + nnl;
            uint4 e4 = Eg[((size_t)(bh * 2048 + nn)) * 256 + (j0 >> 3) + jq];
            float2 rr = rmrs[nn];
            u32 pk[4];
            const u32* ew = (const u32*)&e4;
            #pragma unroll
            for (int q = 0; q < 4; q++) {
                float2 f2 = __bfloat1622float2(*(const __nv_bfloat162*)&ew[q]);
                float ea0 = fexp01(__expf(f2.x - rr.x) * rr.y);
                float ea1 = fexp01(__expf(f2.y - rr.x) * rr.y);
                __nv_bfloat162 h2 = __floats2bfloat162_rn(ea0, ea1);
                pk[q] = *(u32*)&h2;
                float2 fb = __bfloat1622float2(h2);
                sums[q * 2] += fb.x; sums[q * 2 + 1] += fb.y;
            }
            *(uint4*)(smem + EA + SW256(nnl * 256 + jq * 16)) = *(uint4*)pk;
        }
        #pragma unroll
        for (int i = 0; i < 2; i++) {
            int u = i * 256 + tid;
            int r = u >> 3, q = u & 7;
            *(uint4*)(smem + VOF + SW128(r * 128 + q * 16)) =
                Vg[((size_t)(b * C_ + hh * 64 + r)) * 256 + (nn0 >> 3) + q];
        }
        __syncthreads();
        #pragma unroll
        for (int ks = 0; ks < 4; ks++) {
            u32 af[2][4], bf[4][2];
            int rsub = ((lane >> 3) & 1) * 8 + (lane & 7);
            #pragma unroll
            for (int ma = 0; ma < 2; ma++) {
                int nnrow = ks * 16 + ((lane >> 4) & 1) * 8 + (lane & 7);
                int jcol = wy * 32 + ma * 16 + ((lane >> 3) & 1) * 8;
                ldm_x4t(af[ma], sbase + EA + SW256(nnrow * 256 + jcol * 2));
            }
            #pragma unroll
            for (int p = 0; p < 2; p++) {
                int row = wx * 32 + p * 16 + rsub;
                int q = ks * 2 + (lane >> 4);
                u32 t4[4];
                ldm_x4(t4, sbase + VOF + SW128(row * 128 + q * 16));
                bf[p * 2][0] = t4[0]; bf[p * 2][1] = t4[2];
                bf[p * 2 + 1][0] = t4[1]; bf[p * 2 + 1][1] = t4[3];
            }
            #pragma unroll
            for (int ma = 0; ma < 2; ma++)
                #pragma unroll
                for (int na = 0; na < 4; na++)
                    mma16816(acc[ma][na], af[ma], bf[na]);
        }
        __syncthreads();
    }
    #pragma unroll
    for (int i = 0; i < 8; i++) atomicAdd(&scol[jq * 8 + i], sums[i]);
    __syncthreads();
    if (tid < 128) scol[tid] = 1.f / scol[tid];
    __syncthreads();
    float csv[2][2];
    #pragma unroll
    for (int ma = 0; ma < 2; ma++)
        #pragma unroll
        for (int half = 0; half < 2; half++)
            csv[ma][half] = scol[wy * 32 + ma * 16 + half * 8 + (lane >> 2)];
    __syncthreads();
    float* stg = (float*)smem;                  // [128][65]
    #pragma unroll
    for (int ma = 0; ma < 2; ma++)
        #pragma unroll
        for (int half = 0; half < 2; half++) {
            int jl = wy * 32 + ma * 16 + half * 8 + (lane >> 2);
            float cs = csv[ma][half];
            #pragma unroll
            for (int na = 0; na < 4; na++) {
                int d = wx * 32 + na * 8 + (lane & 3) * 2;
                stg[jl * 65 + d]     = acc[ma][na][half * 2] * cs;
                stg[jl * 65 + d + 1] = acc[ma][na][half * 2 + 1] * cs;
            }
        }
    __syncthreads();
    for (int it = 0; it < 32; it++) {
        int d = it * 2 + (tid >> 7);
        int j = tid & 127;
        g_xr[((size_t)(b * C_ + hh * 64 + d)) * N_ + j0 + j] = stg[j * 65 + d];
    }
}

// ------------------------- residual + BN + relu + output write ---------------
__global__ void k_residual(int layer, float* __restrict__ out) {
    int idx = blockIdx.x * 256 + threadIdx.x;
    int b = idx >> 19;
    int c = (idx >> 11) & (C_ - 1);
    int n = idx & (N_ - 1);
    float r = fmaxf(fmaf(g_scale[c], g_t[idx], g_shift[c]), 0.f);
    float o = g_h[idx] + r;
    g_h[idx] = o;
    out[((size_t)b * (4 * C_) + layer * C_ + c) * N_ + n] = o;
}

// ------------------------- host orchestration --------------------------------
extern "C" void kernel_launch(void* const* d_in, const int* in_sizes, int n_in,
                              void* d_out, int out_size) {
    (void)in_sizes; (void)n_in; (void)out_size;
    const float* x       = (const float*)d_in[0];
    const float* xyz     = (const float*)d_in[1];
    const float* conv1_w = (const float*)d_in[2];
    const float* pos_w   = (const float*)d_in[3];
    const float* pos_b   = (const float*)d_in[4];
    const float* bn1_g   = (const float*)d_in[5];
    const float* bn1_b   = (const float*)d_in[6];
    const float* qk_w    = (const float*)d_in[7];
    const float* v_w     = (const float*)d_in[8];
    const float* v_b     = (const float*)d_in[9];
    const float* t_w     = (const float*)d_in[10];
    const float* t_b     = (const float*)d_in[11];
    const float* bn_g    = (const float*)d_in[12];
    const float* bn_b    = (const float*)d_in[13];
    float* out = (float*)d_out;

    float *ph, *pemb, *pxr, *pt;
    cudaGetSymbolAddress((void**)&ph,   g_h);
    cudaGetSymbolAddress((void**)&pemb, g_emb);
    cudaGetSymbolAddress((void**)&pxr,  g_xr);
    cudaGetSymbolAddress((void**)&pt,   g_t);

    cudaFuncSetAttribute(k_energy_mma,     cudaFuncAttributeMaxDynamicSharedMemorySize, 32768);
    cudaFuncSetAttribute(k_attn_mma,       cudaFuncAttributeMaxDynamicSharedMemorySize, 41472);
    cudaFuncSetAttribute(k_convmma<0, 0>,  cudaFuncAttributeMaxDynamicSharedMemorySize, 36864);
    cudaFuncSetAttribute(k_convmma<1, 1>,  cudaFuncAttributeMaxDynamicSharedMemorySize, 36864);
    cudaFuncSetAttribute(k_convmma<1, 2>,  cudaFuncAttributeMaxDynamicSharedMemorySize, 36864);
    cudaFuncSetAttribute(k_convmma<2, 0>,  cudaFuncAttributeMaxDynamicSharedMemorySize, 36864);

    const int EW = (B_ * C_ * N_) / 256;
    dim3 gCv(16, 2, 4);

    k_wsplit<<<13 * 256, 256>>>(conv1_w, qk_w, v_w, t_w);
    k_posemb<<<EW, 256>>>(xyz, pos_w, pos_b);
    k_convmma<0, 0><<<gCv, 256, 36864>>>(0, x, nullptr, nullptr, pt);
    k_bnfinal<<<1, 256>>>(bn1_g, bn1_b);
    k_bnapply<<<EW, 256>>>();

    for (int i = 0; i < 4; i++) {
        const float* vb = v_b  + (size_t)i * C_;
        const float* tb = t_b  + (size_t)i * C_;
        const float* bg = bn_g + (size_t)i * C_;
        const float* bb = bn_b + (size_t)i * C_;

        k_convmma<1, 1><<<gCv, 256, 36864>>>(1 + i, ph, pemb, nullptr, nullptr);
        k_convmma<1, 2><<<gCv, 256, 36864>>>(5 + i, ph, pemb, vb, nullptr);
        k_energy_mma<<<dim3(16, 16, BH_), 256, 32768>>>();
        k_rowreduce<<<(BH_ * N_) / 8, 256>>>();
        k_attn_mma<<<dim3(16, BH_), 256, 41472>>>();
        k_convmma<2, 0><<<gCv, 256, 36864>>>(9 + i, ph, pxr, tb, pt);
        k_bnfinal<<<1, 256>>>(bg, bb);
        k_residual<<<EW, 256>>>(i, out);
    }
}

// round 11
// speedup vs baseline: 4.5387x; 1.0938x over previous
#include <cuda_runtime.h>
#include <cuda_bf16.h>
#include <cstdint>
#include <cstddef>

#define B_ 4
#define C_ 256
#define N_ 2048
#define H_ 4
#define D_ 64
#define BH_ 16

typedef unsigned long long u64;
typedef unsigned int u32;

// ------------------------- scratch (static device globals) -------------------
__device__ __nv_bfloat16 g_E[(size_t)BH_ * N_ * N_];     // 128 MiB energy bf16
__device__ float g_emb[B_ * C_ * N_];
__device__ float g_h[B_ * C_ * N_];
__device__ float g_xr[B_ * C_ * N_];
__device__ float g_t[B_ * C_ * N_];
__device__ __nv_bfloat16 g_qbhi[B_ * C_ * N_];           // q bf16, [c][n]
__device__ __nv_bfloat16 g_Vb[B_ * C_ * N_];             // v bf16
__device__ __nv_bfloat16 g_Whi[13 * C_ * C_];
__device__ __nv_bfloat16 g_Wlo[13 * C_ * C_];
__device__ float g_pm[(size_t)BH_ * N_ * 32];
__device__ float g_ps[(size_t)BH_ * N_ * 32];
__device__ float g_rm[BH_ * N_];
__device__ float g_rsinv[BH_ * N_];
__device__ float g_bnsS[5 * C_];                         // BN sum accum, slot 0=conv1, 1+i=t-conv
__device__ float g_bns2S[5 * C_];                        // BN sumsq accum

// ------------------------- helpers -------------------------------------------
__device__ __forceinline__ u32 smem_u32(const void* p) {
    u32 a;
    asm("{ .reg .u64 t; cvta.to.shared.u64 t, %1; cvt.u32.u64 %0, t; }" : "=r"(a) : "l"(p));
    return a;
}
#define SW128(o) ((o) ^ (((o) >> 3) & 0x70))
#define SW256(o) ((o) ^ (((o) >> 4) & 0x70))

__device__ __forceinline__ void ldm_x4(u32* r, u32 a) {
    asm volatile("ldmatrix.sync.aligned.m8n8.x4.shared.b16 {%0,%1,%2,%3}, [%4];"
        : "=r"(r[0]), "=r"(r[1]), "=r"(r[2]), "=r"(r[3]) : "r"(a));
}
__device__ __forceinline__ void ldm_x4t(u32* r, u32 a) {
    asm volatile("ldmatrix.sync.aligned.m8n8.x4.trans.shared.b16 {%0,%1,%2,%3}, [%4];"
        : "=r"(r[0]), "=r"(r[1]), "=r"(r[2]), "=r"(r[3]) : "r"(a));
}
__device__ __forceinline__ void mma16816(float* c, const u32* a, const u32* b) {
    asm volatile("mma.sync.aligned.m16n8k16.row.col.f32.bf16.bf16.f32 "
        "{%0,%1,%2,%3}, {%4,%5,%6,%7}, {%8,%9}, {%0,%1,%2,%3};"
        : "+f"(c[0]), "+f"(c[1]), "+f"(c[2]), "+f"(c[3])
        : "r"(a[0]), "r"(a[1]), "r"(a[2]), "r"(a[3]), "r"(b[0]), "r"(b[1]));
}
__device__ __forceinline__ u32 pkbf(float a, float b) {
    __nv_bfloat162 t = __floats2bfloat162_rn(a, b);
    return *(u32*)&t;
}
// exp for a in (0,1]: degree-5 Taylor, rel err <= 6e-4 (below bf16 storage rounding)
__device__ __forceinline__ float fexp01(float a) {
    return 1.f + a * (1.f + a * (0.5f + a * (0.16666667f + a * (0.041666668f + a * 0.0083333333f))));
}

// ------------------------- positional embedding ------------------------------
__global__ void k_posemb(const float* __restrict__ xyz, const float* __restrict__ pw,
                         const float* __restrict__ pb) {
    int idx = blockIdx.x * 256 + threadIdx.x;
    int n = idx & (N_ - 1);
    int c = (idx >> 11) & (C_ - 1);
    int b = idx >> 19;
    const float* p = xyz + ((size_t)(b * N_ + n)) * 3;
    g_emb[idx] = fmaf(pw[c * 3 + 0], p[0],
                 fmaf(pw[c * 3 + 1], p[1],
                 fmaf(pw[c * 3 + 2], p[2], pb[c])));
}

// ------------------------- weight pre-split + bn accumulator zero ------------
__global__ void k_wsplit(const float* __restrict__ conv1_w, const float* __restrict__ qk_w,
                         const float* __restrict__ v_w, const float* __restrict__ t_w) {
    int idx = blockIdx.x * 256 + threadIdx.x;     // 13*65536
    if (idx < 5 * C_) { g_bnsS[idx] = 0.f; g_bns2S[idx] = 0.f; }
    int slot = idx >> 16, i = idx & 65535;
    float w;
    if (slot == 0) w = conv1_w[i];
    else if (slot < 5) w = qk_w[(slot - 1) * 65536 + i];
    else if (slot < 9) w = v_w[(slot - 5) * 65536 + i];
    else w = t_w[(slot - 9) * 65536 + i];
    __nv_bfloat16 hi = __float2bfloat16(w);
    g_Whi[idx] = hi;
    g_Wlo[idx] = __float2bfloat16(w - __bfloat162float(hi));
}

// ------------------------- conv (3-pass split-bf16, fp32 out + BN stats) -----
// MODE 0: X=X1, 2: X1-X2
template <int MODE>
__global__ __launch_bounds__(256) void k_convmma(int wslot, int bnslot,
                                                 const float* __restrict__ X1,
                                                 const float* __restrict__ X2,
                                                 const float* __restrict__ bias,
                                                 float* __restrict__ Y) {
    extern __shared__ char smem[];
    const int WHI = 0, WLO = 10240, XHI = 20480, XLO = 28672;
    const u32 sbase = smem_u32(smem);
    int tid = threadIdx.x, wid = tid >> 5, lane = tid & 31;
    int n0 = blockIdx.x * 128, o0 = blockIdx.y * 128, b = blockIdx.z;
    int wy = wid >> 1, wx = wid & 1;   // warp: 32 o x 64 n
    const uint4* WhiG = (const uint4*)(g_Whi + (size_t)wslot * 65536);
    const uint4* WloG = (const uint4*)(g_Wlo + (size_t)wslot * 65536);
    const float* X1b = X1 + (size_t)b * C_ * N_;
    const float* X2b = (MODE != 0) ? (X2 + (size_t)b * C_ * N_) : nullptr;

    float acc[2][8][4] = {};
    for (int k0 = 0; k0 < C_; k0 += 32) {
        #pragma unroll
        for (int i = 0; i < 2; i++) {
            int u = i * 256 + tid;
            int r = u >> 2, q = u & 3;
            int gi = ((o0 + r) << 5) + (k0 >> 3) + q;
            int so = r * 80 + q * 16;
            *(uint4*)(smem + WHI + so) = WhiG[gi];
            *(uint4*)(smem + WLO + so) = WloG[gi];
        }
        #pragma unroll
        for (int i = 0; i < 4; i++) {
            int u = i * 256 + tid;
            int r = u >> 5, s = u & 31;
            size_t off = (size_t)(k0 + r) * N_ + n0 + s * 4;
            float4 xv = *(const float4*)&X1b[off];
            if (MODE == 2) {
                float4 x2 = *(const float4*)&X2b[off];
                xv.x -= x2.x; xv.y -= x2.y; xv.z -= x2.z; xv.w -= x2.w;
            }
            __nv_bfloat16 h0 = __float2bfloat16(xv.x), h1 = __float2bfloat16(xv.y);
            __nv_bfloat16 h2 = __float2bfloat16(xv.z), h3 = __float2bfloat16(xv.w);
            int so = SW256(r * 256 + s * 8);
            ((u32*)(smem + XHI + so))[0] = pkbf(__bfloat162float(h0), __bfloat162float(h1));
            ((u32*)(smem + XHI + so))[1] = pkbf(__bfloat162float(h2), __bfloat162float(h3));
            ((u32*)(smem + XLO + so))[0] = pkbf(xv.x - __bfloat162float(h0), xv.y - __bfloat162float(h1));
            ((u32*)(smem + XLO + so))[1] = pkbf(xv.z - __bfloat162float(h2), xv.w - __bfloat162float(h3));
        }
        __syncthreads();
        #pragma unroll
        for (int kk = 0; kk < 2; kk++) {
            int rsub = ((lane >> 3) & 1) * 8 + (lane & 7);
            u32 ah[2][4], al[2][4], bhf[8][2], blf[8][2];
            #pragma unroll
            for (int ma = 0; ma < 2; ma++) {
                u32 ad = sbase + (wy * 32 + ma * 16 + rsub) * 80 + (kk * 2 + (lane >> 4)) * 16;
                ldm_x4(ah[ma], ad + WHI);
                ldm_x4(al[ma], ad + WLO);
            }
            #pragma unroll
            for (int ng = 0; ng < 4; ng++) {
                int krow = kk * 16 + ((lane >> 4) & 1) * 8 + (lane & 7);
                int ncol = wx * 64 + ng * 16 + ((lane >> 3) & 1) * 8;
                u32 ad = sbase + SW256(krow * 256 + ncol * 2);
                u32 t4[4];
                ldm_x4t(t4, ad + XHI);
                bhf[ng * 2][0] = t4[0]; bhf[ng * 2][1] = t4[2];
                bhf[ng * 2 + 1][0] = t4[1]; bhf[ng * 2 + 1][1] = t4[3];
                ldm_x4t(t4, ad + XLO);
                blf[ng * 2][0] = t4[0]; blf[ng * 2][1] = t4[2];
                blf[ng * 2 + 1][0] = t4[1]; blf[ng * 2 + 1][1] = t4[3];
            }
            #pragma unroll
            for (int ma = 0; ma < 2; ma++)
                #pragma unroll
                for (int nb = 0; nb < 8; nb++) {
                    mma16816(acc[ma][nb], ah[ma], bhf[nb]);
                    mma16816(acc[ma][nb], ah[ma], blf[nb]);
                    mma16816(acc[ma][nb], al[ma], bhf[nb]);
                }
        }
        __syncthreads();
    }
    #pragma unroll
    for (int ma = 0; ma < 2; ma++)
        #pragma unroll
        for (int half = 0; half < 2; half++) {
            int o = o0 + wy * 32 + ma * 16 + half * 8 + (lane >> 2);
            float bv = bias ? bias[o] : 0.f;
            size_t row = (size_t)(b * C_ + o);
            float s = 0.f, s2 = 0.f;
            #pragma unroll
            for (int nb = 0; nb < 8; nb++) {
                int n = n0 + wx * 64 + nb * 8 + (lane & 3) * 2;
                float rx = acc[ma][nb][half * 2] + bv;
                float ry = acc[ma][nb][half * 2 + 1] + bv;
                float2 r; r.x = rx; r.y = ry;
                *(float2*)&Y[row * N_ + n] = r;
                s += rx + ry;
                s2 = fmaf(rx, rx, fmaf(ry, ry, s2));
            }
            s += __shfl_xor_sync(0xffffffffu, s, 1);
            s += __shfl_xor_sync(0xffffffffu, s, 2);
            s2 += __shfl_xor_sync(0xffffffffu, s2, 1);
            s2 += __shfl_xor_sync(0xffffffffu, s2, 2);
            if ((lane & 3) == 0) {
                atomicAdd(&g_bnsS[bnslot * C_ + o], s);
                atomicAdd(&g_bns2S[bnslot * C_ + o], s2);
            }
        }
}

// ------------------------- merged q+v conv (1-pass bf16, bf16 out) -----------
// grid (16, 4, 4): y<2 -> q (o-tile y), y>=2 -> v (o-tile y-2, +bias)
__global__ __launch_bounds__(256) void k_qvconv(int qslot, int vslot,
                                                const float* __restrict__ X1,
                                                const float* __restrict__ X2,
                                                const float* __restrict__ vbias) {
    extern __shared__ char smem[];
    const int WHI = 0, XHI = 10240;
    const u32 sbase = smem_u32(smem);
    int tid = threadIdx.x, wid = tid >> 5, lane = tid & 31;
    int n0 = blockIdx.x * 128, b = blockIdx.z;
    int y = blockIdx.y;
    int isv = y >> 1;
    int o0 = (y & 1) * 128;
    int wslot = isv ? vslot : qslot;
    int wy = wid >> 1, wx = wid & 1;
    const uint4* WhiG = (const uint4*)(g_Whi + (size_t)wslot * 65536);
    const float* X1b = X1 + (size_t)b * C_ * N_;
    const float* X2b = X2 + (size_t)b * C_ * N_;

    float acc[2][8][4] = {};
    for (int k0 = 0; k0 < C_; k0 += 32) {
        #pragma unroll
        for (int i = 0; i < 2; i++) {
            int u = i * 256 + tid;
            int r = u >> 2, q = u & 3;
            *(uint4*)(smem + WHI + r * 80 + q * 16) = WhiG[((o0 + r) << 5) + (k0 >> 3) + q];
        }
        #pragma unroll
        for (int i = 0; i < 4; i++) {
            int u = i * 256 + tid;
            int r = u >> 5, s = u & 31;
            size_t off = (size_t)(k0 + r) * N_ + n0 + s * 4;
            float4 xv = *(const float4*)&X1b[off];
            float4 x2 = *(const float4*)&X2b[off];
            xv.x += x2.x; xv.y += x2.y; xv.z += x2.z; xv.w += x2.w;
            int so = SW256(r * 256 + s * 8);
            ((u32*)(smem + XHI + so))[0] = pkbf(xv.x, xv.y);
            ((u32*)(smem + XHI + so))[1] = pkbf(xv.z, xv.w);
        }
        __syncthreads();
        #pragma unroll
        for (int kk = 0; kk < 2; kk++) {
            int rsub = ((lane >> 3) & 1) * 8 + (lane & 7);
            u32 ah[2][4], bhf[8][2];
            #pragma unroll
            for (int ma = 0; ma < 2; ma++)
                ldm_x4(ah[ma], sbase + WHI + (wy * 32 + ma * 16 + rsub) * 80
                               + (kk * 2 + (lane >> 4)) * 16);
            #pragma unroll
            for (int ng = 0; ng < 4; ng++) {
                int krow = kk * 16 + ((lane >> 4) & 1) * 8 + (lane & 7);
                int ncol = wx * 64 + ng * 16 + ((lane >> 3) & 1) * 8;
                u32 t4[4];
                ldm_x4t(t4, sbase + XHI + SW256(krow * 256 + ncol * 2));
                bhf[ng * 2][0] = t4[0]; bhf[ng * 2][1] = t4[2];
                bhf[ng * 2 + 1][0] = t4[1]; bhf[ng * 2 + 1][1] = t4[3];
            }
            #pragma unroll
            for (int ma = 0; ma < 2; ma++)
                #pragma unroll
                for (int nb = 0; nb < 8; nb++)
                    mma16816(acc[ma][nb], ah[ma], bhf[nb]);
        }
        __syncthreads();
    }
    u32* dst = isv ? (u32*)g_Vb : (u32*)g_qbhi;
    #pragma unroll
    for (int ma = 0; ma < 2; ma++)
        #pragma unroll
        for (int half = 0; half < 2; half++) {
            int o = o0 + wy * 32 + ma * 16 + half * 8 + (lane >> 2);
            float bv = isv ? vbias[o] : 0.f;
            size_t row = (size_t)(b * C_ + o);
            #pragma unroll
            for (int nb = 0; nb < 8; nb++) {
                int nc = (n0 >> 1) + wx * 32 + nb * 4 + (lane & 3);
                float rx = acc[ma][nb][half * 2] + bv;
                float ry = acc[ma][nb][half * 2 + 1] + bv;
                dst[row * 1024 + nc] = pkbf(rx, ry);
            }
        }
}

// ------------------------- BN apply (inline stats, slot 0) -------------------
__global__ void k_bnapply(const float* __restrict__ gamma, const float* __restrict__ beta) {
    int idx = blockIdx.x * 256 + threadIdx.x;
    int c = (idx >> 11) & (C_ - 1);
    float s = g_bnsS[c], s2 = g_bns2S[c];
    float mean = s * (1.f / (B_ * N_));
    float var = s2 * (1.f / (B_ * N_)) - mean * mean;
    float inv = rsqrtf(var + 1e-5f);
    float scale = gamma[c] * inv;
    float shift = beta[c] - mean * scale;
    g_h[idx] = fmaxf(fmaf(scale, g_t[idx], shift), 0.f);
}

// ------------------------- energy MMA (1-pass bf16, fused perm/transpose) ----
__global__ __launch_bounds__(256) void k_energy_mma() {
    extern __shared__ char smem[];
    const int AHI = 0, BHI = 16384;
    const u32 sbase = smem_u32(smem);
    int tid = threadIdx.x, wid = tid >> 5, lane = tid & 31;
    int mt = blockIdx.x, nt = blockIdx.y, bh = blockIdx.z;
    int m0 = mt * 128;
    int b = bh >> 2, hh = bh & 3;
    int wy = wid >> 1, wx = wid & 1;   // warp: 32 nn' x 64 m

    const uint4* Qg = (const uint4*)g_qbhi;
    #pragma unroll
    for (int i = 0; i < 4; i++) {
        int u = i * 256 + tid;
        int c = u >> 2, q = u & 3;
        int d = c & 63, quad = c >> 6;
        uint4 v = Qg[((size_t)(b * C_ + c)) * 256 + hh * 64 + nt * 4 + q];
        *(uint4*)(smem + AHI + SW256(d * 256 + quad * 64 + q * 16)) = v;
    }
    #pragma unroll
    for (int i = 0; i < 4; i++) {
        int u = i * 256 + tid;
        int r = u >> 4, q = u & 15;
        size_t gi = ((size_t)(b * C_ + hh * 64 + r)) * 256 + (m0 >> 3) + q;
        *(uint4*)(smem + BHI + SW256(r * 256 + q * 16)) = Qg[gi];
    }
    __syncthreads();

    float acc[2][8][4] = {};
    #pragma unroll
    for (int ks = 0; ks < 4; ks++) {
        u32 af[2][4], bhf[8][2];
        int drow = ks * 16 + ((lane >> 4) & 1) * 8 + (lane & 7);
        #pragma unroll
        for (int ma = 0; ma < 2; ma++) {
            int nncol = wy * 32 + ma * 16 + ((lane >> 3) & 1) * 8;
            ldm_x4t(af[ma], sbase + AHI + SW256(drow * 256 + nncol * 2));
        }
        #pragma unroll
        for (int ng = 0; ng < 4; ng++) {
            int mcol = wx * 64 + ng * 16 + ((lane >> 3) & 1) * 8;
            u32 t4[4];
            ldm_x4t(t4, sbase + BHI + SW256(drow * 256 + mcol * 2));
            bhf[ng * 2][0] = t4[0]; bhf[ng * 2][1] = t4[2];
            bhf[ng * 2 + 1][0] = t4[1]; bhf[ng * 2 + 1][1] = t4[3];
        }
        #pragma unroll
        for (int ma = 0; ma < 2; ma++)
            #pragma unroll
            for (int na = 0; na < 8; na++)
                mma16816(acc[ma][na], af[ma], bhf[na]);
    }

    #pragma unroll
    for (int ma = 0; ma < 2; ma++) {
        #pragma unroll
        for (int half = 0; half < 2; half++) {
            int rp = wy * 32 + ma * 16 + half * 8 + (lane >> 2);    // nn'
            int nn = nt * 128 + ((rp & 31) << 2) + (rp >> 5);        // actual nn
            int rowg = bh * 2048 + nn;
            u32 pk[8];
            float fr[16];
            #pragma unroll
            for (int na = 0; na < 8; na++) {
                __nv_bfloat162 h2 = __floats2bfloat162_rn(acc[ma][na][half * 2],
                                                          acc[ma][na][half * 2 + 1]);
                pk[na] = *(u32*)&h2;
                float2 f2 = __bfloat1622float2(h2);
                fr[na * 2] = f2.x; fr[na * 2 + 1] = f2.y;
            }
            float mx = -3.4e38f;
            #pragma unroll
            for (int i = 0; i < 16; i++) mx = fmaxf(mx, fr[i]);
            mx = fmaxf(mx, __shfl_xor_sync(0xffffffffu, mx, 1));
            mx = fmaxf(mx, __shfl_xor_sync(0xffffffffu, mx, 2));
            float s = 0.f;
            #pragma unroll
            for (int i = 0; i < 16; i++) s += __expf(fr[i] - mx);
            s += __shfl_xor_sync(0xffffffffu, s, 1);
            s += __shfl_xor_sync(0xffffffffu, s, 2);
            u32* Eo = (u32*)g_E + ((((size_t)bh << 22) + (size_t)nn * 2048
                      + m0 + wx * 64) >> 1) + (lane & 3);
            #pragma unroll
            for (int na = 0; na < 8; na++) Eo[na * 4] = pk[na];
            if ((lane & 3) == 0) {
                g_pm[(size_t)rowg * 32 + mt * 2 + wx] = mx;
                g_ps[(size_t)rowg * 32 + mt * 2 + wx] = s;
            }
        }
    }
}

// combine 32 row partials -> rm, rsinv
__global__ void k_rowreduce() {
    int row = blockIdx.x * 8 + (threadIdx.x >> 5);
    int lane = threadIdx.x & 31;
    float pm = g_pm[((size_t)row << 5) | lane];
    float ps = g_ps[((size_t)row << 5) | lane];
    float m = pm;
    #pragma unroll
    for (int o = 16; o > 0; o >>= 1) m = fmaxf(m, __shfl_xor_sync(0xffffffffu, m, o));
    float s = ps * __expf(pm - m);
    #pragma unroll
    for (int o = 16; o > 0; o >>= 1) s += __shfl_xor_sync(0xffffffffu, s, o);
    if (lane == 0) { g_rm[row] = m; g_rsinv[row] = 1.f / s; }
}

// ------------------------- fused attn: ea on-the-fly + local colsum + MMA ----
__global__ __launch_bounds__(256) void k_attn_mma() {
    extern __shared__ char smem[];
    const int EA = 0, VOF = 16384, SCOL = 24576, RMRS = 25088;
    const u32 sbase = smem_u32(smem);
    int tid = threadIdx.x, wid = tid >> 5, lane = tid & 31;
    int jt = blockIdx.x, bh = blockIdx.y;
    int b = bh >> 2, hh = bh & 3;
    int j0 = jt * 128;
    int wy = wid >> 1, wx = wid & 1;   // warp: 32 j x 32 d

    float* scol = (float*)(smem + SCOL);
    float2* rmrs = (float2*)(smem + RMRS);
    if (tid < 128) scol[tid] = 0.f;
    for (int i = tid; i < 2048; i += 256) {
        float2 rr; rr.x = g_rm[bh * 2048 + i]; rr.y = g_rsinv[bh * 2048 + i];
        rmrs[i] = rr;
    }
    __syncthreads();

    const uint4* Eg = (const uint4*)g_E;
    const uint4* Vg = (const uint4*)g_Vb;
    int jq = tid & 15, r0 = tid >> 4;
    float sums[8];
    #pragma unroll
    for (int i = 0; i < 8; i++) sums[i] = 0.f;

    float acc[2][4][4] = {};
    for (int c = 0; c < 32; c++) {
        int nn0 = c * 64;
        #pragma unroll
        for (int i = 0; i < 4; i++) {
            int nnl = i * 16 + r0;
            int nn = nn0 + nnl;
            uint4 e4 = Eg[((size_t)(bh * 2048 + nn)) * 256 + (j0 >> 3) + jq];
            float2 rr = rmrs[nn];
            u32 pk[4];
            const u32* ew = (const u32*)&e4;
            #pragma unroll
            for (int q = 0; q < 4; q++) {
                float2 f2 = __bfloat1622float2(*(const __nv_bfloat162*)&ew[q]);
                float ea0 = fexp01(__expf(f2.x - rr.x) * rr.y);
                float ea1 = fexp01(__expf(f2.y - rr.x) * rr.y);
                __nv_bfloat162 h2 = __floats2bfloat162_rn(ea0, ea1);
                pk[q] = *(u32*)&h2;
                float2 fb = __bfloat1622float2(h2);
                sums[q * 2] += fb.x; sums[q * 2 + 1] += fb.y;
            }
            *(uint4*)(smem + EA + SW256(nnl * 256 + jq * 16)) = *(uint4*)pk;
        }
        #pragma unroll
        for (int i = 0; i < 2; i++) {
            int u = i * 256 + tid;
            int r = u >> 3, q = u & 7;
            *(uint4*)(smem + VOF + SW128(r * 128 + q * 16)) =
                Vg[((size_t)(b * C_ + hh * 64 + r)) * 256 + (nn0 >> 3) + q];
        }
        __syncthreads();
        #pragma unroll
        for (int ks = 0; ks < 4; ks++) {
            u32 af[2][4], bf[4][2];
            int rsub = ((lane >> 3) & 1) * 8 + (lane & 7);
            #pragma unroll
            for (int ma = 0; ma < 2; ma++) {
                int nnrow = ks * 16 + ((lane >> 4) & 1) * 8 + (lane & 7);
                int jcol = wy * 32 + ma * 16 + ((lane >> 3) & 1) * 8;
                ldm_x4t(af[ma], sbase + EA + SW256(nnrow * 256 + jcol * 2));
            }
            #pragma unroll
            for (int p = 0; p < 2; p++) {
                int row = wx * 32 + p * 16 + rsub;
                int q = ks * 2 + (lane >> 4);
                u32 t4[4];
                ldm_x4(t4, sbase + VOF + SW128(row * 128 + q * 16));
                bf[p * 2][0] = t4[0]; bf[p * 2][1] = t4[2];
                bf[p * 2 + 1][0] = t4[1]; bf[p * 2 + 1][1] = t4[3];
            }
            #pragma unroll
            for (int ma = 0; ma < 2; ma++)
                #pragma unroll
                for (int na = 0; na < 4; na++)
                    mma16816(acc[ma][na], af[ma], bf[na]);
        }
        __syncthreads();
    }
    #pragma unroll
    for (int i = 0; i < 8; i++) atomicAdd(&scol[jq * 8 + i], sums[i]);
    __syncthreads();
    if (tid < 128) scol[tid] = 1.f / scol[tid];
    __syncthreads();
    float csv[2][2];
    #pragma unroll
    for (int ma = 0; ma < 2; ma++)
        #pragma unroll
        for (int half = 0; half < 2; half++)
            csv[ma][half] = scol[wy * 32 + ma * 16 + half * 8 + (lane >> 2)];
    __syncthreads();
    float* stg = (float*)smem;                  // [128][65]
    #pragma unroll
    for (int ma = 0; ma < 2; ma++)
        #pragma unroll
        for (int half = 0; half < 2; half++) {
            int jl = wy * 32 + ma * 16 + half * 8 + (lane >> 2);
            float cs = csv[ma][half];
            #pragma unroll
            for (int na = 0; na < 4; na++) {
                int d = wx * 32 + na * 8 + (lane & 3) * 2;
                stg[jl * 65 + d]     = acc[ma][na][half * 2] * cs;
                stg[jl * 65 + d + 1] = acc[ma][na][half * 2 + 1] * cs;
            }
        }
    __syncthreads();
    for (int it = 0; it < 32; it++) {
        int d = it * 2 + (tid >> 7);
        int j = tid & 127;
        g_xr[((size_t)(b * C_ + hh * 64 + d)) * N_ + j0 + j] = stg[j * 65 + d];
    }
}

// ------------------------- residual + BN(inline) + relu + output write -------
__global__ void k_residual(int slot, const float* __restrict__ gamma,
                           const float* __restrict__ beta, int layer,
                           float* __restrict__ out) {
    int idx = blockIdx.x * 256 + threadIdx.x;
    int b = idx >> 19;
    int c = (idx >> 11) & (C_ - 1);
    int n = idx & (N_ - 1);
    float s = g_bnsS[slot * C_ + c], s2 = g_bns2S[slot * C_ + c];
    float mean = s * (1.f / (B_ * N_));
    float var = s2 * (1.f / (B_ * N_)) - mean * mean;
    float inv = rsqrtf(var + 1e-5f);
    float scale = gamma[c] * inv;
    float shift = beta[c] - mean * scale;
    float r = fmaxf(fmaf(scale, g_t[idx], shift), 0.f);
    float o = g_h[idx] + r;
    g_h[idx] = o;
    out[((size_t)b * (4 * C_) + layer * C_ + c) * N_ + n] = o;
}

// ------------------------- host orchestration --------------------------------
extern "C" void kernel_launch(void* const* d_in, const int* in_sizes, int n_in,
                              void* d_out, int out_size) {
    (void)in_sizes; (void)n_in; (void)out_size;
    const float* x       = (const float*)d_in[0];
    const float* xyz     = (const float*)d_in[1];
    const float* conv1_w = (const float*)d_in[2];
    const float* pos_w   = (const float*)d_in[3];
    const float* pos_b   = (const float*)d_in[4];
    const float* bn1_g   = (const float*)d_in[5];
    const float* bn1_b   = (const float*)d_in[6];
    const float* qk_w    = (const float*)d_in[7];
    const float* v_w     = (const float*)d_in[8];
    const float* v_b     = (const float*)d_in[9];
    const float* t_w     = (const float*)d_in[10];
    const float* t_b     = (const float*)d_in[11];
    const float* bn_g    = (const float*)d_in[12];
    const float* bn_b    = (const float*)d_in[13];
    float* out = (float*)d_out;

    float *ph, *pemb, *pxr, *pt;
    cudaGetSymbolAddress((void**)&ph,   g_h);
    cudaGetSymbolAddress((void**)&pemb, g_emb);
    cudaGetSymbolAddress((void**)&pxr,  g_xr);
    cudaGetSymbolAddress((void**)&pt,   g_t);

    cudaFuncSetAttribute(k_energy_mma,  cudaFuncAttributeMaxDynamicSharedMemorySize, 32768);
    cudaFuncSetAttribute(k_attn_mma,    cudaFuncAttributeMaxDynamicSharedMemorySize, 41472);
    cudaFuncSetAttribute(k_convmma<0>,  cudaFuncAttributeMaxDynamicSharedMemorySize, 36864);
    cudaFuncSetAttribute(k_convmma<2>,  cudaFuncAttributeMaxDynamicSharedMemorySize, 36864);
    cudaFuncSetAttribute(k_qvconv,      cudaFuncAttributeMaxDynamicSharedMemorySize, 18432);

    const int EW = (B_ * C_ * N_) / 256;
    dim3 gCv(16, 2, 4);
    dim3 gQV(16, 4, 4);

    k_wsplit<<<13 * 256, 256>>>(conv1_w, qk_w, v_w, t_w);
    k_posemb<<<EW, 256>>>(xyz, pos_w, pos_b);
    k_convmma<0><<<gCv, 256, 36864>>>(0, 0, x, nullptr, nullptr, pt);
    k_bnapply<<<EW, 256>>>(bn1_g, bn1_b);

    for (int i = 0; i < 4; i++) {
        const float* vb = v_b  + (size_t)i * C_;
        const float* tb = t_b  + (size_t)i * C_;
        const float* bg = bn_g + (size_t)i * C_;
        const float* bb = bn_b + (size_t)i * C_;

        k_qvconv<<<gQV, 256, 18432>>>(1 + i, 5 + i, ph, pemb, vb);
        k_energy_mma<<<dim3(16, 16, BH_), 256, 32768>>>();
        k_rowreduce<<<(BH_ * N_) / 8, 256>>>();
        k_attn_mma<<<dim3(16, BH_), 256, 41472>>>();
        k_convmma<2><<<gCv, 256, 36864>>>(9 + i, 1 + i, ph, pxr, tb, pt);
        k_residual<<<EW, 256>>>(1 + i, bg, bb, i, out);
    }
}

// round 13
// speedup vs baseline: 4.8728x; 1.0736x over previous
#include <cuda_runtime.h>
#include <cuda_bf16.h>
#include <cstdint>
#include <cstddef>

#define B_ 4
#define C_ 256
#define N_ 2048
#define H_ 4
#define D_ 64
#define BH_ 16

typedef unsigned long long u64;
typedef unsigned int u32;

// ------------------------- scratch (static device globals) -------------------
__device__ float g_emb[B_ * C_ * N_];
__device__ float g_h[B_ * C_ * N_];
__device__ float g_xr[B_ * C_ * N_];
__device__ float g_t[B_ * C_ * N_];
__device__ __nv_bfloat16 g_qbhi[B_ * C_ * N_];           // q bf16, [c][n]
__device__ __nv_bfloat16 g_Vb[B_ * C_ * N_];             // v bf16
__device__ __nv_bfloat16 g_Whi[13 * C_ * C_];
__device__ __nv_bfloat16 g_Wlo[13 * C_ * C_];
__device__ float g_pm[(size_t)BH_ * N_ * 32];
__device__ float g_ps[(size_t)BH_ * N_ * 32];
__device__ float2 g_rmrs[BH_ * N_];
__device__ float g_bnsS[5 * C_];
__device__ float g_bns2S[5 * C_];

// ------------------------- helpers -------------------------------------------
__device__ __forceinline__ u32 smem_u32(const void* p) {
    u32 a;
    asm("{ .reg .u64 t; cvta.to.shared.u64 t, %1; cvt.u32.u64 %0, t; }" : "=r"(a) : "l"(p));
    return a;
}
#define SW128(o) ((o) ^ (((o) >> 3) & 0x70))
#define SW256(o) ((o) ^ (((o) >> 4) & 0x70))

__device__ __forceinline__ void ldm_x4(u32* r, u32 a) {
    asm volatile("ldmatrix.sync.aligned.m8n8.x4.shared.b16 {%0,%1,%2,%3}, [%4];"
        : "=r"(r[0]), "=r"(r[1]), "=r"(r[2]), "=r"(r[3]) : "r"(a));
}
__device__ __forceinline__ void ldm_x4t(u32* r, u32 a) {
    asm volatile("ldmatrix.sync.aligned.m8n8.x4.trans.shared.b16 {%0,%1,%2,%3}, [%4];"
        : "=r"(r[0]), "=r"(r[1]), "=r"(r[2]), "=r"(r[3]) : "r"(a));
}
__device__ __forceinline__ void mma16816(float* c, const u32* a, const u32* b) {
    asm volatile("mma.sync.aligned.m16n8k16.row.col.f32.bf16.bf16.f32 "
        "{%0,%1,%2,%3}, {%4,%5,%6,%7}, {%8,%9}, {%0,%1,%2,%3};"
        : "+f"(c[0]), "+f"(c[1]), "+f"(c[2]), "+f"(c[3])
        : "r"(a[0]), "r"(a[1]), "r"(a[2]), "r"(a[3]), "r"(b[0]), "r"(b[1]));
}
__device__ __forceinline__ u32 pkbf(float a, float b) {
    __nv_bfloat162 t = __floats2bfloat162_rn(a, b);
    return *(u32*)&t;
}
// exp for a in (0,1]: degree-5 Taylor, rel err <= 6e-4 (below bf16 storage rounding)
__device__ __forceinline__ float fexp01(float a) {
    return 1.f + a * (1.f + a * (0.5f + a * (0.16666667f + a * (0.041666668f + a * 0.0083333333f))));
}

// ------------------------- positional embedding ------------------------------
__global__ void k_posemb(const float* __restrict__ xyz, const float* __restrict__ pw,
                         const float* __restrict__ pb) {
    int idx = blockIdx.x * 256 + threadIdx.x;
    int n = idx & (N_ - 1);
    int c = (idx >> 11) & (C_ - 1);
    int b = idx >> 19;
    const float* p = xyz + ((size_t)(b * N_ + n)) * 3;
    g_emb[idx] = fmaf(pw[c * 3 + 0], p[0],
                 fmaf(pw[c * 3 + 1], p[1],
                 fmaf(pw[c * 3 + 2], p[2], pb[c])));
}

// ------------------------- weight pre-split + bn accumulator zero ------------
__global__ void k_wsplit(const float* __restrict__ conv1_w, const float* __restrict__ qk_w,
                         const float* __restrict__ v_w, const float* __restrict__ t_w) {
    int idx = blockIdx.x * 256 + threadIdx.x;     // 13*65536
    if (idx < 5 * C_) { g_bnsS[idx] = 0.f; g_bns2S[idx] = 0.f; }
    int slot = idx >> 16, i = idx & 65535;
    float w;
    if (slot == 0) w = conv1_w[i];
    else if (slot < 5) w = qk_w[(slot - 1) * 65536 + i];
    else if (slot < 9) w = v_w[(slot - 5) * 65536 + i];
    else w = t_w[(slot - 9) * 65536 + i];
    __nv_bfloat16 hi = __float2bfloat16(w);
    g_Whi[idx] = hi;
    g_Wlo[idx] = __float2bfloat16(w - __bfloat162float(hi));
}

// ------------------------- conv (3-pass split-bf16, fp32 out + BN stats) -----
// MODE 0: X=X1, 2: X1-X2
template <int MODE>
__global__ __launch_bounds__(256) void k_convmma(int wslot, int bnslot,
                                                 const float* __restrict__ X1,
                                                 const float* __restrict__ X2,
                                                 const float* __restrict__ bias,
                                                 float* __restrict__ Y) {
    extern __shared__ char smem[];
    const int WHI = 0, WLO = 10240, XHI = 20480, XLO = 28672;
    const u32 sbase = smem_u32(smem);
    int tid = threadIdx.x, wid = tid >> 5, lane = tid & 31;
    int n0 = blockIdx.x * 128, o0 = blockIdx.y * 128, b = blockIdx.z;
    int wy = wid >> 1, wx = wid & 1;
    const uint4* WhiG = (const uint4*)(g_Whi + (size_t)wslot * 65536);
    const uint4* WloG = (const uint4*)(g_Wlo + (size_t)wslot * 65536);
    const float* X1b = X1 + (size_t)b * C_ * N_;
    const float* X2b = (MODE != 0) ? (X2 + (size_t)b * C_ * N_) : nullptr;

    float acc[2][8][4] = {};
    for (int k0 = 0; k0 < C_; k0 += 32) {
        #pragma unroll
        for (int i = 0; i < 2; i++) {
            int u = i * 256 + tid;
            int r = u >> 2, q = u & 3;
            int gi = ((o0 + r) << 5) + (k0 >> 3) + q;
            int so = r * 80 + q * 16;
            *(uint4*)(smem + WHI + so) = WhiG[gi];
            *(uint4*)(smem + WLO + so) = WloG[gi];
        }
        #pragma unroll
        for (int i = 0; i < 4; i++) {
            int u = i * 256 + tid;
            int r = u >> 5, s = u & 31;
            size_t off = (size_t)(k0 + r) * N_ + n0 + s * 4;
            float4 xv = *(const float4*)&X1b[off];
            if (MODE == 2) {
                float4 x2 = *(const float4*)&X2b[off];
                xv.x -= x2.x; xv.y -= x2.y; xv.z -= x2.z; xv.w -= x2.w;
            }
            __nv_bfloat16 h0 = __float2bfloat16(xv.x), h1 = __float2bfloat16(xv.y);
            __nv_bfloat16 h2 = __float2bfloat16(xv.z), h3 = __float2bfloat16(xv.w);
            int so = SW256(r * 256 + s * 8);
            ((u32*)(smem + XHI + so))[0] = pkbf(__bfloat162float(h0), __bfloat162float(h1));
            ((u32*)(smem + XHI + so))[1] = pkbf(__bfloat162float(h2), __bfloat162float(h3));
            ((u32*)(smem + XLO + so))[0] = pkbf(xv.x - __bfloat162float(h0), xv.y - __bfloat162float(h1));
            ((u32*)(smem + XLO + so))[1] = pkbf(xv.z - __bfloat162float(h2), xv.w - __bfloat162float(h3));
        }
        __syncthreads();
        #pragma unroll
        for (int kk = 0; kk < 2; kk++) {
            int rsub = ((lane >> 3) & 1) * 8 + (lane & 7);
            u32 ah[2][4], al[2][4], bhf[8][2], blf[8][2];
            #pragma unroll
            for (int ma = 0; ma < 2; ma++) {
                u32 ad = sbase + (wy * 32 + ma * 16 + rsub) * 80 + (kk * 2 + (lane >> 4)) * 16;
                ldm_x4(ah[ma], ad + WHI);
                ldm_x4(al[ma], ad + WLO);
            }
            #pragma unroll
            for (int ng = 0; ng < 4; ng++) {
                int krow = kk * 16 + ((lane >> 4) & 1) * 8 + (lane & 7);
                int ncol = wx * 64 + ng * 16 + ((lane >> 3) & 1) * 8;
                u32 ad = sbase + SW256(krow * 256 + ncol * 2);
                u32 t4[4];
                ldm_x4t(t4, ad + XHI);
                bhf[ng * 2][0] = t4[0]; bhf[ng * 2][1] = t4[2];
                bhf[ng * 2 + 1][0] = t4[1]; bhf[ng * 2 + 1][1] = t4[3];
                ldm_x4t(t4, ad + XLO);
                blf[ng * 2][0] = t4[0]; blf[ng * 2][1] = t4[2];
                blf[ng * 2 + 1][0] = t4[1]; blf[ng * 2 + 1][1] = t4[3];
            }
            #pragma unroll
            for (int ma = 0; ma < 2; ma++)
                #pragma unroll
                for (int nb = 0; nb < 8; nb++) {
                    mma16816(acc[ma][nb], ah[ma], bhf[nb]);
                    mma16816(acc[ma][nb], ah[ma], blf[nb]);
                    mma16816(acc[ma][nb], al[ma], bhf[nb]);
                }
        }
        __syncthreads();
    }
    #pragma unroll
    for (int ma = 0; ma < 2; ma++)
        #pragma unroll
        for (int half = 0; half < 2; half++) {
            int o = o0 + wy * 32 + ma * 16 + half * 8 + (lane >> 2);
            float bv = bias ? bias[o] : 0.f;
            size_t row = (size_t)(b * C_ + o);
            float s = 0.f, s2 = 0.f;
            #pragma unroll
            for (int nb = 0; nb < 8; nb++) {
                int n = n0 + wx * 64 + nb * 8 + (lane & 3) * 2;
                float rx = acc[ma][nb][half * 2] + bv;
                float ry = acc[ma][nb][half * 2 + 1] + bv;
                float2 r; r.x = rx; r.y = ry;
                *(float2*)&Y[row * N_ + n] = r;
                s += rx + ry;
                s2 = fmaf(rx, rx, fmaf(ry, ry, s2));
            }
            s += __shfl_xor_sync(0xffffffffu, s, 1);
            s += __shfl_xor_sync(0xffffffffu, s, 2);
            s2 += __shfl_xor_sync(0xffffffffu, s2, 1);
            s2 += __shfl_xor_sync(0xffffffffu, s2, 2);
            if ((lane & 3) == 0) {
                atomicAdd(&g_bnsS[bnslot * C_ + o], s);
                atomicAdd(&g_bns2S[bnslot * C_ + o], s2);
            }
        }
}

// ------------------------- merged q+v conv (1-pass bf16, bf16 out) -----------
__global__ __launch_bounds__(256) void k_qvconv(int qslot, int vslot,
                                                const float* __restrict__ X1,
                                                const float* __restrict__ X2,
                                                const float* __restrict__ vbias) {
    extern __shared__ char smem[];
    const int WHI = 0, XHI = 10240;
    const u32 sbase = smem_u32(smem);
    int tid = threadIdx.x, wid = tid >> 5, lane = tid & 31;
    int n0 = blockIdx.x * 128, b = blockIdx.z;
    int y = blockIdx.y;
    int isv = y >> 1;
    int o0 = (y & 1) * 128;
    int wslot = isv ? vslot : qslot;
    int wy = wid >> 1, wx = wid & 1;
    const uint4* WhiG = (const uint4*)(g_Whi + (size_t)wslot * 65536);
    const float* X1b = X1 + (size_t)b * C_ * N_;
    const float* X2b = X2 + (size_t)b * C_ * N_;

    float acc[2][8][4] = {};
    for (int k0 = 0; k0 < C_; k0 += 32) {
        #pragma unroll
        for (int i = 0; i < 2; i++) {
            int u = i * 256 + tid;
            int r = u >> 2, q = u & 3;
            *(uint4*)(smem + WHI + r * 80 + q * 16) = WhiG[((o0 + r) << 5) + (k0 >> 3) + q];
        }
        #pragma unroll
        for (int i = 0; i < 4; i++) {
            int u = i * 256 + tid;
            int r = u >> 5, s = u & 31;
            size_t off = (size_t)(k0 + r) * N_ + n0 + s * 4;
            float4 xv = *(const float4*)&X1b[off];
            float4 x2 = *(const float4*)&X2b[off];
            xv.x += x2.x; xv.y += x2.y; xv.z += x2.z; xv.w += x2.w;
            int so = SW256(r * 256 + s * 8);
            ((u32*)(smem + XHI + so))[0] = pkbf(xv.x, xv.y);
            ((u32*)(smem + XHI + so))[1] = pkbf(xv.z, xv.w);
        }
        __syncthreads();
        #pragma unroll
        for (int kk = 0; kk < 2; kk++) {
            int rsub = ((lane >> 3) & 1) * 8 + (lane & 7);
            u32 ah[2][4], bhf[8][2];
            #pragma unroll
            for (int ma = 0; ma < 2; ma++)
                ldm_x4(ah[ma], sbase + WHI + (wy * 32 + ma * 16 + rsub) * 80
                               + (kk * 2 + (lane >> 4)) * 16);
            #pragma unroll
            for (int ng = 0; ng < 4; ng++) {
                int krow = kk * 16 + ((lane >> 4) & 1) * 8 + (lane & 7);
                int ncol = wx * 64 + ng * 16 + ((lane >> 3) & 1) * 8;
                u32 t4[4];
                ldm_x4t(t4, sbase + XHI + SW256(krow * 256 + ncol * 2));
                bhf[ng * 2][0] = t4[0]; bhf[ng * 2][1] = t4[2];
                bhf[ng * 2 + 1][0] = t4[1]; bhf[ng * 2 + 1][1] = t4[3];
            }
            #pragma unroll
            for (int ma = 0; ma < 2; ma++)
                #pragma unroll
                for (int nb = 0; nb < 8; nb++)
                    mma16816(acc[ma][nb], ah[ma], bhf[nb]);
        }
        __syncthreads();
    }
    u32* dst = isv ? (u32*)g_Vb : (u32*)g_qbhi;
    #pragma unroll
    for (int ma = 0; ma < 2; ma++)
        #pragma unroll
        for (int half = 0; half < 2; half++) {
            int o = o0 + wy * 32 + ma * 16 + half * 8 + (lane >> 2);
            float bv = isv ? vbias[o] : 0.f;
            size_t row = (size_t)(b * C_ + o);
            #pragma unroll
            for (int nb = 0; nb < 8; nb++) {
                int nc = (n0 >> 1) + wx * 32 + nb * 4 + (lane & 3);
                float rx = acc[ma][nb][half * 2] + bv;
                float ry = acc[ma][nb][half * 2 + 1] + bv;
                dst[row * 1024 + nc] = pkbf(rx, ry);
            }
        }
}

// ------------------------- BN apply (inline stats, slot 0) -------------------
__global__ void k_bnapply(const float* __restrict__ gamma, const float* __restrict__ beta) {
    int idx = blockIdx.x * 256 + threadIdx.x;
    int c = (idx >> 11) & (C_ - 1);
    float s = g_bnsS[c], s2 = g_bns2S[c];
    float mean = s * (1.f / (B_ * N_));
    float var = s2 * (1.f / (B_ * N_)) - mean * mean;
    float inv = rsqrtf(var + 1e-5f);
    float scale = gamma[c] * inv;
    float shift = beta[c] - mean * scale;
    g_h[idx] = fmaxf(fmaf(scale, g_t[idx], shift), 0.f);
}

// ------------------------- row-stats MMA (no E store) ------------------------
// E[nn][m] = Qperm . K; stats on bf16-ROUNDED E (attn recomputes identically).
__global__ __launch_bounds__(256) void k_stats_mma() {
    extern __shared__ char smem[];
    const int AHI = 0, BHI = 16384;
    const u32 sbase = smem_u32(smem);
    int tid = threadIdx.x, wid = tid >> 5, lane = tid & 31;
    int mt = blockIdx.x, nt = blockIdx.y, bh = blockIdx.z;
    int m0 = mt * 128;
    int b = bh >> 2, hh = bh & 3;
    int wy = wid >> 1, wx = wid & 1;

    const uint4* Qg = (const uint4*)g_qbhi;
    #pragma unroll
    for (int i = 0; i < 4; i++) {
        int u = i * 256 + tid;
        int c = u >> 2, q = u & 3;
        int d = c & 63, quad = c >> 6;
        uint4 v = Qg[((size_t)(b * C_ + c)) * 256 + hh * 64 + nt * 4 + q];
        *(uint4*)(smem + AHI + SW256(d * 256 + quad * 64 + q * 16)) = v;
    }
    #pragma unroll
    for (int i = 0; i < 4; i++) {
        int u = i * 256 + tid;
        int r = u >> 4, q = u & 15;
        size_t gi = ((size_t)(b * C_ + hh * 64 + r)) * 256 + (m0 >> 3) + q;
        *(uint4*)(smem + BHI + SW256(r * 256 + q * 16)) = Qg[gi];
    }
    __syncthreads();

    float acc[2][8][4] = {};
    #pragma unroll
    for (int ks = 0; ks < 4; ks++) {
        u32 af[2][4], bhf[8][2];
        int drow = ks * 16 + ((lane >> 4) & 1) * 8 + (lane & 7);
        #pragma unroll
        for (int ma = 0; ma < 2; ma++) {
            int nncol = wy * 32 + ma * 16 + ((lane >> 3) & 1) * 8;
            ldm_x4t(af[ma], sbase + AHI + SW256(drow * 256 + nncol * 2));
        }
        #pragma unroll
        for (int ng = 0; ng < 4; ng++) {
            int mcol = wx * 64 + ng * 16 + ((lane >> 3) & 1) * 8;
            u32 t4[4];
            ldm_x4t(t4, sbase + BHI + SW256(drow * 256 + mcol * 2));
            bhf[ng * 2][0] = t4[0]; bhf[ng * 2][1] = t4[2];
            bhf[ng * 2 + 1][0] = t4[1]; bhf[ng * 2 + 1][1] = t4[3];
        }
        #pragma unroll
        for (int ma = 0; ma < 2; ma++)
            #pragma unroll
            for (int na = 0; na < 8; na++)
                mma16816(acc[ma][na], af[ma], bhf[na]);
    }

    #pragma unroll
    for (int ma = 0; ma < 2; ma++) {
        #pragma unroll
        for (int half = 0; half < 2; half++) {
            int rp = wy * 32 + ma * 16 + half * 8 + (lane >> 2);
            int nn = nt * 128 + ((rp & 31) << 2) + (rp >> 5);
            int rowg = bh * 2048 + nn;
            float fr[16];
            #pragma unroll
            for (int na = 0; na < 8; na++) {
                __nv_bfloat162 h2 = __floats2bfloat162_rn(acc[ma][na][half * 2],
                                                          acc[ma][na][half * 2 + 1]);
                float2 f2 = __bfloat1622float2(h2);
                fr[na * 2] = f2.x; fr[na * 2 + 1] = f2.y;
            }
            float mx = -3.4e38f;
            #pragma unroll
            for (int i = 0; i < 16; i++) mx = fmaxf(mx, fr[i]);
            mx = fmaxf(mx, __shfl_xor_sync(0xffffffffu, mx, 1));
            mx = fmaxf(mx, __shfl_xor_sync(0xffffffffu, mx, 2));
            float s = 0.f;
            #pragma unroll
            for (int i = 0; i < 16; i++) s += __expf(fr[i] - mx);
            s += __shfl_xor_sync(0xffffffffu, s, 1);
            s += __shfl_xor_sync(0xffffffffu, s, 2);
            if ((lane & 3) == 0) {
                g_pm[(size_t)rowg * 32 + mt * 2 + wx] = mx;
                g_ps[(size_t)rowg * 32 + mt * 2 + wx] = s;
            }
        }
    }
}

// combine 32 row partials -> packed (rm, rsinv)
__global__ void k_rowreduce() {
    int row = blockIdx.x * 8 + (threadIdx.x >> 5);
    int lane = threadIdx.x & 31;
    float pm = g_pm[((size_t)row << 5) | lane];
    float ps = g_ps[((size_t)row << 5) | lane];
    float m = pm;
    #pragma unroll
    for (int o = 16; o > 0; o >>= 1) m = fmaxf(m, __shfl_xor_sync(0xffffffffu, m, o));
    float s = ps * __expf(pm - m);
    #pragma unroll
    for (int o = 16; o > 0; o >>= 1) s += __shfl_xor_sync(0xffffffffu, s, o);
    if (lane == 0) { float2 r; r.x = m; r.y = 1.f / s; g_rmrs[row] = r; }
}

// ------------------------- fused attn: E recompute + exp + colsum + V-MMA ----
__global__ __launch_bounds__(256, 2) void k_attn_mma() {
    extern __shared__ char smem[];
    const int KT = 0;            // 16 KB [64 d][128 j] SW256
    const int QP0 = 16384;       // 8 KB [64 d][64 nn''] SW128 (double buf)
    const int QP1 = 24576;
    const int EA = 32768;        // 16 KB [64 l][128 j] SW256
    const int VOF0 = 49152;      // 8 KB [64 d][64 nn] SW128 (double buf)
    const int VOF1 = 57344;
    const int SCOL = 65536;      // 512 B
    const int RMRS = 66048;      // 16 KB
    const u32 sbase = smem_u32(smem);
    int tid = threadIdx.x, wid = tid >> 5, lane = tid & 31;
    int jt = blockIdx.x, bh = blockIdx.y;
    int b = bh >> 2, hh = bh & 3;
    int j0 = jt * 128;
    int wy = wid >> 1, wx = wid & 1;   // V-MMA warp: 32 j x 32 d
    int wq = wid & 3, wj = wid >> 2;   // E-MMA warp: 16 nn'' x 64 j

    float* scol = (float*)(smem + SCOL);
    float2* rmrs = (float2*)(smem + RMRS);
    if (tid < 128) scol[tid] = 0.f;
    for (int i = tid; i < 2048; i += 256) rmrs[i] = g_rmrs[bh * 2048 + i];

    const uint4* Qg = (const uint4*)g_qbhi;
    const uint4* Vg = (const uint4*)g_Vb;
    // K-tile (B of E-MMA): [64 d][128 j], loaded once
    #pragma unroll
    for (int i = 0; i < 4; i++) {
        int u = i * 256 + tid;
        int r = u >> 4, q = u & 15;
        *(uint4*)(smem + KT + SW256(r * 256 + q * 16)) =
            Qg[((size_t)(b * C_ + hh * 64 + r)) * 256 + (j0 >> 3) + q];
    }
    // prefetch cc=0 QP (perm slice) + V
    int pc = tid >> 1, pq = tid & 1;
    int pr = tid >> 3, pv = tid & 7;
    uint4 qpr0 = Qg[((size_t)(b * C_ + pc)) * 256 + hh * 64 + pq];
    uint4 qpr1 = Qg[((size_t)(b * C_ + pc + 128)) * 256 + hh * 64 + pq];
    uint4 vr0 = Vg[((size_t)(b * C_ + hh * 64 + pr)) * 256 + pv];
    uint4 vr1 = Vg[((size_t)(b * C_ + hh * 64 + pr + 32)) * 256 + pv];

    float sums[16];
    #pragma unroll
    for (int i = 0; i < 16; i++) sums[i] = 0.f;
    float acc[2][4][4] = {};

    for (int cc = 0; cc < 32; cc++) {
        int QPp = (cc & 1) ? QP1 : QP0;
        int VOFp = (cc & 1) ? VOF1 : VOF0;
        // store prefetched tiles
        *(uint4*)(smem + QPp + SW128((pc & 63) * 128 + (pc >> 6) * 32 + pq * 16)) = qpr0;
        *(uint4*)(smem + QPp + SW128(((pc + 128) & 63) * 128 + ((pc + 128) >> 6) * 32 + pq * 16)) = qpr1;
        *(uint4*)(smem + VOFp + SW128(pr * 128 + pv * 16)) = vr0;
        *(uint4*)(smem + VOFp + SW128((pr + 32) * 128 + pv * 16)) = vr1;
        __syncthreads();
        if (cc < 31) {
            qpr0 = Qg[((size_t)(b * C_ + pc)) * 256 + hh * 64 + (cc + 1) * 2 + pq];
            qpr1 = Qg[((size_t)(b * C_ + pc + 128)) * 256 + hh * 64 + (cc + 1) * 2 + pq];
            vr0 = Vg[((size_t)(b * C_ + hh * 64 + pr)) * 256 + (cc + 1) * 8 + pv];
            vr1 = Vg[((size_t)(b * C_ + hh * 64 + pr + 32)) * 256 + (cc + 1) * 8 + pv];
        }
        // E-MMA: [64 nn''][128 j] tile, warp = 16 nn'' x 64 j
        float acce[8][4] = {};
        #pragma unroll
        for (int ks = 0; ks < 4; ks++) {
            int drow = ks * 16 + ((lane >> 4) & 1) * 8 + (lane & 7);
            u32 af[4];
            int nncol = wq * 16 + ((lane >> 3) & 1) * 8;
            ldm_x4t(af, sbase + QPp + SW128(drow * 128 + nncol * 2));
            u32 bhf[8][2];
            #pragma unroll
            for (int ng = 0; ng < 4; ng++) {
                int jcol = wj * 64 + ng * 16 + ((lane >> 3) & 1) * 8;
                u32 t4[4];
                ldm_x4t(t4, sbase + KT + SW256(drow * 256 + jcol * 2));
                bhf[ng * 2][0] = t4[0]; bhf[ng * 2][1] = t4[2];
                bhf[ng * 2 + 1][0] = t4[1]; bhf[ng * 2 + 1][1] = t4[3];
            }
            #pragma unroll
            for (int nf = 0; nf < 8; nf++) mma16816(acce[nf], af, bhf[nf]);
        }
        // exp + EA store + colsums
        int nn0 = cc * 64;
        #pragma unroll
        for (int half = 0; half < 2; half++) {
            int nnpp = wq * 16 + half * 8 + (lane >> 2);
            int l = 4 * (nnpp & 15) + (nnpp >> 4);       // local nn in V order
            float2 rr = rmrs[nn0 + l];
            #pragma unroll
            for (int nf = 0; nf < 8; nf++) {
                __nv_bfloat162 h2 = __floats2bfloat162_rn(acce[nf][half * 2],
                                                          acce[nf][half * 2 + 1]);
                float2 f2 = __bfloat1622float2(h2);
                float ea0 = fexp01(__expf(f2.x - rr.x) * rr.y);
                float ea1 = fexp01(__expf(f2.y - rr.x) * rr.y);
                __nv_bfloat162 e2 = __floats2bfloat162_rn(ea0, ea1);
                float2 fb = __bfloat1622float2(e2);
                sums[nf * 2] += fb.x; sums[nf * 2 + 1] += fb.y;
                *(u32*)(smem + EA + SW256(l * 256 + (wj * 64 + nf * 8 + (lane & 3) * 2) * 2)) = *(u32*)&e2;
            }
        }
        __syncthreads();
        // V-MMA: D[j][d] += ea^T . V^T
        #pragma unroll
        for (int ks = 0; ks < 4; ks++) {
            u32 af2[2][4], bf[4][2];
            int rsub = ((lane >> 3) & 1) * 8 + (lane & 7);
            #pragma unroll
            for (int ma = 0; ma < 2; ma++) {
                int nnrow = ks * 16 + ((lane >> 4) & 1) * 8 + (lane & 7);
                int jcol = wy * 32 + ma * 16 + ((lane >> 3) & 1) * 8;
                ldm_x4t(af2[ma], sbase + EA + SW256(nnrow * 256 + jcol * 2));
            }
            #pragma unroll
            for (int p2 = 0; p2 < 2; p2++) {
                int row = wx * 32 + p2 * 16 + rsub;
                int qq = ks * 2 + (lane >> 4);
                u32 t4[4];
                ldm_x4(t4, sbase + VOFp + SW128(row * 128 + qq * 16));
                bf[p2 * 2][0] = t4[0]; bf[p2 * 2][1] = t4[2];
                bf[p2 * 2 + 1][0] = t4[1]; bf[p2 * 2 + 1][1] = t4[3];
            }
            #pragma unroll
            for (int ma = 0; ma < 2; ma++)
                #pragma unroll
                for (int na = 0; na < 4; na++)
                    mma16816(acc[ma][na], af2[ma], bf[na]);
        }
    }
    // colsums -> csinv
    #pragma unroll
    for (int k = 0; k < 16; k++) {
        int j = wj * 64 + (k >> 1) * 8 + (lane & 3) * 2 + (k & 1);
        atomicAdd(&scol[j], sums[k]);
    }
    __syncthreads();
    if (tid < 128) scol[tid] = 1.f / scol[tid];
    __syncthreads();
    float csv[2][2];
    #pragma unroll
    for (int ma = 0; ma < 2; ma++)
        #pragma unroll
        for (int half = 0; half < 2; half++)
            csv[ma][half] = scol[wy * 32 + ma * 16 + half * 8 + (lane >> 2)];
    __syncthreads();
    float* stg = (float*)smem;                  // [128][65]
    #pragma unroll
    for (int ma = 0; ma < 2; ma++)
        #pragma unroll
        for (int half = 0; half < 2; half++) {
            int jl = wy * 32 + ma * 16 + half * 8 + (lane >> 2);
            float cs = csv[ma][half];
            #pragma unroll
            for (int na = 0; na < 4; na++) {
                int d = wx * 32 + na * 8 + (lane & 3) * 2;
                stg[jl * 65 + d]     = acc[ma][na][half * 2] * cs;
                stg[jl * 65 + d + 1] = acc[ma][na][half * 2 + 1] * cs;
            }
        }
    __syncthreads();
    for (int it = 0; it < 32; it++) {
        int d = it * 2 + (tid >> 7);
        int j = tid & 127;
        g_xr[((size_t)(b * C_ + hh * 64 + d)) * N_ + j0 + j] = stg[j * 65 + d];
    }
}

// ------------------------- residual + BN(inline) + relu + output write -------
__global__ void k_residual(int slot, const float* __restrict__ gamma,
                           const float* __restrict__ beta, int layer,
                           float* __restrict__ out) {
    int idx = blockIdx.x * 256 + threadIdx.x;
    int b = idx >> 19;
    int c = (idx >> 11) & (C_ - 1);
    int n = idx & (N_ - 1);
    float s = g_bnsS[slot * C_ + c], s2 = g_bns2S[slot * C_ + c];
    float mean = s * (1.f / (B_ * N_));
    float var = s2 * (1.f / (B_ * N_)) - mean * mean;
    float inv = rsqrtf(var + 1e-5f);
    float scale = gamma[c] * inv;
    float shift = beta[c] - mean * scale;
    float r = fmaxf(fmaf(scale, g_t[idx], shift), 0.f);
    float o = g_h[idx] + r;
    g_h[idx] = o;
    out[((size_t)b * (4 * C_) + layer * C_ + c) * N_ + n] = o;
}

// ------------------------- host orchestration --------------------------------
extern "C" void kernel_launch(void* const* d_in, const int* in_sizes, int n_in,
                              void* d_out, int out_size) {
    (void)in_sizes; (void)n_in; (void)out_size;
    const float* x       = (const float*)d_in[0];
    const float* xyz     = (const float*)d_in[1];
    const float* conv1_w = (const float*)d_in[2];
    const float* pos_w   = (const float*)d_in[3];
    const float* pos_b   = (const float*)d_in[4];
    const float* bn1_g   = (const float*)d_in[5];
    const float* bn1_b   = (const float*)d_in[6];
    const float* qk_w    = (const float*)d_in[7];
    const float* v_w     = (const float*)d_in[8];
    const float* v_b     = (const float*)d_in[9];
    const float* t_w     = (const float*)d_in[10];
    const float* t_b     = (const float*)d_in[11];
    const float* bn_g    = (const float*)d_in[12];
    const float* bn_b    = (const float*)d_in[13];
    float* out = (float*)d_out;

    float *ph, *pemb, *pxr, *pt;
    cudaGetSymbolAddress((void**)&ph,   g_h);
    cudaGetSymbolAddress((void**)&pemb, g_emb);
    cudaGetSymbolAddress((void**)&pxr,  g_xr);
    cudaGetSymbolAddress((void**)&pt,   g_t);

    cudaFuncSetAttribute(k_stats_mma,   cudaFuncAttributeMaxDynamicSharedMemorySize, 32768);
    cudaFuncSetAttribute(k_attn_mma,    cudaFuncAttributeMaxDynamicSharedMemorySize, 82432);
    cudaFuncSetAttribute(k_convmma<0>,  cudaFuncAttributeMaxDynamicSharedMemorySize, 36864);
    cudaFuncSetAttribute(k_convmma<2>,  cudaFuncAttributeMaxDynamicSharedMemorySize, 36864);
    cudaFuncSetAttribute(k_qvconv,      cudaFuncAttributeMaxDynamicSharedMemorySize, 18432);

    const int EW = (B_ * C_ * N_) / 256;
    dim3 gCv(16, 2, 4);
    dim3 gQV(16, 4, 4);

    k_wsplit<<<13 * 256, 256>>>(conv1_w, qk_w, v_w, t_w);
    k_posemb<<<EW, 256>>>(xyz, pos_w, pos_b);
    k_convmma<0><<<gCv, 256, 36864>>>(0, 0, x, nullptr, nullptr, pt);
    k_bnapply<<<EW, 256>>>(bn1_g, bn1_b);

    for (int i = 0; i < 4; i++) {
        const float* vb = v_b  + (size_t)i * C_;
        const float* tb = t_b  + (size_t)i * C_;
        const float* bg = bn_g + (size_t)i * C_;
        const float* bb = bn_b + (size_t)i * C_;

        k_qvconv<<<gQV, 256, 18432>>>(1 + i, 5 + i, ph, pemb, vb);
        k_stats_mma<<<dim3(16, 16, BH_), 256, 32768>>>();
        k_rowreduce<<<(BH_ * N_) / 8, 256>>>();
        k_attn_mma<<<dim3(16, BH_), 256, 82432>>>();
        k_convmma<2><<<gCv, 256, 36864>>>(9 + i, 1 + i, ph, pxr, tb, pt);
        k_residual<<<EW, 256>>>(1 + i, bg, bb, i, out);
    }
}

// round 16
// speedup vs baseline: 4.9458x; 1.0150x over previous
#include <cuda_runtime.h>
#include <cuda_bf16.h>
#include <cstdint>
#include <cstddef>

#define B_ 4
#define C_ 256
#define N_ 2048
#define H_ 4
#define D_ 64
#define BH_ 16

typedef unsigned long long u64;
typedef unsigned int u32;

// ------------------------- scratch (static device globals) -------------------
__device__ float g_emb[B_ * C_ * N_];
__device__ float g_h[B_ * C_ * N_];
__device__ float g_xr[B_ * C_ * N_];
__device__ float g_t[B_ * C_ * N_];
__device__ __nv_bfloat16 g_qbhi[B_ * C_ * N_];           // q bf16, [c][n]
__device__ __nv_bfloat16 g_Vb[B_ * C_ * N_];             // v bf16
__device__ __nv_bfloat16 g_Whi[13 * C_ * C_];
__device__ __nv_bfloat16 g_Wlo[13 * C_ * C_];
__device__ float g_pm[(size_t)BH_ * N_ * 32];
__device__ float g_ps[(size_t)BH_ * N_ * 32];
__device__ float2 g_rmrs[BH_ * N_];
__device__ float g_bnsS[5 * C_];
__device__ float g_bns2S[5 * C_];

// ------------------------- helpers -------------------------------------------
__device__ __forceinline__ u32 smem_u32(const void* p) {
    u32 a;
    asm("{ .reg .u64 t; cvta.to.shared.u64 t, %1; cvt.u32.u64 %0, t; }" : "=r"(a) : "l"(p));
    return a;
}
#define SW128(o) ((o) ^ (((o) >> 3) & 0x70))
#define SW256(o) ((o) ^ (((o) >> 4) & 0x70))

__device__ __forceinline__ void ldm_x4(u32* r, u32 a) {
    asm volatile("ldmatrix.sync.aligned.m8n8.x4.shared.b16 {%0,%1,%2,%3}, [%4];"
        : "=r"(r[0]), "=r"(r[1]), "=r"(r[2]), "=r"(r[3]) : "r"(a));
}
__device__ __forceinline__ void ldm_x4t(u32* r, u32 a) {
    asm volatile("ldmatrix.sync.aligned.m8n8.x4.trans.shared.b16 {%0,%1,%2,%3}, [%4];"
        : "=r"(r[0]), "=r"(r[1]), "=r"(r[2]), "=r"(r[3]) : "r"(a));
}
__device__ __forceinline__ void mma16816(float* c, const u32* a, const u32* b) {
    asm volatile("mma.sync.aligned.m16n8k16.row.col.f32.bf16.bf16.f32 "
        "{%0,%1,%2,%3}, {%4,%5,%6,%7}, {%8,%9}, {%0,%1,%2,%3};"
        : "+f"(c[0]), "+f"(c[1]), "+f"(c[2]), "+f"(c[3])
        : "r"(a[0]), "r"(a[1]), "r"(a[2]), "r"(a[3]), "r"(b[0]), "r"(b[1]));
}
__device__ __forceinline__ u32 pkbf(float a, float b) {
    __nv_bfloat162 t = __floats2bfloat162_rn(a, b);
    return *(u32*)&t;
}
// exp for a in (0,1]: degree-5 Taylor, rel err <= 6e-4 (below bf16 storage rounding)
__device__ __forceinline__ float fexp01(float a) {
    return 1.f + a * (1.f + a * (0.5f + a * (0.16666667f + a * (0.041666668f + a * 0.0083333333f))));
}

// ------------------------- positional embedding (per-point threads) ----------
__global__ void k_posemb(const float* __restrict__ xyz, const float* __restrict__ pw,
                         const float* __restrict__ pb) {
    __shared__ float spw[3 * C_];
    __shared__ float spb[C_];
    int tid = threadIdx.x;
    #pragma unroll
    for (int i = 0; i < 3; i++) spw[i * 256 + tid] = pw[i * 256 + tid];
    spb[tid] = pb[tid];
    __syncthreads();
    int t = blockIdx.x * 256 + tid;            // b*N + n
    int b = t >> 11, n = t & (N_ - 1);
    const float* p = xyz + (size_t)t * 3;
    float px = p[0], py = p[1], pz = p[2];
    float* eb = g_emb + ((size_t)b * C_ << 11) + n;
    #pragma unroll 4
    for (int c = 0; c < C_; c++) {
        eb[(size_t)c << 11] = fmaf(spw[c * 3 + 0], px,
                              fmaf(spw[c * 3 + 1], py,
                              fmaf(spw[c * 3 + 2], pz, spb[c])));
    }
}

// ------------------------- weight pre-split + bn accumulator zero ------------
__global__ void k_wsplit(const float* __restrict__ conv1_w, const float* __restrict__ qk_w,
                         const float* __restrict__ v_w, const float* __restrict__ t_w) {
    int idx = blockIdx.x * 256 + threadIdx.x;     // 13*65536
    if (idx < 5 * C_) { g_bnsS[idx] = 0.f; g_bns2S[idx] = 0.f; }
    int slot = idx >> 16, i = idx & 65535;
    float w;
    if (slot == 0) w = conv1_w[i];
    else if (slot < 5) w = qk_w[(slot - 1) * 65536 + i];
    else if (slot < 9) w = v_w[(slot - 5) * 65536 + i];
    else w = t_w[(slot - 9) * 65536 + i];
    __nv_bfloat16 hi = __float2bfloat16(w);
    g_Whi[idx] = hi;
    g_Wlo[idx] = __float2bfloat16(w - __bfloat162float(hi));
}

// ------------------------- conv (3-pass split-bf16, fp32 out + BN stats) -----
// MODE 0: X=X1, 2: X1-X2
template <int MODE>
__global__ __launch_bounds__(256) void k_convmma(int wslot, int bnslot,
                                                 const float* __restrict__ X1,
                                                 const float* __restrict__ X2,
                                                 const float* __restrict__ bias,
                                                 float* __restrict__ Y) {
    extern __shared__ char smem[];
    const int WHI = 0, WLO = 10240, XHI = 20480, XLO = 28672;
    const u32 sbase = smem_u32(smem);
    int tid = threadIdx.x, wid = tid >> 5, lane = tid & 31;
    int n0 = blockIdx.x * 128, o0 = blockIdx.y * 128, b = blockIdx.z;
    int wy = wid >> 1, wx = wid & 1;
    const uint4* WhiG = (const uint4*)(g_Whi + (size_t)wslot * 65536);
    const uint4* WloG = (const uint4*)(g_Wlo + (size_t)wslot * 65536);
    const float* X1b = X1 + (size_t)b * C_ * N_;
    const float* X2b = (MODE != 0) ? (X2 + (size_t)b * C_ * N_) : nullptr;

    float acc[2][8][4] = {};
    for (int k0 = 0; k0 < C_; k0 += 32) {
        #pragma unroll
        for (int i = 0; i < 2; i++) {
            int u = i * 256 + tid;
            int r = u >> 2, q = u & 3;
            int gi = ((o0 + r) << 5) + (k0 >> 3) + q;
            int so = r * 80 + q * 16;
            *(uint4*)(smem + WHI + so) = WhiG[gi];
            *(uint4*)(smem + WLO + so) = WloG[gi];
        }
        #pragma unroll
        for (int i = 0; i < 4; i++) {
            int u = i * 256 + tid;
            int r = u >> 5, s = u & 31;
            size_t off = (size_t)(k0 + r) * N_ + n0 + s * 4;
            float4 xv = *(const float4*)&X1b[off];
            if (MODE == 2) {
                float4 x2 = *(const float4*)&X2b[off];
                xv.x -= x2.x; xv.y -= x2.y; xv.z -= x2.z; xv.w -= x2.w;
            }
            __nv_bfloat16 h0 = __float2bfloat16(xv.x), h1 = __float2bfloat16(xv.y);
            __nv_bfloat16 h2 = __float2bfloat16(xv.z), h3 = __float2bfloat16(xv.w);
            int so = SW256(r * 256 + s * 8);
            ((u32*)(smem + XHI + so))[0] = pkbf(__bfloat162float(h0), __bfloat162float(h1));
            ((u32*)(smem + XHI + so))[1] = pkbf(__bfloat162float(h2), __bfloat162float(h3));
            ((u32*)(smem + XLO + so))[0] = pkbf(xv.x - __bfloat162float(h0), xv.y - __bfloat162float(h1));
            ((u32*)(smem + XLO + so))[1] = pkbf(xv.z - __bfloat162float(h2), xv.w - __bfloat162float(h3));
        }
        __syncthreads();
        #pragma unroll
        for (int kk = 0; kk < 2; kk++) {
            int rsub = ((lane >> 3) & 1) * 8 + (lane & 7);
            u32 ah[2][4], al[2][4], bhf[8][2], blf[8][2];
            #pragma unroll
            for (int ma = 0; ma < 2; ma++) {
                u32 ad = sbase + (wy * 32 + ma * 16 + rsub) * 80 + (kk * 2 + (lane >> 4)) * 16;
                ldm_x4(ah[ma], ad + WHI);
                ldm_x4(al[ma], ad + WLO);
            }
            #pragma unroll
            for (int ng = 0; ng < 4; ng++) {
                int krow = kk * 16 + ((lane >> 4) & 1) * 8 + (lane & 7);
                int ncol = wx * 64 + ng * 16 + ((lane >> 3) & 1) * 8;
                u32 ad = sbase + SW256(krow * 256 + ncol * 2);
                u32 t4[4];
                ldm_x4t(t4, ad + XHI);
                bhf[ng * 2][0] = t4[0]; bhf[ng * 2][1] = t4[2];
                bhf[ng * 2 + 1][0] = t4[1]; bhf[ng * 2 + 1][1] = t4[3];
                ldm_x4t(t4, ad + XLO);
                blf[ng * 2][0] = t4[0]; blf[ng * 2][1] = t4[2];
                blf[ng * 2 + 1][0] = t4[1]; blf[ng * 2 + 1][1] = t4[3];
            }
            #pragma unroll
            for (int ma = 0; ma < 2; ma++)
                #pragma unroll
                for (int nb = 0; nb < 8; nb++) {
                    mma16816(acc[ma][nb], ah[ma], bhf[nb]);
                    mma16816(acc[ma][nb], ah[ma], blf[nb]);
                    mma16816(acc[ma][nb], al[ma], bhf[nb]);
                }
        }
        __syncthreads();
    }
    #pragma unroll
    for (int ma = 0; ma < 2; ma++)
        #pragma unroll
        for (int half = 0; half < 2; half++) {
            int o = o0 + wy * 32 + ma * 16 + half * 8 + (lane >> 2);
            float bv = bias ? bias[o] : 0.f;
            size_t row = (size_t)(b * C_ + o);
            float s = 0.f, s2 = 0.f;
            #pragma unroll
            for (int nb = 0; nb < 8; nb++) {
                int n = n0 + wx * 64 + nb * 8 + (lane & 3) * 2;
                float rx = acc[ma][nb][half * 2] + bv;
                float ry = acc[ma][nb][half * 2 + 1] + bv;
                float2 r; r.x = rx; r.y = ry;
                *(float2*)&Y[row * N_ + n] = r;
                s += rx + ry;
                s2 = fmaf(rx, rx, fmaf(ry, ry, s2));
            }
            s += __shfl_xor_sync(0xffffffffu, s, 1);
            s += __shfl_xor_sync(0xffffffffu, s, 2);
            s2 += __shfl_xor_sync(0xffffffffu, s2, 1);
            s2 += __shfl_xor_sync(0xffffffffu, s2, 2);
            if ((lane & 3) == 0) {
                atomicAdd(&g_bnsS[bnslot * C_ + o], s);
                atomicAdd(&g_bns2S[bnslot * C_ + o], s2);
            }
        }
}

// ------------------------- merged q+v conv (1-pass bf16, bf16 out) -----------
__global__ __launch_bounds__(256) void k_qvconv(int qslot, int vslot,
                                                const float* __restrict__ X1,
                                                const float* __restrict__ X2,
                                                const float* __restrict__ vbias) {
    extern __shared__ char smem[];
    const int WHI = 0, XHI = 10240;
    const u32 sbase = smem_u32(smem);
    int tid = threadIdx.x, wid = tid >> 5, lane = tid & 31;
    int n0 = blockIdx.x * 128, b = blockIdx.z;
    int y = blockIdx.y;
    int isv = y >> 1;
    int o0 = (y & 1) * 128;
    int wslot = isv ? vslot : qslot;
    int wy = wid >> 1, wx = wid & 1;
    const uint4* WhiG = (const uint4*)(g_Whi + (size_t)wslot * 65536);
    const float* X1b = X1 + (size_t)b * C_ * N_;
    const float* X2b = X2 + (size_t)b * C_ * N_;

    float acc[2][8][4] = {};
    for (int k0 = 0; k0 < C_; k0 += 32) {
        #pragma unroll
        for (int i = 0; i < 2; i++) {
            int u = i * 256 + tid;
            int r = u >> 2, q = u & 3;
            *(uint4*)(smem + WHI + r * 80 + q * 16) = WhiG[((o0 + r) << 5) + (k0 >> 3) + q];
        }
        #pragma unroll
        for (int i = 0; i < 4; i++) {
            int u = i * 256 + tid;
            int r = u >> 5, s = u & 31;
            size_t off = (size_t)(k0 + r) * N_ + n0 + s * 4;
            float4 xv = *(const float4*)&X1b[off];
            float4 x2 = *(const float4*)&X2b[off];
            xv.x += x2.x; xv.y += x2.y; xv.z += x2.z; xv.w += x2.w;
            int so = SW256(r * 256 + s * 8);
            ((u32*)(smem + XHI + so))[0] = pkbf(xv.x, xv.y);
            ((u32*)(smem + XHI + so))[1] = pkbf(xv.z, xv.w);
        }
        __syncthreads();
        #pragma unroll
        for (int kk = 0; kk < 2; kk++) {
            int rsub = ((lane >> 3) & 1) * 8 + (lane & 7);
            u32 ah[2][4], bhf[8][2];
            #pragma unroll
            for (int ma = 0; ma < 2; ma++)
                ldm_x4(ah[ma], sbase + WHI + (wy * 32 + ma * 16 + rsub) * 80
                               + (kk * 2 + (lane >> 4)) * 16);
            #pragma unroll
            for (int ng = 0; ng < 4; ng++) {
                int krow = kk * 16 + ((lane >> 4) & 1) * 8 + (lane & 7);
                int ncol = wx * 64 + ng * 16 + ((lane >> 3) & 1) * 8;
                u32 t4[4];
                ldm_x4t(t4, sbase + XHI + SW256(krow * 256 + ncol * 2));
                bhf[ng * 2][0] = t4[0]; bhf[ng * 2][1] = t4[2];
                bhf[ng * 2 + 1][0] = t4[1]; bhf[ng * 2 + 1][1] = t4[3];
            }
            #pragma unroll
            for (int ma = 0; ma < 2; ma++)
                #pragma unroll
                for (int nb = 0; nb < 8; nb++)
                    mma16816(acc[ma][nb], ah[ma], bhf[nb]);
        }
        __syncthreads();
    }
    u32* dst = isv ? (u32*)g_Vb : (u32*)g_qbhi;
    #pragma unroll
    for (int ma = 0; ma < 2; ma++)
        #pragma unroll
        for (int half = 0; half < 2; half++) {
            int o = o0 + wy * 32 + ma * 16 + half * 8 + (lane >> 2);
            float bv = isv ? vbias[o] : 0.f;
            size_t row = (size_t)(b * C_ + o);
            #pragma unroll
            for (int nb = 0; nb < 8; nb++) {
                int nc = (n0 >> 1) + wx * 32 + nb * 4 + (lane & 3);
                float rx = acc[ma][nb][half * 2] + bv;
                float ry = acc[ma][nb][half * 2 + 1] + bv;
                dst[row * 1024 + nc] = pkbf(rx, ry);
            }
        }
}

// ------------------------- BN apply (inline stats, slot 0, float4) -----------
__global__ void k_bnapply(const float* __restrict__ gamma, const float* __restrict__ beta) {
    int idx = blockIdx.x * 256 + threadIdx.x;        // over BCN/4
    int base = idx << 2;
    int c = (base >> 11) & (C_ - 1);
    float s = g_bnsS[c], s2 = g_bns2S[c];
    float mean = s * (1.f / (B_ * N_));
    float var = s2 * (1.f / (B_ * N_)) - mean * mean;
    float inv = rsqrtf(var + 1e-5f);
    float scale = gamma[c] * inv;
    float shift = beta[c] - mean * scale;
    float4 t4 = *(const float4*)&g_t[base];
    float4 o;
    o.x = fmaxf(fmaf(scale, t4.x, shift), 0.f);
    o.y = fmaxf(fmaf(scale, t4.y, shift), 0.f);
    o.z = fmaxf(fmaf(scale, t4.z, shift), 0.f);
    o.w = fmaxf(fmaf(scale, t4.w, shift), 0.f);
    *(float4*)&g_h[base] = o;
}

// ------------------------- row-stats MMA (no E store) ------------------------
// E[nn][m] = Qperm . K; stats on bf16-ROUNDED E (attn recomputes identically).
__global__ __launch_bounds__(256) void k_stats_mma() {
    extern __shared__ char smem[];
    const int AHI = 0, BHI = 16384;
    const u32 sbase = smem_u32(smem);
    int tid = threadIdx.x, wid = tid >> 5, lane = tid & 31;
    int mt = blockIdx.x, nt = blockIdx.y, bh = blockIdx.z;
    int m0 = mt * 128;
    int b = bh >> 2, hh = bh & 3;
    int wy = wid >> 1, wx = wid & 1;

    const uint4* Qg = (const uint4*)g_qbhi;
    #pragma unroll
    for (int i = 0; i < 4; i++) {
        int u = i * 256 + tid;
        int c = u >> 2, q = u & 3;
        int d = c & 63, quad = c >> 6;
        uint4 v = Qg[((size_t)(b * C_ + c)) * 256 + hh * 64 + nt * 4 + q];
        *(uint4*)(smem + AHI + SW256(d * 256 + quad * 64 + q * 16)) = v;
    }
    #pragma unroll
    for (int i = 0; i < 4; i++) {
        int u = i * 256 + tid;
        int r = u >> 4, q = u & 15;
        size_t gi = ((size_t)(b * C_ + hh * 64 + r)) * 256 + (m0 >> 3) + q;
        *(uint4*)(smem + BHI + SW256(r * 256 + q * 16)) = Qg[gi];
    }
    __syncthreads();

    float acc[2][8][4] = {};
    #pragma unroll
    for (int ks = 0; ks < 4; ks++) {
        u32 af[2][4], bhf[8][2];
        int drow = ks * 16 + ((lane >> 4) & 1) * 8 + (lane & 7);
        #pragma unroll
        for (int ma = 0; ma < 2; ma++) {
            int nncol = wy * 32 + ma * 16 + ((lane >> 3) & 1) * 8;
            ldm_x4t(af[ma], sbase + AHI + SW256(drow * 256 + nncol * 2));
        }
        #pragma unroll
        for (int ng = 0; ng < 4; ng++) {
            int mcol = wx * 64 + ng * 16 + ((lane >> 3) & 1) * 8;
            u32 t4[4];
            ldm_x4t(t4, sbase + BHI + SW256(drow * 256 + mcol * 2));
            bhf[ng * 2][0] = t4[0]; bhf[ng * 2][1] = t4[2];
            bhf[ng * 2 + 1][0] = t4[1]; bhf[ng * 2 + 1][1] = t4[3];
        }
        #pragma unroll
        for (int ma = 0; ma < 2; ma++)
            #pragma unroll
            for (int na = 0; na < 8; na++)
                mma16816(acc[ma][na], af[ma], bhf[na]);
    }

    #pragma unroll
    for (int ma = 0; ma < 2; ma++) {
        #pragma unroll
        for (int half = 0; half < 2; half++) {
            int rp = wy * 32 + ma * 16 + half * 8 + (lane >> 2);
            int nn = nt * 128 + ((rp & 31) << 2) + (rp >> 5);
            int rowg = bh * 2048 + nn;
            float fr[16];
            #pragma unroll
            for (int na = 0; na < 8; na++) {
                __nv_bfloat162 h2 = __floats2bfloat162_rn(acc[ma][na][half * 2],
                                                          acc[ma][na][half * 2 + 1]);
                float2 f2 = __bfloat1622float2(h2);
                fr[na * 2] = f2.x; fr[na * 2 + 1] = f2.y;
            }
            float mx = -3.4e38f;
            #pragma unroll
            for (int i = 0; i < 16; i++) mx = fmaxf(mx, fr[i]);
            mx = fmaxf(mx, __shfl_xor_sync(0xffffffffu, mx, 1));
            mx = fmaxf(mx, __shfl_xor_sync(0xffffffffu, mx, 2));
            float s = 0.f;
            #pragma unroll
            for (int i = 0; i < 16; i++) s += __expf(fr[i] - mx);
            s += __shfl_xor_sync(0xffffffffu, s, 1);
            s += __shfl_xor_sync(0xffffffffu, s, 2);
            if ((lane & 3) == 0) {
                g_pm[(size_t)rowg * 32 + mt * 2 + wx] = mx;
                g_ps[(size_t)rowg * 32 + mt * 2 + wx] = s;
            }
        }
    }
}

// combine 32 row partials -> packed (rm, rsinv)
__global__ void k_rowreduce() {
    int row = blockIdx.x * 8 + (threadIdx.x >> 5);
    int lane = threadIdx.x & 31;
    float pm = g_pm[((size_t)row << 5) | lane];
    float ps = g_ps[((size_t)row << 5) | lane];
    float m = pm;
    #pragma unroll
    for (int o = 16; o > 0; o >>= 1) m = fmaxf(m, __shfl_xor_sync(0xffffffffu, m, o));
    float s = ps * __expf(pm - m);
    #pragma unroll
    for (int o = 16; o > 0; o >>= 1) s += __shfl_xor_sync(0xffffffffu, s, o);
    if (lane == 0) { float2 r; r.x = m; r.y = 1.f / s; g_rmrs[row] = r; }
}

// ------------------------- fused attn: E recompute + exp + colsum + V-MMA ----
__global__ __launch_bounds__(256, 2) void k_attn_mma() {
    extern __shared__ char smem[];
    const int KT = 0;            // 16 KB [64 d][128 j] SW256
    const int QP0 = 16384;       // 8 KB [64 d][64 nn''] SW128 (double buf)
    const int QP1 = 24576;
    const int EA = 32768;        // 16 KB [64 l][128 j] SW256
    const int VOF0 = 49152;      // 8 KB [64 d][64 nn] SW128 (double buf)
    const int VOF1 = 57344;
    const int SCOL = 65536;      // 512 B
    const int RMRS = 66048;      // 16 KB
    const u32 sbase = smem_u32(smem);
    int tid = threadIdx.x, wid = tid >> 5, lane = tid & 31;
    int jt = blockIdx.x, bh = blockIdx.y;
    int b = bh >> 2, hh = bh & 3;
    int j0 = jt * 128;
    int wy = wid >> 1, wx = wid & 1;   // V-MMA warp: 32 j x 32 d
    int wq = wid & 3, wj = wid >> 2;   // E-MMA warp: 16 nn'' x 64 j

    float* scol = (float*)(smem + SCOL);
    float2* rmrs = (float2*)(smem + RMRS);
    if (tid < 128) scol[tid] = 0.f;
    for (int i = tid; i < 2048; i += 256) rmrs[i] = g_rmrs[bh * 2048 + i];

    const uint4* Qg = (const uint4*)g_qbhi;
    const uint4* Vg = (const uint4*)g_Vb;
    // K-tile (B of E-MMA): [64 d][128 j], loaded once
    #pragma unroll
    for (int i = 0; i < 4; i++) {
        int u = i * 256 + tid;
        int r = u >> 4, q = u & 15;
        *(uint4*)(smem + KT + SW256(r * 256 + q * 16)) =
            Qg[((size_t)(b * C_ + hh * 64 + r)) * 256 + (j0 >> 3) + q];
    }
    // prefetch cc=0 QP (perm slice) + V
    int pc = tid >> 1, pq = tid & 1;
    int pr = tid >> 3, pv = tid & 7;
    uint4 qpr0 = Qg[((size_t)(b * C_ + pc)) * 256 + hh * 64 + pq];
    uint4 qpr1 = Qg[((size_t)(b * C_ + pc + 128)) * 256 + hh * 64 + pq];
    uint4 vr0 = Vg[((size_t)(b * C_ + hh * 64 + pr)) * 256 + pv];
    uint4 vr1 = Vg[((size_t)(b * C_ + hh * 64 + pr + 32)) * 256 + pv];

    float sums[16];
    #pragma unroll
    for (int i = 0; i < 16; i++) sums[i] = 0.f;
    float acc[2][4][4] = {};

    for (int cc = 0; cc < 32; cc++) {
        int QPp = (cc & 1) ? QP1 : QP0;
        int VOFp = (cc & 1) ? VOF1 : VOF0;
        // store prefetched tiles
        *(uint4*)(smem + QPp + SW128((pc & 63) * 128 + (pc >> 6) * 32 + pq * 16)) = qpr0;
        *(uint4*)(smem + QPp + SW128(((pc + 128) & 63) * 128 + ((pc + 128) >> 6) * 32 + pq * 16)) = qpr1;
        *(uint4*)(smem + VOFp + SW128(pr * 128 + pv * 16)) = vr0;
        *(uint4*)(smem + VOFp + SW128((pr + 32) * 128 + pv * 16)) = vr1;
        __syncthreads();
        if (cc < 31) {
            qpr0 = Qg[((size_t)(b * C_ + pc)) * 256 + hh * 64 + (cc + 1) * 2 + pq];
            qpr1 = Qg[((size_t)(b * C_ + pc + 128)) * 256 + hh * 64 + (cc + 1) * 2 + pq];
            vr0 = Vg[((size_t)(b * C_ + hh * 64 + pr)) * 256 + (cc + 1) * 8 + pv];
            vr1 = Vg[((size_t)(b * C_ + hh * 64 + pr + 32)) * 256 + (cc + 1) * 8 + pv];
        }
        // E-MMA: [64 nn''][128 j] tile, warp = 16 nn'' x 64 j
        float acce[8][4] = {};
        #pragma unroll
        for (int ks = 0; ks < 4; ks++) {
            int drow = ks * 16 + ((lane >> 4) & 1) * 8 + (lane & 7);
            u32 af[4];
            int nncol = wq * 16 + ((lane >> 3) & 1) * 8;
            ldm_x4t(af, sbase + QPp + SW128(drow * 128 + nncol * 2));
            u32 bhf[8][2];
            #pragma unroll
            for (int ng = 0; ng < 4; ng++) {
                int jcol = wj * 64 + ng * 16 + ((lane >> 3) & 1) * 8;
                u32 t4[4];
                ldm_x4t(t4, sbase + KT + SW256(drow * 256 + jcol * 2));
                bhf[ng * 2][0] = t4[0]; bhf[ng * 2][1] = t4[2];
                bhf[ng * 2 + 1][0] = t4[1]; bhf[ng * 2 + 1][1] = t4[3];
            }
            #pragma unroll
            for (int nf = 0; nf < 8; nf++) mma16816(acce[nf], af, bhf[nf]);
        }
        // exp + EA store + colsums
        int nn0 = cc * 64;
        #pragma unroll
        for (int half = 0; half < 2; half++) {
            int nnpp = wq * 16 + half * 8 + (lane >> 2);
            int l = 4 * (nnpp & 15) + (nnpp >> 4);       // local nn in V order
            float2 rr = rmrs[nn0 + l];
            #pragma unroll
            for (int nf = 0; nf < 8; nf++) {
                __nv_bfloat162 h2 = __floats2bfloat162_rn(acce[nf][half * 2],
                                                          acce[nf][half * 2 + 1]);
                float2 f2 = __bfloat1622float2(h2);
                float ea0 = fexp01(__expf(f2.x - rr.x) * rr.y);
                float ea1 = fexp01(__expf(f2.y - rr.x) * rr.y);
                __nv_bfloat162 e2 = __floats2bfloat162_rn(ea0, ea1);
                float2 fb = __bfloat1622float2(e2);
                sums[nf * 2] += fb.x; sums[nf * 2 + 1] += fb.y;
                *(u32*)(smem + EA + SW256(l * 256 + (wj * 64 + nf * 8 + (lane & 3) * 2) * 2)) = *(u32*)&e2;
            }
        }
        __syncthreads();
        // V-MMA: D[j][d] += ea^T . V^T
        #pragma unroll
        for (int ks = 0; ks < 4; ks++) {
            u32 af2[2][4], bf[4][2];
            int rsub = ((lane >> 3) & 1) * 8 + (lane & 7);
            #pragma unroll
            for (int ma = 0; ma < 2; ma++) {
                int nnrow = ks * 16 + ((lane >> 4) & 1) * 8 + (lane & 7);
                int jcol = wy * 32 + ma * 16 + ((lane >> 3) & 1) * 8;
                ldm_x4t(af2[ma], sbase + EA + SW256(nnrow * 256 + jcol * 2));
            }
            #pragma unroll
            for (int p2 = 0; p2 < 2; p2++) {
                int row = wx * 32 + p2 * 16 + rsub;
                int qq = ks * 2 + (lane >> 4);
                u32 t4[4];
                ldm_x4(t4, sbase + VOFp + SW128(row * 128 + qq * 16));
                bf[p2 * 2][0] = t4[0]; bf[p2 * 2][1] = t4[2];
                bf[p2 * 2 + 1][0] = t4[1]; bf[p2 * 2 + 1][1] = t4[3];
            }
            #pragma unroll
            for (int ma = 0; ma < 2; ma++)
                #pragma unroll
                for (int na = 0; na < 4; na++)
                    mma16816(acc[ma][na], af2[ma], bf[na]);
        }
    }
    // colsums -> csinv
    #pragma unroll
    for (int k = 0; k < 16; k++) {
        int j = wj * 64 + (k >> 1) * 8 + (lane & 3) * 2 + (k & 1);
        atomicAdd(&scol[j], sums[k]);
    }
    __syncthreads();
    if (tid < 128) scol[tid] = 1.f / scol[tid];
    __syncthreads();
    float csv[2][2];
    #pragma unroll
    for (int ma = 0; ma < 2; ma++)
        #pragma unroll
        for (int half = 0; half < 2; half++)
            csv[ma][half] = scol[wy * 32 + ma * 16 + half * 8 + (lane >> 2)];
    __syncthreads();
    float* stg = (float*)smem;                  // [128][65]
    #pragma unroll
    for (int ma = 0; ma < 2; ma++)
        #pragma unroll
        for (int half = 0; half < 2; half++) {
            int jl = wy * 32 + ma * 16 + half * 8 + (lane >> 2);
            float cs = csv[ma][half];
            #pragma unroll
            for (int na = 0; na < 4; na++) {
                int d = wx * 32 + na * 8 + (lane & 3) * 2;
                stg[jl * 65 + d]     = acc[ma][na][half * 2] * cs;
                stg[jl * 65 + d + 1] = acc[ma][na][half * 2 + 1] * cs;
            }
        }
    __syncthreads();
    for (int it = 0; it < 32; it++) {
        int d = it * 2 + (tid >> 7);
        int j = tid & 127;
        g_xr[((size_t)(b * C_ + hh * 64 + d)) * N_ + j0 + j] = stg[j * 65 + d];
    }
}

// ------------------------- residual + BN(inline) + relu + out (float4) -------
__global__ void k_residual(int slot, const float* __restrict__ gamma,
                           const float* __restrict__ beta, int layer,
                           float* __restrict__ out) {
    int idx = blockIdx.x * 256 + threadIdx.x;        // over BCN/4
    int base = idx << 2;
    int b = base >> 19;
    int c = (base >> 11) & (C_ - 1);
    int n = base & (N_ - 1);
    float s = g_bnsS[slot * C_ + c], s2 = g_bns2S[slot * C_ + c];
    float mean = s * (1.f / (B_ * N_));
    float var = s2 * (1.f / (B_ * N_)) - mean * mean;
    float inv = rsqrtf(var + 1e-5f);
    float scale = gamma[c] * inv;
    float shift = beta[c] - mean * scale;
    float4 t4 = *(const float4*)&g_t[base];
    float4 h4 = *(const float4*)&g_h[base];
    float4 o;
    o.x = h4.x + fmaxf(fmaf(scale, t4.x, shift), 0.f);
    o.y = h4.y + fmaxf(fmaf(scale, t4.y, shift), 0.f);
    o.z = h4.z + fmaxf(fmaf(scale, t4.z, shift), 0.f);
    o.w = h4.w + fmaxf(fmaf(scale, t4.w, shift), 0.f);
    *(float4*)&g_h[base] = o;
    *(float4*)&out[((size_t)b * (4 * C_) + layer * C_ + c) * N_ + n] = o;
}

// ------------------------- host orchestration --------------------------------
extern "C" void kernel_launch(void* const* d_in, const int* in_sizes, int n_in,
                              void* d_out, int out_size) {
    (void)in_sizes; (void)n_in; (void)out_size;
    const float* x       = (const float*)d_in[0];
    const float* xyz     = (const float*)d_in[1];
    const float* conv1_w = (const float*)d_in[2];
    const float* pos_w   = (const float*)d_in[3];
    const float* pos_b   = (const float*)d_in[4];
    const float* bn1_g   = (const float*)d_in[5];
    const float* bn1_b   = (const float*)d_in[6];
    const float* qk_w    = (const float*)d_in[7];
    const float* v_w     = (const float*)d_in[8];
    const float* v_b     = (const float*)d_in[9];
    const float* t_w     = (const float*)d_in[10];
    const float* t_b     = (const float*)d_in[11];
    const float* bn_g    = (const float*)d_in[12];
    const float* bn_b    = (const float*)d_in[13];
    float* out = (float*)d_out;

    float *ph, *pemb, *pxr, *pt;
    cudaGetSymbolAddress((void**)&ph,   g_h);
    cudaGetSymbolAddress((void**)&pemb, g_emb);
    cudaGetSymbolAddress((void**)&pxr,  g_xr);
    cudaGetSymbolAddress((void**)&pt,   g_t);

    cudaFuncSetAttribute(k_stats_mma,   cudaFuncAttributeMaxDynamicSharedMemorySize, 32768);
    cudaFuncSetAttribute(k_attn_mma,    cudaFuncAttributeMaxDynamicSharedMemorySize, 82432);
    cudaFuncSetAttribute(k_convmma<0>,  cudaFuncAttributeMaxDynamicSharedMemorySize, 36864);
    cudaFuncSetAttribute(k_convmma<2>,  cudaFuncAttributeMaxDynamicSharedMemorySize, 36864);
    cudaFuncSetAttribute(k_qvconv,      cudaFuncAttributeMaxDynamicSharedMemorySize, 18432);

    const int EW4 = (B_ * C_ * N_) / 1024;   // float4 elementwise blocks
    dim3 gCv(16, 2, 4);
    dim3 gQV(16, 4, 4);

    k_wsplit<<<13 * 256, 256>>>(conv1_w, qk_w, v_w, t_w);
    k_posemb<<<(B_ * N_) / 256, 256>>>(xyz, pos_w, pos_b);
    k_convmma<0><<<gCv, 256, 36864>>>(0, 0, x, nullptr, nullptr, pt);
    k_bnapply<<<EW4, 256>>>(bn1_g, bn1_b);

    for (int i = 0; i < 4; i++) {
        const float* vb = v_b  + (size_t)i * C_;
        const float* tb = t_b  + (size_t)i * C_;
        const float* bg = bn_g + (size_t)i * C_;
        const float* bb = bn_b + (size_t)i * C_;

        k_qvconv<<<gQV, 256, 18432>>>(1 + i, 5 + i, ph, pemb, vb);
        k_stats_mma<<<dim3(16, 16, BH_), 256, 32768>>>();
        k_rowreduce<<<(BH_ * N_) / 8, 256>>>();
        k_attn_mma<<<dim3(16, BH_), 256, 82432>>>();
        k_convmma<2><<<gCv, 256, 36864>>>(9 + i, 1 + i, ph, pxr, tb, pt);
        k_residual<<<EW4, 256>>>(1 + i, bg, bb, i, out);
    }
}